// round 1
// baseline (speedup 1.0000x reference)
#include <cuda_runtime.h>
#include <math.h>

// ---------------------------------------------------------------------------
// Problem constants
// ---------------------------------------------------------------------------
#define B_   16
#define HH   64
#define WW   64
#define CC   512
#define C8   64
#define C2   256
#define LOC  4096            // H*W
#define DOWN 1024            // LOC/4
#define MTOT (B_ * LOC)      // 65536

// ---------------------------------------------------------------------------
// Device scratch (static globals: allocation-free per harness rules)
// ---------------------------------------------------------------------------
__device__ float d_wtheta[CC * C8];
__device__ float d_wphi  [CC * C8];
__device__ float d_wg    [CC * C2];
__device__ float d_wattn [C2 * CC];
__device__ float d_theta  [MTOT * C8];            // 16 MB
__device__ float d_phifull[MTOT * C8];            // 16 MB
__device__ float d_phip   [B_ * DOWN * C8];       // 4  MB
__device__ float d_gfull  [MTOT * C2];            // 64 MB
__device__ float d_gp     [B_ * DOWN * C2];       // 16 MB
__device__ float d_attng  [MTOT * C2];            // 64 MB

// ---------------------------------------------------------------------------
// Spectral norm: one block per call. w:[Cin,Cout] row-major, u:[Cout]
// v = l2n(u @ w^T); r = v @ w; sigma = ||r||^2/(||r||+eps); wout = w/sigma
// ---------------------------------------------------------------------------
__global__ void spectral_kernel(const float* __restrict__ W,
                                const float* __restrict__ u,
                                float* __restrict__ Wout,
                                int Cin, int Cout)
{
    __shared__ float v[512];
    __shared__ float r[512];
    __shared__ float red[256];
    const int t = threadIdx.x;

    // v_raw[i] = sum_j u[j]*W[i,j]
    for (int i = t; i < Cin; i += 256) {
        float s = 0.f;
        const float* wr = W + (size_t)i * Cout;
        for (int j = 0; j < Cout; j++) s += u[j] * wr[j];
        v[i] = s;
    }
    __syncthreads();

    float ss = 0.f;
    for (int i = t; i < Cin; i += 256) ss += v[i] * v[i];
    red[t] = ss; __syncthreads();
    for (int o = 128; o; o >>= 1) { if (t < o) red[t] += red[t + o]; __syncthreads(); }
    float vnorm = sqrtf(red[0]) + 1e-12f;
    for (int i = t; i < Cin; i += 256) v[i] /= vnorm;
    __syncthreads();

    // r[j] = sum_i v[i]*W[i,j]
    for (int j = t; j < Cout; j += 256) {
        float s = 0.f;
        for (int i = 0; i < Cin; i++) s += v[i] * W[(size_t)i * Cout + j];
        r[j] = s;
    }
    __syncthreads();

    float ss2 = 0.f;
    for (int j = t; j < Cout; j += 256) ss2 += r[j] * r[j];
    red[t] = ss2; __syncthreads();
    for (int o = 128; o; o >>= 1) { if (t < o) red[t] += red[t + o]; __syncthreads(); }
    float rn    = red[0];
    float sigma = rn / (sqrtf(rn) + 1e-12f);
    float inv   = 1.0f / sigma;

    int total = Cin * Cout;
    for (int i = t; i < total; i += 256) Wout[i] = W[i] * inv;
}

// ---------------------------------------------------------------------------
// Tiled fp32 GEMM: C[M,N] = A[M,K] @ W[K,N]  (all row-major)
// BM=BN=64, BK=16, 256 threads, 4x4 micro-tile.
// RES=1: C = X + sigma*acc (fused residual epilogue)
// M%64==0, N%64==0, K%16==0 guaranteed by the problem shapes.
// ---------------------------------------------------------------------------
#define BM 64
#define BN 64
#define BK 16
#define APAD 68   // row stride in smem floats (68*4 = 272 B, 16B aligned)

template<int RES>
__global__ __launch_bounds__(256)
void gemm_kernel(const float* __restrict__ A, const float* __restrict__ W,
                 float* __restrict__ C, int M, int N, int K,
                 const float* __restrict__ X, const float* __restrict__ sigma_ptr)
{
    __shared__ float As[BK][APAD];
    __shared__ float Bs[BK][APAD];

    const int bm = blockIdx.y * BM;
    const int bn = blockIdx.x * BN;
    const int t  = threadIdx.x;
    const int tm = (t >> 4) * 4;  // 0..60
    const int tn = (t & 15) * 4;  // 0..60

    float acc[4][4] = {};

    for (int k0 = 0; k0 < K; k0 += BK) {
        // Load A tile [64 rows][16 k], transposed into As[k][m]
        #pragma unroll
        for (int p = 0; p < 4; p++) {
            int m = (t >> 4) + p * 16;
            int k = t & 15;
            As[k][m] = A[(size_t)(bm + m) * K + k0 + k];
        }
        // Load W tile [16 k][64 n] into Bs[k][n]
        #pragma unroll
        for (int p = 0; p < 4; p++) {
            int k = (t >> 6) + p * 4;
            int n = t & 63;
            Bs[k][n] = W[(size_t)(k0 + k) * N + bn + n];
        }
        __syncthreads();

        #pragma unroll
        for (int k = 0; k < BK; k++) {
            float4 av = *(const float4*)(&As[k][tm]);
            float4 bv = *(const float4*)(&Bs[k][tn]);
            float a[4] = {av.x, av.y, av.z, av.w};
            float b[4] = {bv.x, bv.y, bv.z, bv.w};
            #pragma unroll
            for (int i = 0; i < 4; i++)
                #pragma unroll
                for (int j = 0; j < 4; j++)
                    acc[i][j] = fmaf(a[i], b[j], acc[i][j]);
        }
        __syncthreads();
    }

    float sg = 0.f;
    if (RES) sg = *sigma_ptr;

    #pragma unroll
    for (int i = 0; i < 4; i++) {
        size_t idx = (size_t)(bm + tm + i) * N + bn + tn;
        float4 o;
        if (RES) {
            float4 xv = *(const float4*)(&X[idx]);
            o.x = xv.x + sg * acc[i][0];
            o.y = xv.y + sg * acc[i][1];
            o.z = xv.z + sg * acc[i][2];
            o.w = xv.w + sg * acc[i][3];
        } else {
            o.x = acc[i][0]; o.y = acc[i][1]; o.z = acc[i][2]; o.w = acc[i][3];
        }
        *(float4*)(&C[idx]) = o;
    }
}

// ---------------------------------------------------------------------------
// 2x2 max pool over spatial dims. in: [B,64,64,C]  out: [B,32,32,C]
// ---------------------------------------------------------------------------
__global__ void pool_kernel(const float* __restrict__ in, float* __restrict__ out,
                            int C, int total)
{
    int idx = blockIdx.x * blockDim.x + threadIdx.x;
    if (idx >= total) return;
    int c  = idx % C;
    int r  = idx / C;
    int w2 = r % 32; r /= 32;
    int h2 = r % 32; r /= 32;
    int b  = r;
    const float* p = in + (((size_t)(b * 64 + h2 * 2)) * 64 + w2 * 2) * C + c;
    float m0 = fmaxf(p[0], p[C]);
    float m1 = fmaxf(p[(size_t)64 * C], p[(size_t)65 * C]);
    out[idx] = fmaxf(m0, m1);
}

// ---------------------------------------------------------------------------
// Fused attention: scores = theta @ phi^T, softmax, attn @ g
// theta: [B,4096,64]  phi: [B,1024,64]  g: [B,1024,256]  out: [B,4096,256]
// One block handles 32 query rows. Full 1024-wide score rows kept in smem.
// ---------------------------------------------------------------------------
#define AROWS 32
#define SSTR  1032   // score row stride (floats): 1032 % 32 == 8 -> no bank clash
// smem: theta_s 32*64 | scores 32*1032 | stage 64*256 (phi uses stride-65 view)
#define ATTN_SMEM ((AROWS*64 + AROWS*SSTR + 64*256) * 4)

__global__ __launch_bounds__(256)
void attn_kernel(const float* __restrict__ theta,
                 const float* __restrict__ phi,
                 const float* __restrict__ g,
                 float* __restrict__ attng)
{
    extern __shared__ float sm[];
    float* theta_s = sm;                       // 2048 floats
    float* scores  = sm + AROWS * 64;          // 32*1032 floats
    float* stage   = scores + AROWS * SSTR;    // 64*256 floats (reused)

    const int b  = blockIdx.y;
    const int n0 = blockIdx.x * AROWS;
    const int t  = threadIdx.x;

    // load theta tile (32 x 64)
    {
        const float* th = theta + ((size_t)b * LOC + n0) * C8;
        for (int i = t; i < AROWS * 64; i += 256) theta_s[i] = th[i];
    }

    // ---- score phase: S[r][m] = dot(theta[r], phi[m]) -----------------
    const int rg = t >> 4;        // 0..15 -> 2 rows each
    const int mg = t & 15;        // 0..15 -> 4 m each
    const int r0 = rg * 2;
    const int m0 = mg * 4;

    for (int mb = 0; mb < DOWN; mb += 64) {
        const float* ph = phi + ((size_t)b * DOWN + mb) * C8;
        __syncthreads();  // protect stage (and theta_s on first iter)
        for (int i = t; i < 64 * 64; i += 256) {
            int mm = i >> 6, d = i & 63;
            stage[mm * 65 + d] = ph[i];
        }
        __syncthreads();

        float acc[2][4] = {};
        #pragma unroll 4
        for (int k = 0; k < 64; k++) {
            float a0 = theta_s[(r0 + 0) * 64 + k];
            float a1 = theta_s[(r0 + 1) * 64 + k];
            float b0 = stage[(m0 + 0) * 65 + k];
            float b1 = stage[(m0 + 1) * 65 + k];
            float b2 = stage[(m0 + 2) * 65 + k];
            float b3 = stage[(m0 + 3) * 65 + k];
            acc[0][0] = fmaf(a0, b0, acc[0][0]);
            acc[0][1] = fmaf(a0, b1, acc[0][1]);
            acc[0][2] = fmaf(a0, b2, acc[0][2]);
            acc[0][3] = fmaf(a0, b3, acc[0][3]);
            acc[1][0] = fmaf(a1, b0, acc[1][0]);
            acc[1][1] = fmaf(a1, b1, acc[1][1]);
            acc[1][2] = fmaf(a1, b2, acc[1][2]);
            acc[1][3] = fmaf(a1, b3, acc[1][3]);
        }
        #pragma unroll
        for (int i = 0; i < 2; i++)
            #pragma unroll
            for (int j = 0; j < 4; j++)
                scores[(r0 + i) * SSTR + mb + m0 + j] = acc[i][j];
    }
    __syncthreads();

    // ---- softmax: 8 threads per row ------------------------------------
    {
        const int r  = t >> 3;
        const int l8 = t & 7;
        float* srow = scores + r * SSTR;
        float mx = -1e30f;
        for (int j = l8; j < DOWN; j += 8) mx = fmaxf(mx, srow[j]);
        #pragma unroll
        for (int o = 4; o; o >>= 1) mx = fmaxf(mx, __shfl_xor_sync(0xffffffffu, mx, o));
        float sum = 0.f;
        for (int j = l8; j < DOWN; j += 8) {
            float e = __expf(srow[j] - mx);
            srow[j] = e;
            sum += e;
        }
        #pragma unroll
        for (int o = 4; o; o >>= 1) sum += __shfl_xor_sync(0xffffffffu, sum, o);
        float inv = 1.0f / sum;
        for (int j = l8; j < DOWN; j += 8) srow[j] *= inv;
    }
    __syncthreads();

    // ---- PV phase: out[r][c] = sum_m P[r][m] * g[m][c] ------------------
    const int prg = t >> 5;       // 0..7  -> 4 rows each
    const int pcg = t & 31;       // 0..31 -> 8 cols each
    const int pr0 = prg * 4;
    const int pc0 = pcg * 8;
    float oacc[4][8] = {};

    for (int mb = 0; mb < DOWN; mb += 64) {
        const float* gpc = g + ((size_t)b * DOWN + mb) * C2;
        __syncthreads();  // protect stage
        for (int i = t; i < 64 * C2; i += 256) stage[i] = gpc[i];
        __syncthreads();

        #pragma unroll 2
        for (int m = 0; m < 64; m++) {
            float p0 = scores[(pr0 + 0) * SSTR + mb + m];
            float p1 = scores[(pr0 + 1) * SSTR + mb + m];
            float p2 = scores[(pr0 + 2) * SSTR + mb + m];
            float p3 = scores[(pr0 + 3) * SSTR + mb + m];
            float4 g0 = *(const float4*)(&stage[m * C2 + pc0]);
            float4 g1 = *(const float4*)(&stage[m * C2 + pc0 + 4]);
            float gv[8] = {g0.x, g0.y, g0.z, g0.w, g1.x, g1.y, g1.z, g1.w};
            #pragma unroll
            for (int j = 0; j < 8; j++) {
                oacc[0][j] = fmaf(p0, gv[j], oacc[0][j]);
                oacc[1][j] = fmaf(p1, gv[j], oacc[1][j]);
                oacc[2][j] = fmaf(p2, gv[j], oacc[2][j]);
                oacc[3][j] = fmaf(p3, gv[j], oacc[3][j]);
            }
        }
    }

    // write attn_g
    #pragma unroll
    for (int i = 0; i < 4; i++) {
        size_t idx = ((size_t)b * LOC + n0 + pr0 + i) * C2 + pc0;
        float4 o0 = {oacc[i][0], oacc[i][1], oacc[i][2], oacc[i][3]};
        float4 o1 = {oacc[i][4], oacc[i][5], oacc[i][6], oacc[i][7]};
        *(float4*)(&attng[idx])     = o0;
        *(float4*)(&attng[idx + 4]) = o1;
    }
}

// ---------------------------------------------------------------------------
// kernel_launch
// ---------------------------------------------------------------------------
extern "C" void kernel_launch(void* const* d_in, const int* in_sizes, int n_in,
                              void* d_out, int out_size)
{
    const float* x       = (const float*)d_in[0];
    const float* k_theta = (const float*)d_in[1];
    const float* u_theta = (const float*)d_in[2];
    const float* k_phi   = (const float*)d_in[3];
    const float* u_phi   = (const float*)d_in[4];
    const float* k_g     = (const float*)d_in[5];
    const float* u_g     = (const float*)d_in[6];
    const float* k_attn  = (const float*)d_in[7];
    const float* u_attn  = (const float*)d_in[8];
    const float* sigma   = (const float*)d_in[9];
    float* out = (float*)d_out;

    float *wtheta, *wphi, *wg, *wattn, *theta, *phifull, *phip, *gfull, *gp, *attng;
    cudaGetSymbolAddress((void**)&wtheta,  d_wtheta);
    cudaGetSymbolAddress((void**)&wphi,    d_wphi);
    cudaGetSymbolAddress((void**)&wg,      d_wg);
    cudaGetSymbolAddress((void**)&wattn,   d_wattn);
    cudaGetSymbolAddress((void**)&theta,   d_theta);
    cudaGetSymbolAddress((void**)&phifull, d_phifull);
    cudaGetSymbolAddress((void**)&phip,    d_phip);
    cudaGetSymbolAddress((void**)&gfull,   d_gfull);
    cudaGetSymbolAddress((void**)&gp,      d_gp);
    cudaGetSymbolAddress((void**)&attng,   d_attng);

    cudaFuncSetAttribute(attn_kernel,
                         cudaFuncAttributeMaxDynamicSharedMemorySize, ATTN_SMEM);

    // spectral norms (tiny)
    spectral_kernel<<<1, 256>>>(k_theta, u_theta, wtheta, CC, C8);
    spectral_kernel<<<1, 256>>>(k_phi,   u_phi,   wphi,   CC, C8);
    spectral_kernel<<<1, 256>>>(k_g,     u_g,     wg,     CC, C2);
    spectral_kernel<<<1, 256>>>(k_attn,  u_attn,  wattn,  C2, CC);

    // convs
    gemm_kernel<0><<<dim3(C8 / BN, MTOT / BM), 256>>>(x, wtheta, theta,   MTOT, C8, CC, nullptr, nullptr);
    gemm_kernel<0><<<dim3(C8 / BN, MTOT / BM), 256>>>(x, wphi,   phifull, MTOT, C8, CC, nullptr, nullptr);
    gemm_kernel<0><<<dim3(C2 / BN, MTOT / BM), 256>>>(x, wg,     gfull,   MTOT, C2, CC, nullptr, nullptr);

    // pooling
    int phi_total = B_ * DOWN * C8;
    int g_total   = B_ * DOWN * C2;
    pool_kernel<<<(phi_total + 255) / 256, 256>>>(phifull, phip, C8, phi_total);
    pool_kernel<<<(g_total   + 255) / 256, 256>>>(gfull,   gp,   C2, g_total);

    // fused attention
    attn_kernel<<<dim3(LOC / AROWS, B_), 256, ATTN_SMEM>>>(theta, phip, gp, attng);

    // output conv + residual
    gemm_kernel<1><<<dim3(CC / BN, MTOT / BM), 256>>>(attng, wattn, out, MTOT, CC, C2, x, sigma);
}

// round 2
// speedup vs baseline: 1.0224x; 1.0224x over previous
#include <cuda_runtime.h>
#include <math.h>

// ---------------------------------------------------------------------------
// Problem constants
// ---------------------------------------------------------------------------
#define B_   16
#define HH   64
#define WW   64
#define CC   512
#define C8   64
#define C2   256
#define LOC  4096
#define DOWN 1024
#define MTOT (B_ * LOC)      // 65536

// ---------------------------------------------------------------------------
// Device scratch
// ---------------------------------------------------------------------------
__device__ float d_invs[4];                       // 1/sigma for theta,phi,g,attn
__device__ float d_theta  [MTOT * C8];            // 16 MB
__device__ float d_phifull[MTOT * C8];            // 16 MB
__device__ float d_phip   [B_ * DOWN * C8];       // 4  MB
__device__ float d_gfull  [MTOT * C2];            // 64 MB
__device__ float d_gp     [B_ * DOWN * C2];       // 16 MB
__device__ float d_attng  [MTOT * C2];            // 64 MB

// ---------------------------------------------------------------------------
// f32x2 packed-FMA helpers (FFMA2 in SASS — only reachable via PTX)
// ---------------------------------------------------------------------------
__device__ __forceinline__ unsigned long long dup2(float a) {
    unsigned long long r;
    asm("mov.b64 %0, {%1, %1};" : "=l"(r) : "f"(a));
    return r;
}
__device__ __forceinline__ void ffma2(unsigned long long& d,
                                      unsigned long long a, unsigned long long b) {
    asm("fma.rn.f32x2 %0, %1, %2, %0;" : "+l"(d) : "l"(a), "l"(b));
}
__device__ __forceinline__ float2 unpk(unsigned long long v) {
    float2 r;
    asm("mov.b64 {%0, %1}, %2;" : "=f"(r.x), "=f"(r.y) : "l"(v));
    return r;
}

// ---------------------------------------------------------------------------
// Spectral norms: 4 blocks, one per weight. Computes ONLY 1/sigma.
// Weight scaling is folded into the GEMM epilogues.
// ---------------------------------------------------------------------------
__global__ void spectral4_kernel(const float* __restrict__ kt, const float* __restrict__ ut,
                                 const float* __restrict__ kp, const float* __restrict__ up,
                                 const float* __restrict__ kg, const float* __restrict__ ug,
                                 const float* __restrict__ ka, const float* __restrict__ ua)
{
    const float* W; const float* u; int Cin, Cout;
    switch (blockIdx.x) {
        case 0:  W = kt; u = ut; Cin = 512; Cout = 64;  break;
        case 1:  W = kp; u = up; Cin = 512; Cout = 64;  break;
        case 2:  W = kg; u = ug; Cin = 512; Cout = 256; break;
        default: W = ka; u = ua; Cin = 256; Cout = 512; break;
    }
    __shared__ float us[512];
    __shared__ float v[512];
    __shared__ float red[256];
    const int t = threadIdx.x;

    for (int j = t; j < Cout; j += 256) us[j] = u[j];
    __syncthreads();

    // v[i] = dot(u, W[i,:])
    for (int i = t; i < Cin; i += 256) {
        const float4* wr = (const float4*)(W + (size_t)i * Cout);
        float s = 0.f;
        for (int j = 0; j < Cout / 4; j++) {
            float4 w4 = wr[j];
            s += us[4*j] * w4.x + us[4*j+1] * w4.y + us[4*j+2] * w4.z + us[4*j+3] * w4.w;
        }
        v[i] = s;
    }
    __syncthreads();

    float ss = 0.f;
    for (int i = t; i < Cin; i += 256) ss += v[i] * v[i];
    red[t] = ss; __syncthreads();
    for (int o = 128; o; o >>= 1) { if (t < o) red[t] += red[t + o]; __syncthreads(); }
    float inv_vn = 1.0f / (sqrtf(red[0]) + 1e-12f);
    __syncthreads();

    // r[j] = dot(v_normalized, W[:,j]); accumulate ||r||^2
    float rr = 0.f;
    for (int j = t; j < Cout; j += 256) {
        float s = 0.f;
        for (int i = 0; i < Cin; i++) s += v[i] * W[(size_t)i * Cout + j];
        s *= inv_vn;
        rr += s * s;
    }
    red[t] = rr; __syncthreads();
    for (int o = 128; o; o >>= 1) { if (t < o) red[t] += red[t + o]; __syncthreads(); }
    if (t == 0) {
        float rn = red[0];
        // sigma = rn / (sqrt(rn)+eps)  ->  1/sigma = (sqrt(rn)+eps)/rn
        d_invs[blockIdx.x] = (sqrtf(rn) + 1e-12f) / rn;
    }
}

// ---------------------------------------------------------------------------
// f32x2 GEMM: C = A[M,K] @ W[K,N], BM=64, BN=128, BK=16, 256 thr, 4x8 micro.
// MODE 0: dual-output theta|phi (W0/W1 each [K,64], scales invs[0]/invs[1])
// MODE 1: single output, scale invs[2]
// MODE 2: residual: C = X + sigma*invs[3]*acc
// ---------------------------------------------------------------------------
#define BM 64
#define BN 128
#define BK 16

template<int MODE>
__global__ __launch_bounds__(256)
void gemm_f2(const float* __restrict__ A,
             const float* __restrict__ W0, const float* __restrict__ W1,
             float* __restrict__ C0, float* __restrict__ C1,
             int M, int N, int K,
             const float* __restrict__ X, const float* __restrict__ sigma_ptr)
{
    __shared__ float As[BK][BM + 4];
    __shared__ float Bs[BK][BN + 4];

    const int bm = blockIdx.y * BM;
    const int bn = blockIdx.x * BN;
    const int t  = threadIdx.x;
    const int tm = (t >> 4) * 4;     // 4 rows
    const int tn = (t & 15) * 8;     // 8 cols (4 packed pairs)

    unsigned long long acc[4][4] = {};

    for (int k0 = 0; k0 < K; k0 += BK) {
        #pragma unroll
        for (int p = 0; p < 4; p++) {
            int m = (t >> 4) + p * 16;
            int k = t & 15;
            As[k][m] = A[(size_t)(bm + m) * K + k0 + k];
        }
        #pragma unroll
        for (int p = 0; p < (BK * BN) / 256; p++) {
            int idx = t + p * 256;
            int k = idx / BN, n = idx % BN;
            float w;
            if (MODE == 0)
                w = (n < 64) ? W0[(size_t)(k0 + k) * 64 + n]
                             : W1[(size_t)(k0 + k) * 64 + (n - 64)];
            else
                w = W0[(size_t)(k0 + k) * N + bn + n];
            Bs[k][n] = w;
        }
        __syncthreads();

        #pragma unroll
        for (int k = 0; k < BK; k++) {
            float4 av = *(const float4*)&As[k][tm];
            unsigned long long ad[4] = {dup2(av.x), dup2(av.y), dup2(av.z), dup2(av.w)};
            ulonglong2 b0 = *(const ulonglong2*)&Bs[k][tn];
            ulonglong2 b1 = *(const ulonglong2*)&Bs[k][tn + 4];
            unsigned long long bp[4] = {b0.x, b0.y, b1.x, b1.y};
            #pragma unroll
            for (int i = 0; i < 4; i++)
                #pragma unroll
                for (int j = 0; j < 4; j++)
                    ffma2(acc[i][j], ad[i], bp[j]);
        }
        __syncthreads();
    }

    float scale;
    if (MODE == 0)      scale = (tn < 64) ? d_invs[0] : d_invs[1];
    else if (MODE == 1) scale = d_invs[2];
    else                scale = d_invs[3] * __ldg(sigma_ptr);

    #pragma unroll
    for (int i = 0; i < 4; i++) {
        float o[8];
        #pragma unroll
        for (int j = 0; j < 4; j++) {
            float2 p = unpk(acc[i][j]);
            o[2*j]   = p.x * scale;
            o[2*j+1] = p.y * scale;
        }
        int row = bm + tm + i;
        if (MODE == 0) {
            float* dst = (tn < 64) ? (C0 + (size_t)row * 64 + tn)
                                   : (C1 + (size_t)row * 64 + (tn - 64));
            *(float4*)dst       = make_float4(o[0], o[1], o[2], o[3]);
            *(float4*)(dst + 4) = make_float4(o[4], o[5], o[6], o[7]);
        } else if (MODE == 1) {
            size_t idx = (size_t)row * N + bn + tn;
            *(float4*)&C0[idx]     = make_float4(o[0], o[1], o[2], o[3]);
            *(float4*)&C0[idx + 4] = make_float4(o[4], o[5], o[6], o[7]);
        } else {
            size_t idx = (size_t)row * N + bn + tn;
            float4 x0 = *(const float4*)&X[idx];
            float4 x1 = *(const float4*)&X[idx + 4];
            *(float4*)&C0[idx]     = make_float4(x0.x + o[0], x0.y + o[1], x0.z + o[2], x0.w + o[3]);
            *(float4*)&C0[idx + 4] = make_float4(x1.x + o[4], x1.y + o[5], x1.z + o[6], x1.w + o[7]);
        }
    }
}

// ---------------------------------------------------------------------------
// 2x2 max pool: [B,64,64,C] -> [B,32,32,C]
// ---------------------------------------------------------------------------
__global__ void pool_kernel(const float* __restrict__ in, float* __restrict__ out,
                            int C, int total)
{
    int idx = blockIdx.x * blockDim.x + threadIdx.x;
    if (idx >= total) return;
    int c  = idx % C;
    int r  = idx / C;
    int w2 = r % 32; r /= 32;
    int h2 = r % 32; r /= 32;
    int b  = r;
    const float* p = in + (((size_t)(b * 64 + h2 * 2)) * 64 + w2 * 2) * C + c;
    float m0 = fmaxf(p[0], p[C]);
    float m1 = fmaxf(p[(size_t)64 * C], p[(size_t)65 * C]);
    out[idx] = fmaxf(m0, m1);
}

// ---------------------------------------------------------------------------
// Fused attention (f32x2): scores = theta@phi^T, softmax, P@g
// theta:[B,4096,64] phi:[B,1024,64] g:[B,1024,256] out:[B,4096,256]
// One block = 32 query rows. Full 1024-wide score rows in smem.
// ---------------------------------------------------------------------------
#define AROWS 32
#define SSTR  1041   // odd: 2*SSTR % 32 == 2 -> PV p-loads hit 16 distinct banks
#define STAGE_F (64 * 256)
#define ATTN_SMEM ((AROWS*64 + AROWS*SSTR + STAGE_F) * 4)

__global__ __launch_bounds__(256)
void attn_kernel(const float* __restrict__ theta,
                 const float* __restrict__ phi,
                 const float* __restrict__ g,
                 float* __restrict__ attng)
{
    extern __shared__ float sm[];
    float* theta_s = sm;                      // 32*64
    float* scores  = sm + AROWS * 64;         // 32*SSTR
    float* stage   = scores + AROWS * SSTR;   // 64*256 (reused)

    const int b  = blockIdx.y;
    const int n0 = blockIdx.x * AROWS;
    const int t  = threadIdx.x;

    {
        const float* th = theta + ((size_t)b * LOC + n0) * C8;
        for (int i = t; i < AROWS * 64; i += 256) theta_s[i] = th[i];
    }

    // ---- scores: S[r][m] = dot(theta[r], phi[m]) ------------------------
    // stage holds phi chunk transposed: stage[k*68 + m], k<64, m<64
    const int r0 = (t >> 4) * 2;
    const int m0 = (t & 15) * 4;

    for (int mb = 0; mb < DOWN; mb += 64) {
        const float* ph = phi + ((size_t)b * DOWN + mb) * C8;
        __syncthreads();
        for (int i = t; i < 64 * 64; i += 256) {
            int mm = i >> 6, kk = i & 63;
            stage[kk * 68 + mm] = ph[i];
        }
        __syncthreads();

        unsigned long long a0p[2] = {}, a1p[2] = {};
        #pragma unroll 4
        for (int k = 0; k < 64; k++) {
            float a0 = theta_s[r0 * 64 + k];
            float a1 = theta_s[(r0 + 1) * 64 + k];
            unsigned long long d0 = dup2(a0), d1 = dup2(a1);
            ulonglong2 bp = *(const ulonglong2*)&stage[k * 68 + m0];
            ffma2(a0p[0], d0, bp.x); ffma2(a0p[1], d0, bp.y);
            ffma2(a1p[0], d1, bp.x); ffma2(a1p[1], d1, bp.y);
        }
        float2 s00 = unpk(a0p[0]), s01 = unpk(a0p[1]);
        float2 s10 = unpk(a1p[0]), s11 = unpk(a1p[1]);
        float* sr0 = scores + r0 * SSTR + mb + m0;
        float* sr1 = sr0 + SSTR;
        sr0[0] = s00.x; sr0[1] = s00.y; sr0[2] = s01.x; sr0[3] = s01.y;
        sr1[0] = s10.x; sr1[1] = s10.y; sr1[2] = s11.x; sr1[3] = s11.y;
    }
    __syncthreads();

    // ---- softmax: 8 threads per row --------------------------------------
    {
        const int r  = t >> 3;
        const int l8 = t & 7;
        float* srow = scores + r * SSTR;
        float mx = -1e30f;
        for (int j = l8; j < DOWN; j += 8) mx = fmaxf(mx, srow[j]);
        #pragma unroll
        for (int o = 4; o; o >>= 1) mx = fmaxf(mx, __shfl_xor_sync(0xffffffffu, mx, o));
        float sum = 0.f;
        for (int j = l8; j < DOWN; j += 8) {
            float e = __expf(srow[j] - mx);
            srow[j] = e;
            sum += e;
        }
        #pragma unroll
        for (int o = 4; o; o >>= 1) sum += __shfl_xor_sync(0xffffffffu, sum, o);
        float inv = 1.0f / sum;
        for (int j = l8; j < DOWN; j += 8) srow[j] *= inv;
    }
    __syncthreads();

    // ---- PV: out[r][c] = sum_m P[r][m] * g[m][c] -------------------------
    // 2 rows x 16 cols per thread; g pairs contiguous; p-loads conflict-free.
    const int pr0 = (t & 15) * 2;
    const int pc0 = (t >> 4) * 16;
    unsigned long long oacc[2][8] = {};

    for (int mb = 0; mb < DOWN; mb += 64) {
        const float* gpc = g + ((size_t)b * DOWN + mb) * C2;
        __syncthreads();
        for (int i = t; i < 64 * C2; i += 256) stage[i] = gpc[i];
        __syncthreads();

        #pragma unroll 2
        for (int m = 0; m < 64; m++) {
            float p0 = scores[pr0 * SSTR + mb + m];
            float p1 = scores[(pr0 + 1) * SSTR + mb + m];
            unsigned long long d0 = dup2(p0), d1 = dup2(p1);
            ulonglong2 g0 = *(const ulonglong2*)&stage[m * C2 + pc0];
            ulonglong2 g1 = *(const ulonglong2*)&stage[m * C2 + pc0 + 4];
            ulonglong2 g2 = *(const ulonglong2*)&stage[m * C2 + pc0 + 8];
            ulonglong2 g3 = *(const ulonglong2*)&stage[m * C2 + pc0 + 12];
            ffma2(oacc[0][0], d0, g0.x); ffma2(oacc[0][1], d0, g0.y);
            ffma2(oacc[0][2], d0, g1.x); ffma2(oacc[0][3], d0, g1.y);
            ffma2(oacc[0][4], d0, g2.x); ffma2(oacc[0][5], d0, g2.y);
            ffma2(oacc[0][6], d0, g3.x); ffma2(oacc[0][7], d0, g3.y);
            ffma2(oacc[1][0], d1, g0.x); ffma2(oacc[1][1], d1, g0.y);
            ffma2(oacc[1][2], d1, g1.x); ffma2(oacc[1][3], d1, g1.y);
            ffma2(oacc[1][4], d1, g2.x); ffma2(oacc[1][5], d1, g2.y);
            ffma2(oacc[1][6], d1, g3.x); ffma2(oacc[1][7], d1, g3.y);
        }
    }

    #pragma unroll
    for (int i = 0; i < 2; i++) {
        size_t idx = ((size_t)b * LOC + n0 + pr0 + i) * C2 + pc0;
        #pragma unroll
        for (int j = 0; j < 4; j++) {
            float2 pa = unpk(oacc[i][2*j]);
            float2 pb = unpk(oacc[i][2*j + 1]);
            *(float4*)&attng[idx + 4*j] = make_float4(pa.x, pa.y, pb.x, pb.y);
        }
    }
}

// ---------------------------------------------------------------------------
// kernel_launch
// ---------------------------------------------------------------------------
extern "C" void kernel_launch(void* const* d_in, const int* in_sizes, int n_in,
                              void* d_out, int out_size)
{
    const float* x       = (const float*)d_in[0];
    const float* k_theta = (const float*)d_in[1];
    const float* u_theta = (const float*)d_in[2];
    const float* k_phi   = (const float*)d_in[3];
    const float* u_phi   = (const float*)d_in[4];
    const float* k_g     = (const float*)d_in[5];
    const float* u_g     = (const float*)d_in[6];
    const float* k_attn  = (const float*)d_in[7];
    const float* u_attn  = (const float*)d_in[8];
    const float* sigma   = (const float*)d_in[9];
    float* out = (float*)d_out;

    float *theta, *phifull, *phip, *gfull, *gp, *attng;
    cudaGetSymbolAddress((void**)&theta,   d_theta);
    cudaGetSymbolAddress((void**)&phifull, d_phifull);
    cudaGetSymbolAddress((void**)&phip,    d_phip);
    cudaGetSymbolAddress((void**)&gfull,   d_gfull);
    cudaGetSymbolAddress((void**)&gp,      d_gp);
    cudaGetSymbolAddress((void**)&attng,   d_attng);

    cudaFuncSetAttribute(attn_kernel,
                         cudaFuncAttributeMaxDynamicSharedMemorySize, ATTN_SMEM);

    // spectral norms: 4 blocks, one launch, inv_sigma only
    spectral4_kernel<<<4, 256>>>(k_theta, u_theta, k_phi, u_phi,
                                 k_g, u_g, k_attn, u_attn);

    // theta+phi fused conv (N=128 dual output)
    gemm_f2<0><<<dim3(1, MTOT / BM), 256>>>(x, k_theta, k_phi, theta, phifull,
                                            MTOT, 128, CC, nullptr, nullptr);
    // g conv
    gemm_f2<1><<<dim3(C2 / BN, MTOT / BM), 256>>>(x, k_g, nullptr, gfull, nullptr,
                                                  MTOT, C2, CC, nullptr, nullptr);

    // pooling
    int phi_total = B_ * DOWN * C8;
    int g_total   = B_ * DOWN * C2;
    pool_kernel<<<(phi_total + 255) / 256, 256>>>(phifull, phip, C8, phi_total);
    pool_kernel<<<(g_total   + 255) / 256, 256>>>(gfull,   gp,   C2, g_total);

    // fused attention
    attn_kernel<<<dim3(LOC / AROWS, B_), 256, ATTN_SMEM>>>(theta, phip, gp, attng);

    // output conv + residual
    gemm_f2<2><<<dim3(CC / BN, MTOT / BM), 256>>>(attng, k_attn, nullptr, out, nullptr,
                                                  MTOT, CC, C2, x, sigma);
}

// round 4
// speedup vs baseline: 1.6695x; 1.6329x over previous
#include <cuda_runtime.h>
#include <cuda_bf16.h>
#include <math.h>
#include <stdint.h>

// ---------------------------------------------------------------------------
// Problem constants
// ---------------------------------------------------------------------------
#define B_   16
#define CC   512
#define C8   64
#define C2   256
#define LOC  4096
#define DOWN 1024
#define MTOT 65536

// ---------------------------------------------------------------------------
// Device scratch
// ---------------------------------------------------------------------------
__device__ float d_invs[4];
__device__ float d_theta  [MTOT * C8];
__device__ float d_phifull[MTOT * C8];
__device__ float d_phip   [B_ * DOWN * C8];
__device__ float d_gfull  [MTOT * C2];
__device__ float d_gp     [B_ * DOWN * C2];
__device__ float d_attng  [MTOT * C2];

// ---------------------------------------------------------------------------
// bf16 split helpers: a = hi + lo, |lo| <= 2^-8 |a|, pairs packed low-k-first
// ---------------------------------------------------------------------------
__device__ __forceinline__ uint32_t pack2(float a, float b) {
    __nv_bfloat162 h = __floats2bfloat162_rn(a, b);
    return *(uint32_t*)&h;
}
__device__ __forceinline__ void split2(float a, float b, uint32_t& hi, uint32_t& lo) {
    float ha = __bfloat162float(__float2bfloat16_rn(a));
    float hb = __bfloat162float(__float2bfloat16_rn(b));
    hi = pack2(ha, hb);
    lo = pack2(a - ha, b - hb);
}
__device__ __forceinline__ void mma_bf16(float4& d,
    uint32_t a0, uint32_t a1, uint32_t a2, uint32_t a3, uint32_t b0, uint32_t b1)
{
    asm volatile("mma.sync.aligned.m16n8k16.row.col.f32.bf16.bf16.f32 "
        "{%0,%1,%2,%3}, {%4,%5,%6,%7}, {%8,%9}, {%0,%1,%2,%3};"
        : "+f"(d.x), "+f"(d.y), "+f"(d.z), "+f"(d.w)
        : "r"(a0), "r"(a1), "r"(a2), "r"(a3), "r"(b0), "r"(b1));
}
// x3: acc += hi*hi + hi*lo + lo*hi
__device__ __forceinline__ void mma_x3(float4& d,
    const uint32_t ah[4], const uint32_t al[4],
    uint32_t bh0, uint32_t bh1, uint32_t bl0, uint32_t bl1)
{
    mma_bf16(d, ah[0], ah[1], ah[2], ah[3], bh0, bh1);
    mma_bf16(d, ah[0], ah[1], ah[2], ah[3], bl0, bl1);
    mma_bf16(d, al[0], al[1], al[2], al[3], bh0, bh1);
}

// ---------------------------------------------------------------------------
// Spectral norms: 4 blocks, computes only 1/sigma into d_invs (fp32 exact)
// ---------------------------------------------------------------------------
__global__ void spectral4_kernel(const float* __restrict__ kt, const float* __restrict__ ut,
                                 const float* __restrict__ kp, const float* __restrict__ up,
                                 const float* __restrict__ kg, const float* __restrict__ ug,
                                 const float* __restrict__ ka, const float* __restrict__ ua)
{
    const float* W; const float* u; int Cin, Cout;
    switch (blockIdx.x) {
        case 0:  W = kt; u = ut; Cin = 512; Cout = 64;  break;
        case 1:  W = kp; u = up; Cin = 512; Cout = 64;  break;
        case 2:  W = kg; u = ug; Cin = 512; Cout = 256; break;
        default: W = ka; u = ua; Cin = 256; Cout = 512; break;
    }
    __shared__ float us[512];
    __shared__ float v[512];
    __shared__ float red[256];
    const int t = threadIdx.x;

    for (int j = t; j < Cout; j += 256) us[j] = u[j];
    __syncthreads();

    for (int i = t; i < Cin; i += 256) {
        const float4* wr = (const float4*)(W + (size_t)i * Cout);
        float s = 0.f;
        for (int j = 0; j < Cout / 4; j++) {
            float4 w4 = wr[j];
            s += us[4*j] * w4.x + us[4*j+1] * w4.y + us[4*j+2] * w4.z + us[4*j+3] * w4.w;
        }
        v[i] = s;
    }
    __syncthreads();

    float ss = 0.f;
    for (int i = t; i < Cin; i += 256) ss += v[i] * v[i];
    red[t] = ss; __syncthreads();
    for (int o = 128; o; o >>= 1) { if (t < o) red[t] += red[t + o]; __syncthreads(); }
    float inv_vn = 1.0f / (sqrtf(red[0]) + 1e-12f);
    __syncthreads();

    float rr = 0.f;
    for (int j = t; j < Cout; j += 256) {
        float s = 0.f;
        for (int i = 0; i < Cin; i++) s += v[i] * W[(size_t)i * Cout + j];
        s *= inv_vn;
        rr += s * s;
    }
    red[t] = rr; __syncthreads();
    for (int o = 128; o; o >>= 1) { if (t < o) red[t] += red[t + o]; __syncthreads(); }
    if (t == 0) {
        float rn = red[0];
        d_invs[blockIdx.x] = (sqrtf(rn) + 1e-12f) / rn;   // 1/sigma
    }
}

// ---------------------------------------------------------------------------
// bf16x3 GEMM: C = A[M,K] @ W[K,N]
// Block 128x128x32, 8 warps (4m x 2n), warp tile 32x64, m16n8k16.
// Smem: A as [m][k/2] u32 pairs (stride 20), B transposed [n][k/2] (stride 20),
// both with hi/lo copies. Conflict-free fragment loads.
// MODE 0: dual output theta|phi; MODE 1: single (invs[2]); MODE 2: residual.
// ---------------------------------------------------------------------------
#define GBM 128
#define GBN 128
#define GBK 32
#define KP   16     // k-pairs per tile
#define TSTR 20     // (20*g + tg) mod 32 all-distinct

template<int MODE>
__global__ __launch_bounds__(256)
void gemm_x3(const float* __restrict__ A,
             const float* __restrict__ W0, const float* __restrict__ W1,
             float* __restrict__ C0, float* __restrict__ C1,
             int M, int N, int K,
             const float* __restrict__ X, const float* __restrict__ sigma_ptr)
{
    __shared__ uint32_t Ah[GBM * TSTR], Al[GBM * TSTR];
    __shared__ uint32_t Bh[GBN * TSTR], Bl[GBN * TSTR];

    const int bm = blockIdx.y * GBM;
    const int bn = blockIdx.x * GBN;
    const int t = threadIdx.x;
    const int warp = t >> 5, lane = t & 31;
    const int g = lane >> 2, tg = lane & 3;
    const int wm = (warp >> 1) * 32;
    const int wn = (warp & 1) * 64;

    float4 acc[2][8];
    #pragma unroll
    for (int i = 0; i < 2; i++)
        #pragma unroll
        for (int j = 0; j < 8; j++) acc[i][j] = make_float4(0.f, 0.f, 0.f, 0.f);

    for (int k0 = 0; k0 < K; k0 += GBK) {
        // --- stage A: 128 rows x 32 k -> pairs
        #pragma unroll
        for (int p = 0; p < 4; p++) {
            int idx = t + p * 256;
            int row = idx >> 3, c4 = (idx & 7) * 4;
            float4 v = *(const float4*)&A[(size_t)(bm + row) * K + k0 + c4];
            uint32_t h0, l0, h1, l1;
            split2(v.x, v.y, h0, l0);
            split2(v.z, v.w, h1, l1);
            int o = row * TSTR + (c4 >> 1);
            Ah[o] = h0; Ah[o + 1] = h1;
            Al[o] = l0; Al[o + 1] = l1;
        }
        // --- stage B transposed: task = (kpair j, n-group of 4)
        #pragma unroll
        for (int p = 0; p < 2; p++) {
            int idx = t + p * 256;
            int j = idx & 15, n0 = (idx >> 4) * 4;
            float4 v0, v1;
            if (MODE == 0) {
                const float* Wc = (n0 < 64) ? W0 : W1;
                int nn = (n0 < 64) ? n0 : n0 - 64;
                v0 = *(const float4*)&Wc[(size_t)(k0 + 2*j)     * 64 + nn];
                v1 = *(const float4*)&Wc[(size_t)(k0 + 2*j + 1) * 64 + nn];
            } else {
                v0 = *(const float4*)&W0[(size_t)(k0 + 2*j)     * N + bn + n0];
                v1 = *(const float4*)&W0[(size_t)(k0 + 2*j + 1) * N + bn + n0];
            }
            const float a0[4] = {v0.x, v0.y, v0.z, v0.w};
            const float a1[4] = {v1.x, v1.y, v1.z, v1.w};
            #pragma unroll
            for (int q = 0; q < 4; q++) {
                uint32_t h, l;
                split2(a0[q], a1[q], h, l);
                Bh[(n0 + q) * TSTR + j] = h;
                Bl[(n0 + q) * TSTR + j] = l;
            }
        }
        __syncthreads();

        #pragma unroll
        for (int s = 0; s < 2; s++) {           // two k16 chunks
            uint32_t ah[2][4], al[2][4];
            #pragma unroll
            for (int mf = 0; mf < 2; mf++) {
                int m = wm + mf * 16 + g;
                int o  = m * TSTR + s * 8 + tg;
                int o8 = (m + 8) * TSTR + s * 8 + tg;
                ah[mf][0] = Ah[o];  ah[mf][1] = Ah[o8];
                ah[mf][2] = Ah[o + 4]; ah[mf][3] = Ah[o8 + 4];
                al[mf][0] = Al[o];  al[mf][1] = Al[o8];
                al[mf][2] = Al[o + 4]; al[mf][3] = Al[o8 + 4];
            }
            #pragma unroll
            for (int nf = 0; nf < 8; nf++) {
                int n = wn + nf * 8 + g;
                uint32_t bh0 = Bh[n * TSTR + s * 8 + tg];
                uint32_t bh1 = Bh[n * TSTR + s * 8 + tg + 4];
                uint32_t bl0 = Bl[n * TSTR + s * 8 + tg];
                uint32_t bl1 = Bl[n * TSTR + s * 8 + tg + 4];
                mma_x3(acc[0][nf], ah[0], al[0], bh0, bh1, bl0, bl1);
                mma_x3(acc[1][nf], ah[1], al[1], bh0, bh1, bl0, bl1);
            }
        }
        __syncthreads();
    }

    float s0 = 0.f, s1 = 0.f;
    if (MODE == 0)      { s0 = d_invs[0]; s1 = d_invs[1]; }
    else if (MODE == 1) { s0 = d_invs[2]; }
    else                { s0 = d_invs[3] * __ldg(sigma_ptr); }

    #pragma unroll
    for (int mf = 0; mf < 2; mf++) {
        int row = bm + wm + mf * 16 + g;
        #pragma unroll
        for (int nf = 0; nf < 8; nf++) {
            int coln = wn + nf * 8 + 2 * tg;
            float4 c = acc[mf][nf];
            if (MODE == 0) {
                float sc = (coln < 64) ? s0 : s1;
                float* dst = (coln < 64) ? C0 : C1;
                int cc = (coln < 64) ? coln : coln - 64;
                *(float2*)&dst[(size_t)row * 64 + cc]       = make_float2(c.x * sc, c.y * sc);
                *(float2*)&dst[(size_t)(row + 8) * 64 + cc] = make_float2(c.z * sc, c.w * sc);
            } else if (MODE == 1) {
                int col = bn + coln;
                *(float2*)&C0[(size_t)row * N + col]       = make_float2(c.x * s0, c.y * s0);
                *(float2*)&C0[(size_t)(row + 8) * N + col] = make_float2(c.z * s0, c.w * s0);
            } else {
                int col = bn + coln;
                size_t i0 = (size_t)row * N + col;
                size_t i1 = (size_t)(row + 8) * N + col;
                float2 x0 = *(const float2*)&X[i0];
                float2 x1 = *(const float2*)&X[i1];
                *(float2*)&C0[i0] = make_float2(x0.x + s0 * c.x, x0.y + s0 * c.y);
                *(float2*)&C0[i1] = make_float2(x1.x + s0 * c.z, x1.y + s0 * c.w);
            }
        }
    }
}

// ---------------------------------------------------------------------------
// 2x2 max pool: [B,64,64,C] -> [B,32,32,C]
// ---------------------------------------------------------------------------
__global__ void pool_kernel(const float* __restrict__ in, float* __restrict__ out,
                            int C, int total)
{
    int idx = blockIdx.x * blockDim.x + threadIdx.x;
    if (idx >= total) return;
    int c  = idx % C;
    int r  = idx / C;
    int w2 = r % 32; r /= 32;
    int h2 = r % 32; r /= 32;
    int b  = r;
    const float* p = in + (((size_t)(b * 64 + h2 * 2)) * 64 + w2 * 2) * C + c;
    float m0 = fmaxf(p[0], p[C]);
    float m1 = fmaxf(p[(size_t)64 * C], p[(size_t)65 * C]);
    out[idx] = fmaxf(m0, m1);
}

// ---------------------------------------------------------------------------
// Fused attention (bf16x3): scores = theta@phi^T, softmax, P@g
// Block = 32 query rows, 8 warps. Scores: 2m x 4n warps over 128-wide phi
// chunks. PV: 2m x 4n warps over 256 cols, 64-deep g chunks.
// ---------------------------------------------------------------------------
#define AROWS 32
#define QSTR  36      // q pairs stride: (36g+tg)%32 distinct
#define SSTR  1028    // fp32 score stride
#define NSTR  36      // staged-B [n][k/2] stride
#define QS_U  (32 * QSTR)              // per copy
#define SC_U  (32 * SSTR)
#define ST_U  (256 * NSTR)             // per copy (g chunk; phi chunk fits: 128*36)
#define ATTN_SMEM ((2*QS_U + SC_U + 2*ST_U) * 4)

__global__ __launch_bounds__(256)
void attn_x3(const float* __restrict__ theta,
             const float* __restrict__ phi,
             const float* __restrict__ gmat,
             float* __restrict__ attng)
{
    extern __shared__ uint32_t smu[];
    uint32_t* qh = smu;                    // [32][QSTR]
    uint32_t* ql = qh + QS_U;
    float*    scores = (float*)(ql + QS_U);  // [32][SSTR]
    uint32_t* sth = (uint32_t*)scores + SC_U; // staged B hi [n][NSTR]
    uint32_t* stl = sth + ST_U;               // staged B lo

    const int b  = blockIdx.y;
    const int n0 = blockIdx.x * AROWS;
    const int t  = threadIdx.x;
    const int warp = t >> 5, lane = t & 31;
    const int g_ = lane >> 2, tg = lane & 3;
    const int wm = (warp >> 2) * 16;   // 0 or 16
    const int wq = warp & 3;

    // theta tile -> q hi/lo pairs
    #pragma unroll
    for (int p = 0; p < 2; p++) {
        int idx = t + p * 256;
        int row = idx >> 4, c4 = (idx & 15) * 4;
        float4 v = *(const float4*)&theta[((size_t)b * LOC + n0 + row) * C8 + c4];
        uint32_t h0, l0, h1, l1;
        split2(v.x, v.y, h0, l0);
        split2(v.z, v.w, h1, l1);
        int o = row * QSTR + (c4 >> 1);
        qh[o] = h0; qh[o + 1] = h1;
        ql[o] = l0; ql[o + 1] = l1;
    }

    // ---- scores ----
    for (int mb = 0; mb < DOWN; mb += 128) {
        __syncthreads();
        // stage phi chunk: [n=phi row][k/2] pairs (k contiguous in gmem)
        #pragma unroll
        for (int p = 0; p < 8; p++) {
            int idx = t + p * 256;
            int row = idx & 127, c4 = (idx >> 7) * 4;
            float4 v = *(const float4*)&phi[((size_t)b * DOWN + mb + row) * C8 + c4];
            uint32_t h0, l0, h1, l1;
            split2(v.x, v.y, h0, l0);
            split2(v.z, v.w, h1, l1);
            int o = row * NSTR + (c4 >> 1);
            sth[o] = h0; sth[o + 1] = h1;
            stl[o] = l0; stl[o + 1] = l1;
        }
        __syncthreads();

        float4 sc[4];
        #pragma unroll
        for (int nf = 0; nf < 4; nf++) sc[nf] = make_float4(0.f, 0.f, 0.f, 0.f);

        #pragma unroll
        for (int s = 0; s < 4; s++) {     // K=64 -> 4 k16 chunks
            int m = wm + g_;
            int o  = m * QSTR + s * 8 + tg;
            int o8 = (m + 8) * QSTR + s * 8 + tg;
            uint32_t ah[4] = {qh[o], qh[o8], qh[o + 4], qh[o8 + 4]};
            uint32_t al[4] = {ql[o], ql[o8], ql[o + 4], ql[o8 + 4]};
            #pragma unroll
            for (int nf = 0; nf < 4; nf++) {
                int n = wq * 32 + nf * 8 + g_;
                uint32_t bh0 = sth[n * NSTR + s * 8 + tg];
                uint32_t bh1 = sth[n * NSTR + s * 8 + tg + 4];
                uint32_t bl0 = stl[n * NSTR + s * 8 + tg];
                uint32_t bl1 = stl[n * NSTR + s * 8 + tg + 4];
                mma_x3(sc[nf], ah, al, bh0, bh1, bl0, bl1);
            }
        }
        #pragma unroll
        for (int nf = 0; nf < 4; nf++) {
            int n = mb + wq * 32 + nf * 8 + 2 * tg;
            *(float2*)&scores[(wm + g_) * SSTR + n]     = make_float2(sc[nf].x, sc[nf].y);
            *(float2*)&scores[(wm + 8 + g_) * SSTR + n] = make_float2(sc[nf].z, sc[nf].w);
        }
    }
    __syncthreads();

    // ---- softmax: 8 threads per row ----
    {
        const int r  = t >> 3;
        const int l8 = t & 7;
        float* srow = scores + r * SSTR;
        float mx = -1e30f;
        for (int j = l8; j < DOWN; j += 8) mx = fmaxf(mx, srow[j]);
        #pragma unroll
        for (int o = 4; o; o >>= 1) mx = fmaxf(mx, __shfl_xor_sync(0xffffffffu, mx, o));
        float sum = 0.f;
        for (int j = l8; j < DOWN; j += 8) {
            float e = __expf(srow[j] - mx);
            srow[j] = e;
            sum += e;
        }
        #pragma unroll
        for (int o = 4; o; o >>= 1) sum += __shfl_xor_sync(0xffffffffu, sum, o);
        float inv = 1.0f / sum;
        for (int j = l8; j < DOWN; j += 8) srow[j] *= inv;
    }
    __syncthreads();

    // ---- PV: out[32][256] = P[32][1024] @ g[1024][256] ----
    const int wn2 = (warp & 3) * 64;
    float4 oc[8];
    #pragma unroll
    for (int nf = 0; nf < 8; nf++) oc[nf] = make_float4(0.f, 0.f, 0.f, 0.f);

    for (int kb = 0; kb < DOWN; kb += 64) {
        __syncthreads();
        // stage g chunk: [n=channel][k/2] pairs — pair along k needs 2 rows
        #pragma unroll
        for (int p = 0; p < 8; p++) {
            int idx = t + p * 256;
            int j = idx & 31, nn = (idx >> 5) * 4;   // kpair j<32, n-group
            const float* gp0 = &gmat[((size_t)b * DOWN + kb + 2*j)     * C2 + nn];
            const float* gp1 = &gmat[((size_t)b * DOWN + kb + 2*j + 1) * C2 + nn];
            float4 v0 = *(const float4*)gp0;
            float4 v1 = *(const float4*)gp1;
            const float a0[4] = {v0.x, v0.y, v0.z, v0.w};
            const float a1[4] = {v1.x, v1.y, v1.z, v1.w};
            #pragma unroll
            for (int q = 0; q < 4; q++) {
                uint32_t h, l;
                split2(a0[q], a1[q], h, l);
                sth[(nn + q) * NSTR + j] = h;
                stl[(nn + q) * NSTR + j] = l;
            }
        }
        __syncthreads();

        #pragma unroll
        for (int s = 0; s < 4; s++) {     // 64 k -> 4 chunks of 16
            int kk = kb + s * 16;
            float2 p00 = *(const float2*)&scores[(wm + g_) * SSTR + kk + 2*tg];
            float2 p08 = *(const float2*)&scores[(wm + 8 + g_) * SSTR + kk + 2*tg];
            float2 p80 = *(const float2*)&scores[(wm + g_) * SSTR + kk + 2*tg + 8];
            float2 p88 = *(const float2*)&scores[(wm + 8 + g_) * SSTR + kk + 2*tg + 8];
            uint32_t ah[4], al[4];
            split2(p00.x, p00.y, ah[0], al[0]);
            split2(p08.x, p08.y, ah[1], al[1]);
            split2(p80.x, p80.y, ah[2], al[2]);
            split2(p88.x, p88.y, ah[3], al[3]);
            #pragma unroll
            for (int nf = 0; nf < 8; nf++) {
                int n = wn2 + nf * 8 + g_;
                uint32_t bh0 = sth[n * NSTR + s * 8 + tg];
                uint32_t bh1 = sth[n * NSTR + s * 8 + tg + 4];
                uint32_t bl0 = stl[n * NSTR + s * 8 + tg];
                uint32_t bl1 = stl[n * NSTR + s * 8 + tg + 4];
                mma_x3(oc[nf], ah, al, bh0, bh1, bl0, bl1);
            }
        }
    }

    #pragma unroll
    for (int nf = 0; nf < 8; nf++) {
        int col = wn2 + nf * 8 + 2 * tg;
        size_t i0 = ((size_t)b * LOC + n0 + wm + g_) * C2 + col;
        size_t i1 = ((size_t)b * LOC + n0 + wm + 8 + g_) * C2 + col;
        *(float2*)&attng[i0] = make_float2(oc[nf].x, oc[nf].y);
        *(float2*)&attng[i1] = make_float2(oc[nf].z, oc[nf].w);
    }
}

// ---------------------------------------------------------------------------
// kernel_launch
// ---------------------------------------------------------------------------
extern "C" void kernel_launch(void* const* d_in, const int* in_sizes, int n_in,
                              void* d_out, int out_size)
{
    const float* x       = (const float*)d_in[0];
    const float* k_theta = (const float*)d_in[1];
    const float* u_theta = (const float*)d_in[2];
    const float* k_phi   = (const float*)d_in[3];
    const float* u_phi   = (const float*)d_in[4];
    const float* k_g     = (const float*)d_in[5];
    const float* u_g     = (const float*)d_in[6];
    const float* k_attn  = (const float*)d_in[7];
    const float* u_attn  = (const float*)d_in[8];
    const float* sigma   = (const float*)d_in[9];
    float* out = (float*)d_out;

    float *theta, *phifull, *phip, *gfull, *gp, *attng;
    cudaGetSymbolAddress((void**)&theta,   d_theta);
    cudaGetSymbolAddress((void**)&phifull, d_phifull);
    cudaGetSymbolAddress((void**)&phip,    d_phip);
    cudaGetSymbolAddress((void**)&gfull,   d_gfull);
    cudaGetSymbolAddress((void**)&gp,      d_gp);
    cudaGetSymbolAddress((void**)&attng,   d_attng);

    cudaFuncSetAttribute(attn_x3,
                         cudaFuncAttributeMaxDynamicSharedMemorySize, ATTN_SMEM);

    // spectral norms (one launch, inv_sigma only)
    spectral4_kernel<<<4, 256>>>(k_theta, u_theta, k_phi, u_phi,
                                 k_g, u_g, k_attn, u_attn);

    // theta+phi fused conv (N=128 dual output)
    gemm_x3<0><<<dim3(1, MTOT / GBM), 256>>>(x, k_theta, k_phi, theta, phifull,
                                             MTOT, 128, CC, nullptr, nullptr);
    // g conv (N=256)
    gemm_x3<1><<<dim3(C2 / GBN, MTOT / GBM), 256>>>(x, k_g, nullptr, gfull, nullptr,
                                                    MTOT, C2, CC, nullptr, nullptr);

    // pooling
    int phi_total = B_ * DOWN * C8;
    int g_total   = B_ * DOWN * C2;
    pool_kernel<<<(phi_total + 255) / 256, 256>>>(phifull, phip, C8, phi_total);
    pool_kernel<<<(g_total   + 255) / 256, 256>>>(gfull,   gp,   C2, g_total);

    // fused attention
    attn_x3<<<dim3(LOC / AROWS, B_), 256, ATTN_SMEM>>>(theta, phip, gp, attng);

    // output conv + residual (N=512, K=256)
    gemm_x3<2><<<dim3(CC / GBN, MTOT / GBM), 256>>>(attng, k_attn, nullptr, out, nullptr,
                                                    MTOT, CC, C2, x, sigma);
}

// round 5
// speedup vs baseline: 2.2879x; 1.3704x over previous
#include <cuda_runtime.h>
#include <cuda_bf16.h>
#include <math.h>
#include <stdint.h>

// ---------------------------------------------------------------------------
// Problem constants
// ---------------------------------------------------------------------------
#define B_   16
#define CC   512
#define C8   64
#define C2   256
#define LOC  4096
#define DOWN 1024
#define MTOT 65536

// ---------------------------------------------------------------------------
// Device scratch: bf16 hi/lo "planes" = packed bf16x2 (u32), pairs along k
// ---------------------------------------------------------------------------
__device__ float d_invs[4];
__device__ uint32_t d_xh   [MTOT * 256];         // x  [65536][512/2]
__device__ uint32_t d_xl   [MTOT * 256];
__device__ uint32_t d_wtpTh[128 * 256];          // theta|phi weights, transposed
__device__ uint32_t d_wtpTl[128 * 256];
__device__ uint32_t d_wgTh [256 * 256];
__device__ uint32_t d_wgTl [256 * 256];
__device__ uint32_t d_waTh [512 * 128];
__device__ uint32_t d_waTl [512 * 128];
__device__ uint32_t d_thh  [MTOT * 32];          // theta [65536][64/2]
__device__ uint32_t d_thl  [MTOT * 32];
__device__ float    d_phifull[MTOT * C8];        // fp32 (pooled later)
__device__ uint32_t d_phh  [B_ * DOWN * 32];     // pooled phi planes
__device__ uint32_t d_phl  [B_ * DOWN * 32];
__device__ float    d_gfull[MTOT * C2];          // fp32 (pooled later)
__device__ uint32_t d_gTh  [B_ * C2 * 512];      // pooled g, transposed [b][c][down/2]
__device__ uint32_t d_gTl  [B_ * C2 * 512];
__device__ uint32_t d_agh  [MTOT * 128];         // attn_g [65536][256/2]
__device__ uint32_t d_agl  [MTOT * 128];

// ---------------------------------------------------------------------------
// helpers
// ---------------------------------------------------------------------------
__device__ __forceinline__ uint32_t pack2(float a, float b) {
    __nv_bfloat162 h = __floats2bfloat162_rn(a, b);
    return *(uint32_t*)&h;
}
__device__ __forceinline__ void split2(float a, float b, uint32_t& hi, uint32_t& lo) {
    float ha = __bfloat162float(__float2bfloat16_rn(a));
    float hb = __bfloat162float(__float2bfloat16_rn(b));
    hi = pack2(ha, hb);
    lo = pack2(a - ha, b - hb);
}
__device__ __forceinline__ void mma_bf16(float4& d,
    uint32_t a0, uint32_t a1, uint32_t a2, uint32_t a3, uint32_t b0, uint32_t b1)
{
    asm volatile("mma.sync.aligned.m16n8k16.row.col.f32.bf16.bf16.f32 "
        "{%0,%1,%2,%3}, {%4,%5,%6,%7}, {%8,%9}, {%0,%1,%2,%3};"
        : "+f"(d.x), "+f"(d.y), "+f"(d.z), "+f"(d.w)
        : "r"(a0), "r"(a1), "r"(a2), "r"(a3), "r"(b0), "r"(b1));
}
__device__ __forceinline__ void mma_x3(float4& d,
    const uint32_t ah[4], const uint32_t al[4],
    uint32_t bh0, uint32_t bh1, uint32_t bl0, uint32_t bl1)
{
    mma_bf16(d, ah[0], ah[1], ah[2], ah[3], bh0, bh1);
    mma_bf16(d, ah[0], ah[1], ah[2], ah[3], bl0, bl1);
    mma_bf16(d, al[0], al[1], al[2], al[3], bh0, bh1);
}
__device__ __forceinline__ void cp16(uint32_t* dst, const uint32_t* src) {
    uint32_t d = (uint32_t)__cvta_generic_to_shared(dst);
    asm volatile("cp.async.cg.shared.global [%0], [%1], 16;\n" :: "r"(d), "l"(src));
}
__device__ __forceinline__ void cp_commit() {
    asm volatile("cp.async.commit_group;\n" ::: "memory");
}

// ---------------------------------------------------------------------------
// prep kernels
// ---------------------------------------------------------------------------
__global__ void prep_x(const float* __restrict__ x,
                       uint32_t* __restrict__ xh, uint32_t* __restrict__ xl)
{
    size_t idx = (size_t)blockIdx.x * 256 + threadIdx.x;   // 4M threads
    const float4* p = (const float4*)(x + idx * 8);
    float4 v0 = p[0], v1 = p[1];
    uint32_t h0,l0,h1,l1,h2,l2,h3,l3;
    split2(v0.x, v0.y, h0, l0); split2(v0.z, v0.w, h1, l1);
    split2(v1.x, v1.y, h2, l2); split2(v1.z, v1.w, h3, l3);
    *(uint4*)&xh[idx * 4] = make_uint4(h0, h1, h2, h3);
    *(uint4*)&xl[idx * 4] = make_uint4(l0, l1, l2, l3);
}

__global__ void prep_w(const float* __restrict__ kt, const float* __restrict__ kp,
                       const float* __restrict__ kg, const float* __restrict__ ka,
                       uint32_t* __restrict__ tpTh, uint32_t* __restrict__ tpTl,
                       uint32_t* __restrict__ gTh,  uint32_t* __restrict__ gTl,
                       uint32_t* __restrict__ aTh,  uint32_t* __restrict__ aTl)
{
    int i = blockIdx.x * 256 + threadIdx.x;
    if (i < 32768) {
        int n = i >> 8, j = i & 255;
        float a, b;
        if (n < 64) { a = kt[(2*j)*64 + n];      b = kt[(2*j+1)*64 + n]; }
        else        { a = kp[(2*j)*64 + n - 64]; b = kp[(2*j+1)*64 + n - 64]; }
        uint32_t h, l; split2(a, b, h, l);
        tpTh[i] = h; tpTl[i] = l;
    } else if (i < 98304) {
        int i2 = i - 32768; int n = i2 >> 8, j = i2 & 255;
        float a = kg[(2*j)*256 + n], b = kg[(2*j+1)*256 + n];
        uint32_t h, l; split2(a, b, h, l);
        gTh[i2] = h; gTl[i2] = l;
    } else if (i < 163840) {
        int i2 = i - 98304; int n = i2 >> 7, j = i2 & 127;
        float a = ka[(2*j)*512 + n], b = ka[(2*j+1)*512 + n];
        uint32_t h, l; split2(a, b, h, l);
        aTh[i2] = h; aTl[i2] = l;
    }
}

// ---------------------------------------------------------------------------
// Spectral norms (unchanged): 4 blocks, 1/sigma -> d_invs
// ---------------------------------------------------------------------------
__global__ void spectral4_kernel(const float* __restrict__ kt, const float* __restrict__ ut,
                                 const float* __restrict__ kp, const float* __restrict__ up,
                                 const float* __restrict__ kg, const float* __restrict__ ug,
                                 const float* __restrict__ ka, const float* __restrict__ ua)
{
    const float* W; const float* u; int Cin, Cout;
    switch (blockIdx.x) {
        case 0:  W = kt; u = ut; Cin = 512; Cout = 64;  break;
        case 1:  W = kp; u = up; Cin = 512; Cout = 64;  break;
        case 2:  W = kg; u = ug; Cin = 512; Cout = 256; break;
        default: W = ka; u = ua; Cin = 256; Cout = 512; break;
    }
    __shared__ float us[512];
    __shared__ float v[512];
    __shared__ float red[256];
    const int t = threadIdx.x;

    for (int j = t; j < Cout; j += 256) us[j] = u[j];
    __syncthreads();
    for (int i = t; i < Cin; i += 256) {
        const float4* wr = (const float4*)(W + (size_t)i * Cout);
        float s = 0.f;
        for (int j = 0; j < Cout / 4; j++) {
            float4 w4 = wr[j];
            s += us[4*j]*w4.x + us[4*j+1]*w4.y + us[4*j+2]*w4.z + us[4*j+3]*w4.w;
        }
        v[i] = s;
    }
    __syncthreads();
    float ss = 0.f;
    for (int i = t; i < Cin; i += 256) ss += v[i] * v[i];
    red[t] = ss; __syncthreads();
    for (int o = 128; o; o >>= 1) { if (t < o) red[t] += red[t + o]; __syncthreads(); }
    float inv_vn = 1.0f / (sqrtf(red[0]) + 1e-12f);
    __syncthreads();
    float rr = 0.f;
    for (int j = t; j < Cout; j += 256) {
        float s = 0.f;
        for (int i = 0; i < Cin; i++) s += v[i] * W[(size_t)i * Cout + j];
        s *= inv_vn;
        rr += s * s;
    }
    red[t] = rr; __syncthreads();
    for (int o = 128; o; o >>= 1) { if (t < o) red[t] += red[t + o]; __syncthreads(); }
    if (t == 0) {
        float rn = red[0];
        d_invs[blockIdx.x] = (sqrtf(rn) + 1e-12f) / rn;
    }
}

// ---------------------------------------------------------------------------
// bf16x3 GEMM v2: copy-only staging + cp.async double buffering
// Block 128x128, k-tile 32 (16 pairs), 8 warps (4m x 2n), warp 32x64.
// A planes [M][KP], B planes [N][KP] (pre-transposed). Stride-20 smem.
// ---------------------------------------------------------------------------
#define PLANE 2560          // 128 rows * 20
#define GEMM_SMEM (8 * PLANE * 4)

__device__ __forceinline__ void gemm2_compute(
    const uint32_t* __restrict__ sAh, const uint32_t* __restrict__ sAl,
    const uint32_t* __restrict__ sBh, const uint32_t* __restrict__ sBl,
    int wm, int wn, int g, int tg, float4 acc[2][8])
{
    #pragma unroll
    for (int s = 0; s < 2; s++) {
        uint32_t ah[2][4], al[2][4];
        #pragma unroll
        for (int mf = 0; mf < 2; mf++) {
            int o  = (wm + mf*16 + g) * 20 + s*8 + tg;
            int o8 = o + 8 * 20;
            ah[mf][0] = sAh[o]; ah[mf][1] = sAh[o8];
            ah[mf][2] = sAh[o+4]; ah[mf][3] = sAh[o8+4];
            al[mf][0] = sAl[o]; al[mf][1] = sAl[o8];
            al[mf][2] = sAl[o+4]; al[mf][3] = sAl[o8+4];
        }
        #pragma unroll
        for (int nf = 0; nf < 8; nf++) {
            int o = (wn + nf*8 + g) * 20 + s*8 + tg;
            uint32_t bh0 = sBh[o], bh1 = sBh[o+4];
            uint32_t bl0 = sBl[o], bl1 = sBl[o+4];
            mma_x3(acc[0][nf], ah[0], al[0], bh0, bh1, bl0, bl1);
            mma_x3(acc[1][nf], ah[1], al[1], bh0, bh1, bl0, bl1);
        }
    }
}

template<int MODE>
__global__ __launch_bounds__(256)
void gemm2(const uint32_t* __restrict__ Ah, const uint32_t* __restrict__ Al,
           const uint32_t* __restrict__ Bh, const uint32_t* __restrict__ Bl,
           uint32_t* __restrict__ oph, uint32_t* __restrict__ opl,
           float* __restrict__ of,
           const float* __restrict__ X, const float* __restrict__ sigma_ptr,
           int N, int KP)
{
    extern __shared__ uint32_t smg[];
    uint32_t* sAh = smg;
    uint32_t* sAl = smg + 2 * PLANE;
    uint32_t* sBh = smg + 4 * PLANE;
    uint32_t* sBl = smg + 6 * PLANE;

    const int bm = blockIdx.y * 128;
    const int bn = blockIdx.x * 128;
    const int t = threadIdx.x;
    const int warp = t >> 5, lane = t & 31, g = lane >> 2, tg = lane & 3;
    const int wm = (warp >> 1) * 32, wn = (warp & 1) * 64;
    const int rs = t >> 1;            // staging row
    const int hf = (t & 1) * 8;       // staging k offset (u32)
    const int sidx = rs * 20 + hf;

    const uint32_t* pAh = Ah + (size_t)(bm + rs) * KP + hf;
    const uint32_t* pAl = Al + (size_t)(bm + rs) * KP + hf;
    const uint32_t* pBh = Bh + (size_t)(bn + rs) * KP + hf;
    const uint32_t* pBl = Bl + (size_t)(bn + rs) * KP + hf;

    float4 acc[2][8];
    #pragma unroll
    for (int i = 0; i < 2; i++)
        #pragma unroll
        for (int j = 0; j < 8; j++) acc[i][j] = make_float4(0.f, 0.f, 0.f, 0.f);

    const int nt = KP / 16;

    #define PREF(kt_, buf_) do {                                     \
        size_t off = (size_t)(kt_) * 16;                             \
        uint32_t* d;                                                  \
        d = sAh + (buf_) * PLANE + sidx;                              \
        cp16(d, pAh + off); cp16(d + 4, pAh + off + 4);               \
        d = sAl + (buf_) * PLANE + sidx;                              \
        cp16(d, pAl + off); cp16(d + 4, pAl + off + 4);               \
        d = sBh + (buf_) * PLANE + sidx;                              \
        cp16(d, pBh + off); cp16(d + 4, pBh + off + 4);               \
        d = sBl + (buf_) * PLANE + sidx;                              \
        cp16(d, pBl + off); cp16(d + 4, pBl + off + 4);               \
    } while (0)

    PREF(0, 0);
    cp_commit();

    for (int kt = 0; kt < nt; kt++) {
        int cur = kt & 1;
        bool more = (kt + 1 < nt);
        if (more) { PREF(kt + 1, cur ^ 1); cp_commit(); }
        if (more) asm volatile("cp.async.wait_group 1;\n" ::: "memory");
        else      asm volatile("cp.async.wait_group 0;\n" ::: "memory");
        __syncthreads();
        gemm2_compute(sAh + cur*PLANE, sAl + cur*PLANE,
                      sBh + cur*PLANE, sBl + cur*PLANE, wm, wn, g, tg, acc);
        __syncthreads();
    }
    #undef PREF

    // ----- epilogue -----
    float s0 = 0.f, s1 = 0.f;
    if (MODE == 0)      { s0 = d_invs[0]; s1 = d_invs[1]; }
    else if (MODE == 1) { s0 = d_invs[2]; }
    else                { s0 = d_invs[3] * __ldg(sigma_ptr); }

    #pragma unroll
    for (int mf = 0; mf < 2; mf++) {
        int row = bm + wm + mf * 16 + g;
        #pragma unroll
        for (int nf = 0; nf < 8; nf++) {
            int coln = wn + nf * 8 + 2 * tg;
            float4 c = acc[mf][nf];
            if (MODE == 0) {
                if (coln < 64) {
                    // theta -> bf16 planes, pairs along c8
                    int colp = nf * 4 + tg;
                    uint32_t h0, l0, h1, l1;
                    split2(c.x * s0, c.y * s0, h0, l0);
                    split2(c.z * s0, c.w * s0, h1, l1);
                    oph[(size_t)row * 32 + colp]       = h0;
                    opl[(size_t)row * 32 + colp]       = l0;
                    oph[(size_t)(row + 8) * 32 + colp] = h1;
                    opl[(size_t)(row + 8) * 32 + colp] = l1;
                } else {
                    int col = coln - 64;
                    *(float2*)&of[(size_t)row * 64 + col]       = make_float2(c.x * s1, c.y * s1);
                    *(float2*)&of[(size_t)(row + 8) * 64 + col] = make_float2(c.z * s1, c.w * s1);
                }
            } else if (MODE == 1) {
                int col = bn + coln;
                *(float2*)&of[(size_t)row * N + col]       = make_float2(c.x * s0, c.y * s0);
                *(float2*)&of[(size_t)(row + 8) * N + col] = make_float2(c.z * s0, c.w * s0);
            } else {
                int col = bn + coln;
                size_t i0 = (size_t)row * N + col;
                size_t i1 = (size_t)(row + 8) * N + col;
                float2 x0 = *(const float2*)&X[i0];
                float2 x1 = *(const float2*)&X[i1];
                *(float2*)&of[i0] = make_float2(x0.x + s0 * c.x, x0.y + s0 * c.y);
                *(float2*)&of[i1] = make_float2(x1.x + s0 * c.z, x1.y + s0 * c.w);
            }
        }
    }
}

// ---------------------------------------------------------------------------
// pool kernels: pool + split into planes
// ---------------------------------------------------------------------------
__global__ void pool_phi(const float* __restrict__ pf,
                         uint32_t* __restrict__ oh, uint32_t* __restrict__ ol)
{
    int idx = blockIdx.x * 256 + threadIdx.x;   // 524288
    int cp = idx & 31;
    int m  = (idx >> 5) & 1023;
    int b  = idx >> 15;
    int h2 = m >> 5, w2 = m & 31;
    size_t r = (size_t)b * 4096 + h2 * 128 + w2 * 2;
    const float* p = pf + r * 64 + cp * 2;
    float2 v00 = *(const float2*)(p);
    float2 v01 = *(const float2*)(p + 64);
    float2 v10 = *(const float2*)(p + 64 * 64);
    float2 v11 = *(const float2*)(p + 65 * 64);
    float m0 = fmaxf(fmaxf(v00.x, v01.x), fmaxf(v10.x, v11.x));
    float m1 = fmaxf(fmaxf(v00.y, v01.y), fmaxf(v10.y, v11.y));
    uint32_t h, l; split2(m0, m1, h, l);
    oh[idx] = h; ol[idx] = l;
}

__global__ void pool_g(const float* __restrict__ gf,
                       uint32_t* __restrict__ oh, uint32_t* __restrict__ ol)
{
    int idx = blockIdx.x * 256 + threadIdx.x;   // 2097152
    int c  = idx & 255;
    int mp = (idx >> 8) & 511;
    int b  = idx >> 17;
    int m0 = mp * 2;
    int h2 = m0 >> 5, w2 = m0 & 31;
    size_t base = ((size_t)b * 4096 + h2 * 128 + w2 * 2) * 256 + c;
    float a00 = gf[base],           a01 = gf[base + 256];
    float a02 = gf[base + 512],     a03 = gf[base + 768];
    float a10 = gf[base + 64*256],  a11 = gf[base + 65*256];
    float a12 = gf[base + 66*256],  a13 = gf[base + 67*256];
    float q0 = fmaxf(fmaxf(a00, a01), fmaxf(a10, a11));
    float q1 = fmaxf(fmaxf(a02, a03), fmaxf(a12, a13));
    uint32_t h, l; split2(q0, q1, h, l);
    oh[((size_t)b * 256 + c) * 512 + mp] = h;
    ol[((size_t)b * 256 + c) * 512 + mp] = l;
}

// ---------------------------------------------------------------------------
// Fused attention v2: copy-only staging from planes.
// 32 q-rows/block, 8 warps. scores: 128-wide phi chunks. PV: 64-deep g chunks.
// ---------------------------------------------------------------------------
#define SSTR 1028
#define STG  9216                         // 256*36 u32 per plane (g); phi fits 128*36
#define ATTN_SMEM ((2*(32*36) + 32*SSTR + 2*STG) * 4)

__global__ __launch_bounds__(256)
void attn2(const uint32_t* __restrict__ th_h, const uint32_t* __restrict__ th_l,
           const uint32_t* __restrict__ ph_h, const uint32_t* __restrict__ ph_l,
           const uint32_t* __restrict__ gT_h, const uint32_t* __restrict__ gT_l,
           uint32_t* __restrict__ ag_h, uint32_t* __restrict__ ag_l)
{
    extern __shared__ uint32_t sma[];
    uint32_t* qh = sma;                       // [32][36]
    uint32_t* ql = sma + 1152;
    float* scores = (float*)(sma + 2304);     // [32][1028]
    uint32_t* sth = sma + 2304 + 32 * SSTR;   // [*][36] staged B hi
    uint32_t* stl = sth + STG;

    const int b  = blockIdx.y;
    const int n0 = blockIdx.x * 32;
    const int t  = threadIdx.x;
    const int warp = t >> 5, lane = t & 31;
    const int g_ = lane >> 2, tg = lane & 3;
    const int wm = (warp >> 2) * 16;    // 0 or 16
    const int wq = warp & 3;

    // q staging: 32 rows x 32 u32 per plane
    {
        int row = t >> 3, off = (t & 7) * 4;
        size_t src = ((size_t)b * LOC + n0 + row) * 32 + off;
        *(uint4*)&qh[row * 36 + off] = *(const uint4*)&th_h[src];
        *(uint4*)&ql[row * 36 + off] = *(const uint4*)&th_l[src];
    }

    // ---- scores ----
    for (int mb = 0; mb < DOWN; mb += 128) {
        __syncthreads();
        {
            int row = t >> 1, half = (t & 1) * 16;
            size_t src = ((size_t)b * DOWN + mb + row) * 32 + half;
            #pragma unroll
            for (int j = 0; j < 4; j++) {
                *(uint4*)&sth[row * 36 + half + 4*j] = *(const uint4*)&ph_h[src + 4*j];
                *(uint4*)&stl[row * 36 + half + 4*j] = *(const uint4*)&ph_l[src + 4*j];
            }
        }
        __syncthreads();

        float4 sc[4];
        #pragma unroll
        for (int nf = 0; nf < 4; nf++) sc[nf] = make_float4(0.f, 0.f, 0.f, 0.f);

        #pragma unroll
        for (int s = 0; s < 4; s++) {
            int o  = (wm + g_) * 36 + s * 8 + tg;
            int o8 = o + 8 * 36;
            uint32_t ah[4] = {qh[o], qh[o8], qh[o+4], qh[o8+4]};
            uint32_t al[4] = {ql[o], ql[o8], ql[o+4], ql[o8+4]};
            #pragma unroll
            for (int nf = 0; nf < 4; nf++) {
                int n = wq * 32 + nf * 8 + g_;
                int bo = n * 36 + s * 8 + tg;
                mma_x3(sc[nf], ah, al, sth[bo], sth[bo+4], stl[bo], stl[bo+4]);
            }
        }
        #pragma unroll
        for (int nf = 0; nf < 4; nf++) {
            int n = mb + wq * 32 + nf * 8 + 2 * tg;
            *(float2*)&scores[(wm + g_) * SSTR + n]     = make_float2(sc[nf].x, sc[nf].y);
            *(float2*)&scores[(wm + 8 + g_) * SSTR + n] = make_float2(sc[nf].z, sc[nf].w);
        }
    }
    __syncthreads();

    // ---- softmax: 8 threads per row ----
    {
        const int r  = t >> 3;
        const int l8 = t & 7;
        float* srow = scores + r * SSTR;
        float mx = -1e30f;
        for (int j = l8; j < DOWN; j += 8) mx = fmaxf(mx, srow[j]);
        #pragma unroll
        for (int o = 4; o; o >>= 1) mx = fmaxf(mx, __shfl_xor_sync(0xffffffffu, mx, o));
        float sum = 0.f;
        for (int j = l8; j < DOWN; j += 8) {
            float e = __expf(srow[j] - mx);
            srow[j] = e;
            sum += e;
        }
        #pragma unroll
        for (int o = 4; o; o >>= 1) sum += __shfl_xor_sync(0xffffffffu, sum, o);
        float inv = 1.0f / sum;
        for (int j = l8; j < DOWN; j += 8) srow[j] *= inv;
    }
    __syncthreads();

    // ---- PV: out[32][256] = P[32][1024] @ g ----
    const int wn2 = (warp & 3) * 64;
    float4 oc[8];
    #pragma unroll
    for (int nf = 0; nf < 8; nf++) oc[nf] = make_float4(0.f, 0.f, 0.f, 0.f);

    for (int kb = 0; kb < DOWN; kb += 64) {
        __syncthreads();
        {
            // stage gT chunk: 256 channel-rows x 32 kp
            size_t src = ((size_t)b * 256 + t) * 512 + (kb >> 1);
            #pragma unroll
            for (int j = 0; j < 8; j++) {
                *(uint4*)&sth[t * 36 + 4*j] = *(const uint4*)&gT_h[src + 4*j];
                *(uint4*)&stl[t * 36 + 4*j] = *(const uint4*)&gT_l[src + 4*j];
            }
        }
        __syncthreads();

        #pragma unroll
        for (int s = 0; s < 4; s++) {
            int kk = kb + s * 16;
            float2 p00 = *(const float2*)&scores[(wm + g_) * SSTR + kk + 2*tg];
            float2 p08 = *(const float2*)&scores[(wm + 8 + g_) * SSTR + kk + 2*tg];
            float2 p80 = *(const float2*)&scores[(wm + g_) * SSTR + kk + 2*tg + 8];
            float2 p88 = *(const float2*)&scores[(wm + 8 + g_) * SSTR + kk + 2*tg + 8];
            uint32_t ah[4], al[4];
            split2(p00.x, p00.y, ah[0], al[0]);
            split2(p08.x, p08.y, ah[1], al[1]);
            split2(p80.x, p80.y, ah[2], al[2]);
            split2(p88.x, p88.y, ah[3], al[3]);
            #pragma unroll
            for (int nf = 0; nf < 8; nf++) {
                int n = wn2 + nf * 8 + g_;
                int bo = n * 36 + s * 8 + tg;
                mma_x3(oc[nf], ah, al, sth[bo], sth[bo+4], stl[bo], stl[bo+4]);
            }
        }
    }

    // epilogue: write attng planes (pairs along c2)
    #pragma unroll
    for (int nf = 0; nf < 8; nf++) {
        int colp = (wn2 + nf * 8) / 2 + tg;
        size_t r0 = ((size_t)b * LOC + n0 + wm + g_) * 128 + colp;
        size_t r1 = ((size_t)b * LOC + n0 + wm + 8 + g_) * 128 + colp;
        uint32_t h0, l0, h1, l1;
        split2(oc[nf].x, oc[nf].y, h0, l0);
        split2(oc[nf].z, oc[nf].w, h1, l1);
        ag_h[r0] = h0; ag_l[r0] = l0;
        ag_h[r1] = h1; ag_l[r1] = l1;
    }
}

// ---------------------------------------------------------------------------
// kernel_launch
// ---------------------------------------------------------------------------
extern "C" void kernel_launch(void* const* d_in, const int* in_sizes, int n_in,
                              void* d_out, int out_size)
{
    const float* x       = (const float*)d_in[0];
    const float* k_theta = (const float*)d_in[1];
    const float* u_theta = (const float*)d_in[2];
    const float* k_phi   = (const float*)d_in[3];
    const float* u_phi   = (const float*)d_in[4];
    const float* k_g     = (const float*)d_in[5];
    const float* u_g     = (const float*)d_in[6];
    const float* k_attn  = (const float*)d_in[7];
    const float* u_attn  = (const float*)d_in[8];
    const float* sigma   = (const float*)d_in[9];
    float* out = (float*)d_out;

    uint32_t *xh, *xl, *wtpTh, *wtpTl, *wgTh, *wgTl, *waTh, *waTl;
    uint32_t *thh, *thl, *phh, *phl, *gTh, *gTl, *agh, *agl;
    float *phifull, *gfull;
    cudaGetSymbolAddress((void**)&xh,    d_xh);
    cudaGetSymbolAddress((void**)&xl,    d_xl);
    cudaGetSymbolAddress((void**)&wtpTh, d_wtpTh);
    cudaGetSymbolAddress((void**)&wtpTl, d_wtpTl);
    cudaGetSymbolAddress((void**)&wgTh,  d_wgTh);
    cudaGetSymbolAddress((void**)&wgTl,  d_wgTl);
    cudaGetSymbolAddress((void**)&waTh,  d_waTh);
    cudaGetSymbolAddress((void**)&waTl,  d_waTl);
    cudaGetSymbolAddress((void**)&thh,   d_thh);
    cudaGetSymbolAddress((void**)&thl,   d_thl);
    cudaGetSymbolAddress((void**)&phh,   d_phh);
    cudaGetSymbolAddress((void**)&phl,   d_phl);
    cudaGetSymbolAddress((void**)&gTh,   d_gTh);
    cudaGetSymbolAddress((void**)&gTl,   d_gTl);
    cudaGetSymbolAddress((void**)&agh,   d_agh);
    cudaGetSymbolAddress((void**)&agl,   d_agl);
    cudaGetSymbolAddress((void**)&phifull, d_phifull);
    cudaGetSymbolAddress((void**)&gfull,   d_gfull);

    cudaFuncSetAttribute(gemm2<0>, cudaFuncAttributeMaxDynamicSharedMemorySize, GEMM_SMEM);
    cudaFuncSetAttribute(gemm2<1>, cudaFuncAttributeMaxDynamicSharedMemorySize, GEMM_SMEM);
    cudaFuncSetAttribute(gemm2<2>, cudaFuncAttributeMaxDynamicSharedMemorySize, GEMM_SMEM);
    cudaFuncSetAttribute(attn2,    cudaFuncAttributeMaxDynamicSharedMemorySize, ATTN_SMEM);

    // 1: weight transpose+split
    prep_w<<<640, 256>>>(k_theta, k_phi, k_g, k_attn,
                         wtpTh, wtpTl, wgTh, wgTl, waTh, waTl);
    // 2: x split
    prep_x<<<16384, 256>>>(x, xh, xl);
    // 3: spectral norms
    spectral4_kernel<<<4, 256>>>(k_theta, u_theta, k_phi, u_phi,
                                 k_g, u_g, k_attn, u_attn);
    // 4: theta+phi conv (dual output)
    gemm2<0><<<dim3(1, MTOT / 128), 256, GEMM_SMEM>>>(
        xh, xl, wtpTh, wtpTl, thh, thl, phifull, nullptr, nullptr, 128, 256);
    // 5: phi pool -> planes
    pool_phi<<<2048, 256>>>(phifull, phh, phl);
    // 6: g conv  (profiled slot)
    gemm2<1><<<dim3(2, MTOT / 128), 256, GEMM_SMEM>>>(
        xh, xl, wgTh, wgTl, nullptr, nullptr, gfull, nullptr, nullptr, 256, 256);
    // 7: g pool -> transposed planes
    pool_g<<<8192, 256>>>(gfull, gTh, gTl);
    // 8: fused attention
    attn2<<<dim3(LOC / 32, B_), 256, ATTN_SMEM>>>(thh, thl, phh, phl, gTh, gTl, agh, agl);
    // 9: output conv + residual
    gemm2<2><<<dim3(4, MTOT / 128), 256, GEMM_SMEM>>>(
        agh, agl, waTh, waTl, nullptr, nullptr, out, x, sigma, 512, 128);
}

// round 6
// speedup vs baseline: 3.2841x; 1.4354x over previous
#include <cuda_runtime.h>
#include <cuda_bf16.h>
#include <math.h>
#include <stdint.h>

#define B_   16
#define CC   512
#define C8   64
#define C2   256
#define LOC  4096
#define DOWN 1024
#define MTOT 65536

// ---------------------------------------------------------------------------
// Device scratch: bf16 hi/lo planes (packed bf16x2 u32, pairs along k)
// ---------------------------------------------------------------------------
__device__ float d_invs[4];
__device__ uint32_t d_xh   [MTOT * 256];
__device__ uint32_t d_xl   [MTOT * 256];
__device__ uint32_t d_wtpTh[128 * 256];
__device__ uint32_t d_wtpTl[128 * 256];
__device__ uint32_t d_wgTh [256 * 256];
__device__ uint32_t d_wgTl [256 * 256];
__device__ uint32_t d_waTh [512 * 128];
__device__ uint32_t d_waTl [512 * 128];
__device__ uint32_t d_thh  [MTOT * 32];
__device__ uint32_t d_thl  [MTOT * 32];
__device__ float    d_phifull[MTOT * C8];
__device__ uint32_t d_phh  [B_ * DOWN * 32];
__device__ uint32_t d_phl  [B_ * DOWN * 32];
__device__ float    d_gfull[MTOT * C2];
__device__ uint32_t d_gTh  [B_ * C2 * 512];      // pooled g hi, transposed [b][c][down/2]
__device__ uint32_t d_agh  [MTOT * 128];
__device__ uint32_t d_agl  [MTOT * 128];

// ---------------------------------------------------------------------------
// helpers
// ---------------------------------------------------------------------------
__device__ __forceinline__ uint32_t pack2(float a, float b) {
    __nv_bfloat162 h = __floats2bfloat162_rn(a, b);
    return *(uint32_t*)&h;
}
__device__ __forceinline__ void split2(float a, float b, uint32_t& hi, uint32_t& lo) {
    float ha = __bfloat162float(__float2bfloat16_rn(a));
    float hb = __bfloat162float(__float2bfloat16_rn(b));
    hi = pack2(ha, hb);
    lo = pack2(a - ha, b - hb);
}
__device__ __forceinline__ void mma_bf16(float4& d,
    uint32_t a0, uint32_t a1, uint32_t a2, uint32_t a3, uint32_t b0, uint32_t b1)
{
    asm volatile("mma.sync.aligned.m16n8k16.row.col.f32.bf16.bf16.f32 "
        "{%0,%1,%2,%3}, {%4,%5,%6,%7}, {%8,%9}, {%0,%1,%2,%3};"
        : "+f"(d.x), "+f"(d.y), "+f"(d.z), "+f"(d.w)
        : "r"(a0), "r"(a1), "r"(a2), "r"(a3), "r"(b0), "r"(b1));
}
__device__ __forceinline__ void mma_x3(float4& d,
    const uint32_t ah[4], const uint32_t al[4],
    uint32_t bh0, uint32_t bh1, uint32_t bl0, uint32_t bl1)
{
    mma_bf16(d, ah[0], ah[1], ah[2], ah[3], bh0, bh1);
    mma_bf16(d, ah[0], ah[1], ah[2], ah[3], bl0, bl1);
    mma_bf16(d, al[0], al[1], al[2], al[3], bh0, bh1);
}
__device__ __forceinline__ void ldsm4(uint32_t r[4], uint32_t addr) {
    asm volatile("ldmatrix.sync.aligned.m8n8.x4.shared.b16 {%0,%1,%2,%3}, [%4];"
        : "=r"(r[0]), "=r"(r[1]), "=r"(r[2]), "=r"(r[3]) : "r"(addr));
}
__device__ __forceinline__ void cp16(uint32_t dst_saddr, const uint32_t* src) {
    asm volatile("cp.async.cg.shared.global [%0], [%1], 16;\n" :: "r"(dst_saddr), "l"(src));
}
__device__ __forceinline__ void cp_commit() {
    asm volatile("cp.async.commit_group;\n" ::: "memory");
}
__device__ __forceinline__ void cp_wait0() {
    asm volatile("cp.async.wait_group 0;\n" ::: "memory");
}

// ---------------------------------------------------------------------------
// prep kernels
// ---------------------------------------------------------------------------
__global__ void prep_x(const float* __restrict__ x,
                       uint32_t* __restrict__ xh, uint32_t* __restrict__ xl)
{
    size_t idx = (size_t)blockIdx.x * 256 + threadIdx.x;
    const float4* p = (const float4*)(x + idx * 8);
    float4 v0 = p[0], v1 = p[1];
    uint32_t h0,l0,h1,l1,h2,l2,h3,l3;
    split2(v0.x, v0.y, h0, l0); split2(v0.z, v0.w, h1, l1);
    split2(v1.x, v1.y, h2, l2); split2(v1.z, v1.w, h3, l3);
    *(uint4*)&xh[idx * 4] = make_uint4(h0, h1, h2, h3);
    *(uint4*)&xl[idx * 4] = make_uint4(l0, l1, l2, l3);
}

__global__ void prep_w(const float* __restrict__ kt, const float* __restrict__ kp,
                       const float* __restrict__ kg, const float* __restrict__ ka,
                       uint32_t* __restrict__ tpTh, uint32_t* __restrict__ tpTl,
                       uint32_t* __restrict__ gTh,  uint32_t* __restrict__ gTl,
                       uint32_t* __restrict__ aTh,  uint32_t* __restrict__ aTl)
{
    int i = blockIdx.x * 256 + threadIdx.x;
    if (i < 32768) {
        int n = i >> 8, j = i & 255;
        float a, b;
        if (n < 64) { a = kt[(2*j)*64 + n];      b = kt[(2*j+1)*64 + n]; }
        else        { a = kp[(2*j)*64 + n - 64]; b = kp[(2*j+1)*64 + n - 64]; }
        uint32_t h, l; split2(a, b, h, l);
        tpTh[i] = h; tpTl[i] = l;
    } else if (i < 98304) {
        int i2 = i - 32768; int n = i2 >> 8, j = i2 & 255;
        float a = kg[(2*j)*256 + n], b = kg[(2*j+1)*256 + n];
        uint32_t h, l; split2(a, b, h, l);
        gTh[i2] = h; gTl[i2] = l;
    } else if (i < 163840) {
        int i2 = i - 98304; int n = i2 >> 7, j = i2 & 127;
        float a = ka[(2*j)*512 + n], b = ka[(2*j+1)*512 + n];
        uint32_t h, l; split2(a, b, h, l);
        aTh[i2] = h; aTl[i2] = l;
    }
}

// ---------------------------------------------------------------------------
// Spectral norms: 4 blocks -> 1/sigma
// ---------------------------------------------------------------------------
__global__ void spectral4_kernel(const float* __restrict__ kt, const float* __restrict__ ut,
                                 const float* __restrict__ kp, const float* __restrict__ up,
                                 const float* __restrict__ kg, const float* __restrict__ ug,
                                 const float* __restrict__ ka, const float* __restrict__ ua)
{
    const float* W; const float* u; int Cin, Cout;
    switch (blockIdx.x) {
        case 0:  W = kt; u = ut; Cin = 512; Cout = 64;  break;
        case 1:  W = kp; u = up; Cin = 512; Cout = 64;  break;
        case 2:  W = kg; u = ug; Cin = 512; Cout = 256; break;
        default: W = ka; u = ua; Cin = 256; Cout = 512; break;
    }
    __shared__ float us[512];
    __shared__ float v[512];
    __shared__ float red[256];
    const int t = threadIdx.x;

    for (int j = t; j < Cout; j += 256) us[j] = u[j];
    __syncthreads();
    for (int i = t; i < Cin; i += 256) {
        const float4* wr = (const float4*)(W + (size_t)i * Cout);
        float s = 0.f;
        for (int j = 0; j < Cout / 4; j++) {
            float4 w4 = wr[j];
            s += us[4*j]*w4.x + us[4*j+1]*w4.y + us[4*j+2]*w4.z + us[4*j+3]*w4.w;
        }
        v[i] = s;
    }
    __syncthreads();
    float ss = 0.f;
    for (int i = t; i < Cin; i += 256) ss += v[i] * v[i];
    red[t] = ss; __syncthreads();
    for (int o = 128; o; o >>= 1) { if (t < o) red[t] += red[t + o]; __syncthreads(); }
    float inv_vn = 1.0f / (sqrtf(red[0]) + 1e-12f);
    __syncthreads();
    float rr = 0.f;
    for (int j = t; j < Cout; j += 256) {
        float s = 0.f;
        for (int i = 0; i < Cin; i++) s += v[i] * W[(size_t)i * Cout + j];
        s *= inv_vn;
        rr += s * s;
    }
    red[t] = rr; __syncthreads();
    for (int o = 128; o; o >>= 1) { if (t < o) red[t] += red[t + o]; __syncthreads(); }
    if (t == 0) {
        float rn = red[0];
        d_invs[blockIdx.x] = (sqrtf(rn) + 1e-12f) / rn;
    }
}

// ---------------------------------------------------------------------------
// bf16x3 GEMM v3: ldmatrix fragments + single-sync 2-stage cp.async
// Block 128x128, k-tile 32 (16 pairs), 8 warps (4m x 2n), warp 32x64.
// Stage layout: [Ah PLANE][Al PLANE][Bh PLANE][Bl PLANE], stride 20.
// ---------------------------------------------------------------------------
#define PLANE 2560
#define GEMM_SMEM (8 * PLANE * 4)

template<int MODE>
__global__ __launch_bounds__(256)
void gemm2(const uint32_t* __restrict__ Ah, const uint32_t* __restrict__ Al,
           const uint32_t* __restrict__ Bh, const uint32_t* __restrict__ Bl,
           uint32_t* __restrict__ oph, uint32_t* __restrict__ opl,
           float* __restrict__ of,
           const float* __restrict__ X, const float* __restrict__ sigma_ptr,
           int N, int KP)
{
    extern __shared__ uint32_t smg[];
    const uint32_t smb = (uint32_t)__cvta_generic_to_shared(smg);

    const int bm = blockIdx.y * 128;
    const int bn = blockIdx.x * 128;
    const int t = threadIdx.x;
    const int warp = t >> 5, lane = t & 31, g = lane >> 2, tg = lane & 3;
    const int wm = (warp >> 1) * 32, wn = (warp & 1) * 64;

    // ldmatrix per-lane fragment byte offsets (within a plane)
    const int ar = (lane & 7) + ((lane >> 3) & 1) * 8;
    const int ak = (lane >> 4) * 4;
    const int br = (lane & 7) + (lane >> 4) * 8;
    const int bk = ((lane >> 3) & 1) * 4;
    uint32_t aoff[2], boff[4];
    #pragma unroll
    for (int mf = 0; mf < 2; mf++) aoff[mf] = ((wm + mf*16 + ar) * 20 + ak) * 4;
    #pragma unroll
    for (int p = 0; p < 4; p++)    boff[p]  = ((wn + p*16 + br) * 20 + bk) * 4;

    // staging
    const int rs = t >> 1;
    const int hf = (t & 1) * 8;
    const int sidx = rs * 20 + hf;
    const uint32_t* pAh = Ah + (size_t)(bm + rs) * KP + hf;
    const uint32_t* pAl = Al + (size_t)(bm + rs) * KP + hf;
    const uint32_t* pBh = Bh + (size_t)(bn + rs) * KP + hf;
    const uint32_t* pBl = Bl + (size_t)(bn + rs) * KP + hf;

    float4 acc[2][8];
    #pragma unroll
    for (int i = 0; i < 2; i++)
        #pragma unroll
        for (int j = 0; j < 8; j++) acc[i][j] = make_float4(0.f, 0.f, 0.f, 0.f);

    const int nt = KP / 16;

    #define PREF(kt_, buf_) do {                                       \
        size_t off = (size_t)(kt_) * 16;                                \
        uint32_t d0 = smb + ((buf_) * 4 * PLANE + sidx) * 4;            \
        cp16(d0,                pAh + off); cp16(d0 + 16,               pAh + off + 4); \
        cp16(d0 + PLANE*4,      pAl + off); cp16(d0 + PLANE*4 + 16,     pAl + off + 4); \
        cp16(d0 + 2*PLANE*4,    pBh + off); cp16(d0 + 2*PLANE*4 + 16,   pBh + off + 4); \
        cp16(d0 + 3*PLANE*4,    pBl + off); cp16(d0 + 3*PLANE*4 + 16,   pBl + off + 4); \
    } while (0)

    PREF(0, 0);
    cp_commit();

    for (int kt = 0; kt < nt; kt++) {
        cp_wait0();
        __syncthreads();
        if (kt + 1 < nt) { PREF(kt + 1, (kt + 1) & 1); cp_commit(); }

        const uint32_t base = smb + ((kt & 1) * 4 * PLANE) * 4;
        #pragma unroll
        for (int s = 0; s < 2; s++) {
            uint32_t ah0[4], ah1[4], al0[4], al1[4];
            ldsm4(ah0, base + aoff[0] + s*32);
            ldsm4(ah1, base + aoff[1] + s*32);
            ldsm4(al0, base + PLANE*4 + aoff[0] + s*32);
            ldsm4(al1, base + PLANE*4 + aoff[1] + s*32);
            #pragma unroll
            for (int p = 0; p < 4; p++) {
                uint32_t bh[4], bl[4];
                ldsm4(bh, base + 2*PLANE*4 + boff[p] + s*32);
                ldsm4(bl, base + 3*PLANE*4 + boff[p] + s*32);
                mma_x3(acc[0][2*p],   ah0, al0, bh[0], bh[1], bl[0], bl[1]);
                mma_x3(acc[0][2*p+1], ah0, al0, bh[2], bh[3], bl[2], bl[3]);
                mma_x3(acc[1][2*p],   ah1, al1, bh[0], bh[1], bl[0], bl[1]);
                mma_x3(acc[1][2*p+1], ah1, al1, bh[2], bh[3], bl[2], bl[3]);
            }
        }
        __syncthreads();   // readers done before next iter's prefetch overwrites
    }
    #undef PREF

    float s0 = 0.f, s1 = 0.f;
    if (MODE == 0)      { s0 = d_invs[0]; s1 = d_invs[1]; }
    else if (MODE == 1) { s0 = d_invs[2]; }
    else                { s0 = d_invs[3] * __ldg(sigma_ptr); }

    #pragma unroll
    for (int mf = 0; mf < 2; mf++) {
        int row = bm + wm + mf * 16 + g;
        #pragma unroll
        for (int nf = 0; nf < 8; nf++) {
            int coln = wn + nf * 8 + 2 * tg;
            float4 c = acc[mf][nf];
            if (MODE == 0) {
                if (coln < 64) {
                    int colp = nf * 4 + tg;
                    uint32_t h0, l0, h1, l1;
                    split2(c.x * s0, c.y * s0, h0, l0);
                    split2(c.z * s0, c.w * s0, h1, l1);
                    oph[(size_t)row * 32 + colp]       = h0;
                    opl[(size_t)row * 32 + colp]       = l0;
                    oph[(size_t)(row + 8) * 32 + colp] = h1;
                    opl[(size_t)(row + 8) * 32 + colp] = l1;
                } else {
                    int col = coln - 64;
                    *(float2*)&of[(size_t)row * 64 + col]       = make_float2(c.x * s1, c.y * s1);
                    *(float2*)&of[(size_t)(row + 8) * 64 + col] = make_float2(c.z * s1, c.w * s1);
                }
            } else if (MODE == 1) {
                int col = bn + coln;
                *(float2*)&of[(size_t)row * N + col]       = make_float2(c.x * s0, c.y * s0);
                *(float2*)&of[(size_t)(row + 8) * N + col] = make_float2(c.z * s0, c.w * s0);
            } else {
                int col = bn + coln;
                size_t i0 = (size_t)row * N + col;
                size_t i1 = (size_t)(row + 8) * N + col;
                float2 x0 = *(const float2*)&X[i0];
                float2 x1 = *(const float2*)&X[i1];
                *(float2*)&of[i0] = make_float2(x0.x + s0 * c.x, x0.y + s0 * c.y);
                *(float2*)&of[i1] = make_float2(x1.x + s0 * c.z, x1.y + s0 * c.w);
            }
        }
    }
}

// ---------------------------------------------------------------------------
// pool kernels
// ---------------------------------------------------------------------------
__global__ void pool_phi(const float* __restrict__ pf,
                         uint32_t* __restrict__ oh, uint32_t* __restrict__ ol)
{
    int idx = blockIdx.x * 256 + threadIdx.x;
    int cp = idx & 31;
    int m  = (idx >> 5) & 1023;
    int b  = idx >> 15;
    int h2 = m >> 5, w2 = m & 31;
    size_t r = (size_t)b * 4096 + h2 * 128 + w2 * 2;
    const float* p = pf + r * 64 + cp * 2;
    float2 v00 = *(const float2*)(p);
    float2 v01 = *(const float2*)(p + 64);
    float2 v10 = *(const float2*)(p + 64 * 64);
    float2 v11 = *(const float2*)(p + 65 * 64);
    float m0 = fmaxf(fmaxf(v00.x, v01.x), fmaxf(v10.x, v11.x));
    float m1 = fmaxf(fmaxf(v00.y, v01.y), fmaxf(v10.y, v11.y));
    uint32_t h, l; split2(m0, m1, h, l);
    oh[idx] = h; ol[idx] = l;
}

// pooled g -> transposed bf16 hi plane only (PV is x1)
__global__ void pool_g(const float* __restrict__ gf, uint32_t* __restrict__ oh)
{
    int idx = blockIdx.x * 256 + threadIdx.x;   // 2097152
    int c  = idx & 255;
    int mp = (idx >> 8) & 511;
    int b  = idx >> 17;
    int m0 = mp * 2;
    int h2 = m0 >> 5, w2 = m0 & 31;
    size_t base = ((size_t)b * 4096 + h2 * 128 + w2 * 2) * 256 + c;
    float a00 = gf[base],           a01 = gf[base + 256];
    float a02 = gf[base + 512],     a03 = gf[base + 768];
    float a10 = gf[base + 64*256],  a11 = gf[base + 65*256];
    float a12 = gf[base + 66*256],  a13 = gf[base + 67*256];
    float q0 = fmaxf(fmaxf(a00, a01), fmaxf(a10, a11));
    float q1 = fmaxf(fmaxf(a02, a03), fmaxf(a12, a13));
    oh[((size_t)b * 256 + c) * 512 + mp] = pack2(q0, q1);
}

// ---------------------------------------------------------------------------
// Fused attention v3: ldmatrix + cp.async staging; scores x3, PV x1
// ---------------------------------------------------------------------------
#define SSTR 1028
#define STBASE (2304 + 32 * SSTR)       // u32 offset of stage buffers
#define STBUF  9216                     // u32 per buffer
#define ATTN_SMEM ((STBASE + 2 * STBUF) * 4)

__global__ __launch_bounds__(256)
void attn2(const uint32_t* __restrict__ th_h, const uint32_t* __restrict__ th_l,
           const uint32_t* __restrict__ ph_h, const uint32_t* __restrict__ ph_l,
           const uint32_t* __restrict__ gT_h,
           uint32_t* __restrict__ ag_h, uint32_t* __restrict__ ag_l)
{
    extern __shared__ uint32_t sma[];
    const uint32_t smb = (uint32_t)__cvta_generic_to_shared(sma);
    uint32_t* qh = sma;                       // [32][36]
    uint32_t* ql = sma + 1152;
    float* scores = (float*)(sma + 2304);     // [32][1028]

    const int b  = blockIdx.y;
    const int n0 = blockIdx.x * 32;
    const int t  = threadIdx.x;
    const int warp = t >> 5, lane = t & 31;
    const int g_ = lane >> 2, tg = lane & 3;
    const int wm = (warp >> 2) * 16;    // 0 or 16
    const int wq = warp & 3;

    // ldmatrix lane offsets
    const int ar = (lane & 7) + ((lane >> 3) & 1) * 8;
    const int ak = (lane >> 4) * 4;
    const int br = (lane & 7) + (lane >> 4) * 8;
    const int bk = ((lane >> 3) & 1) * 4;
    const uint32_t qoff = ((wm + ar) * 36 + ak) * 4;

    // stage q (regular stores; first loop sync covers visibility)
    {
        int row = t >> 3, off = (t & 7) * 4;
        size_t src = ((size_t)b * LOC + n0 + row) * 32 + off;
        *(uint4*)&qh[row * 36 + off] = *(const uint4*)&th_h[src];
        *(uint4*)&ql[row * 36 + off] = *(const uint4*)&th_l[src];
    }

    // ---- scores (x3): chunks of 128 phi rows, cp.async double buffer ----
    const int srow = t >> 1, shalf = (t & 1) * 16;
    #define PREFS(mb_, buf_) do {                                              \
        size_t src = ((size_t)b * DOWN + (mb_) + srow) * 32 + shalf;           \
        uint32_t d = smb + (STBASE + (buf_) * STBUF + srow * 36 + shalf) * 4;  \
        cp16(d,      ph_h + src);      cp16(d + 16, ph_h + src + 4);           \
        cp16(d + 32, ph_h + src + 8);  cp16(d + 48, ph_h + src + 12);          \
        uint32_t dl = d + 4608 * 4;                                            \
        cp16(dl,      ph_l + src);     cp16(dl + 16, ph_l + src + 4);          \
        cp16(dl + 32, ph_l + src + 8); cp16(dl + 48, ph_l + src + 12);         \
    } while (0)

    PREFS(0, 0);
    cp_commit();

    for (int c = 0; c < 8; c++) {
        cp_wait0();
        __syncthreads();
        if (c + 1 < 8) { PREFS((c + 1) * 128, (c + 1) & 1); cp_commit(); }

        const uint32_t bb = smb + (STBASE + (c & 1) * STBUF) * 4;
        float4 sc[4];
        #pragma unroll
        for (int nf = 0; nf < 4; nf++) sc[nf] = make_float4(0.f, 0.f, 0.f, 0.f);

        #pragma unroll
        for (int s = 0; s < 4; s++) {
            uint32_t ah[4], al[4];
            ldsm4(ah, smb + qoff + s*32);
            ldsm4(al, smb + 1152*4 + qoff + s*32);
            #pragma unroll
            for (int p = 0; p < 2; p++) {
                uint32_t boffb = ((wq*32 + p*16 + br) * 36 + bk) * 4;
                uint32_t bh[4], bl[4];
                ldsm4(bh, bb + boffb + s*32);
                ldsm4(bl, bb + 4608*4 + boffb + s*32);
                mma_x3(sc[2*p],   ah, al, bh[0], bh[1], bl[0], bl[1]);
                mma_x3(sc[2*p+1], ah, al, bh[2], bh[3], bl[2], bl[3]);
            }
        }
        int mb = c * 128;
        #pragma unroll
        for (int nf = 0; nf < 4; nf++) {
            int n = mb + wq * 32 + nf * 8 + 2 * tg;
            *(float2*)&scores[(wm + g_) * SSTR + n]     = make_float2(sc[nf].x, sc[nf].y);
            *(float2*)&scores[(wm + 8 + g_) * SSTR + n] = make_float2(sc[nf].z, sc[nf].w);
        }
        __syncthreads();
    }
    #undef PREFS

    // prefetch first PV g-chunk; it flies during softmax
    const int grow = t;
    #define PREFG(kb_, buf_) do {                                              \
        size_t src = ((size_t)b * 256 + grow) * 512 + ((kb_) >> 1);            \
        uint32_t d = smb + (STBASE + (buf_) * STBUF + grow * 36) * 4;          \
        cp16(d,      gT_h + src);      cp16(d + 16, gT_h + src + 4);           \
        cp16(d + 32, gT_h + src + 8);  cp16(d + 48, gT_h + src + 12);          \
        cp16(d + 64, gT_h + src + 16); cp16(d + 80, gT_h + src + 20);          \
        cp16(d + 96, gT_h + src + 24); cp16(d + 112, gT_h + src + 28);         \
    } while (0)
    PREFG(0, 0);
    cp_commit();

    // ---- softmax: 8 threads per row ----
    {
        const int r  = t >> 3;
        const int l8 = t & 7;
        float* srow2 = scores + r * SSTR;
        float mx = -1e30f;
        for (int j = l8; j < DOWN; j += 8) mx = fmaxf(mx, srow2[j]);
        #pragma unroll
        for (int o = 4; o; o >>= 1) mx = fmaxf(mx, __shfl_xor_sync(0xffffffffu, mx, o));
        float sum = 0.f;
        for (int j = l8; j < DOWN; j += 8) {
            float e = __expf(srow2[j] - mx);
            srow2[j] = e;
            sum += e;
        }
        #pragma unroll
        for (int o = 4; o; o >>= 1) sum += __shfl_xor_sync(0xffffffffu, sum, o);
        float inv = 1.0f / sum;
        for (int j = l8; j < DOWN; j += 8) srow2[j] *= inv;
    }

    // ---- PV (x1): out[32][256] = P @ g ----
    const int wn2 = (warp & 3) * 64;
    float4 oc[8];
    #pragma unroll
    for (int nf = 0; nf < 8; nf++) oc[nf] = make_float4(0.f, 0.f, 0.f, 0.f);

    for (int ki = 0; ki < 16; ki++) {
        cp_wait0();
        __syncthreads();
        if (ki + 1 < 16) { PREFG((ki + 1) * 64, (ki + 1) & 1); cp_commit(); }

        const uint32_t bb = smb + (STBASE + (ki & 1) * STBUF) * 4;
        int kb = ki * 64;
        #pragma unroll
        for (int s = 0; s < 4; s++) {
            int kk = kb + s * 16;
            float2 p00 = *(const float2*)&scores[(wm + g_) * SSTR + kk + 2*tg];
            float2 p08 = *(const float2*)&scores[(wm + 8 + g_) * SSTR + kk + 2*tg];
            float2 p80 = *(const float2*)&scores[(wm + g_) * SSTR + kk + 2*tg + 8];
            float2 p88 = *(const float2*)&scores[(wm + 8 + g_) * SSTR + kk + 2*tg + 8];
            uint32_t a0 = pack2(p00.x, p00.y);
            uint32_t a1 = pack2(p08.x, p08.y);
            uint32_t a2 = pack2(p80.x, p80.y);
            uint32_t a3 = pack2(p88.x, p88.y);
            #pragma unroll
            for (int p = 0; p < 4; p++) {
                uint32_t boffb = ((wn2 + p*16 + br) * 36 + bk) * 4;
                uint32_t bh[4];
                ldsm4(bh, bb + boffb + s*32);
                mma_bf16(oc[2*p],   a0, a1, a2, a3, bh[0], bh[1]);
                mma_bf16(oc[2*p+1], a0, a1, a2, a3, bh[2], bh[3]);
            }
        }
        __syncthreads();
    }
    #undef PREFG

    #pragma unroll
    for (int nf = 0; nf < 8; nf++) {
        int colp = (wn2 + nf * 8) / 2 + tg;
        size_t r0 = ((size_t)b * LOC + n0 + wm + g_) * 128 + colp;
        size_t r1 = ((size_t)b * LOC + n0 + wm + 8 + g_) * 128 + colp;
        uint32_t h0, l0, h1, l1;
        split2(oc[nf].x, oc[nf].y, h0, l0);
        split2(oc[nf].z, oc[nf].w, h1, l1);
        ag_h[r0] = h0; ag_l[r0] = l0;
        ag_h[r1] = h1; ag_l[r1] = l1;
    }
}

// ---------------------------------------------------------------------------
// kernel_launch
// ---------------------------------------------------------------------------
extern "C" void kernel_launch(void* const* d_in, const int* in_sizes, int n_in,
                              void* d_out, int out_size)
{
    const float* x       = (const float*)d_in[0];
    const float* k_theta = (const float*)d_in[1];
    const float* u_theta = (const float*)d_in[2];
    const float* k_phi   = (const float*)d_in[3];
    const float* u_phi   = (const float*)d_in[4];
    const float* k_g     = (const float*)d_in[5];
    const float* u_g     = (const float*)d_in[6];
    const float* k_attn  = (const float*)d_in[7];
    const float* u_attn  = (const float*)d_in[8];
    const float* sigma   = (const float*)d_in[9];
    float* out = (float*)d_out;

    uint32_t *xh, *xl, *wtpTh, *wtpTl, *wgTh, *wgTl, *waTh, *waTl;
    uint32_t *thh, *thl, *phh, *phl, *gTh, *agh, *agl;
    float *phifull, *gfull;
    cudaGetSymbolAddress((void**)&xh,    d_xh);
    cudaGetSymbolAddress((void**)&xl,    d_xl);
    cudaGetSymbolAddress((void**)&wtpTh, d_wtpTh);
    cudaGetSymbolAddress((void**)&wtpTl, d_wtpTl);
    cudaGetSymbolAddress((void**)&wgTh,  d_wgTh);
    cudaGetSymbolAddress((void**)&wgTl,  d_wgTl);
    cudaGetSymbolAddress((void**)&waTh,  d_waTh);
    cudaGetSymbolAddress((void**)&waTl,  d_waTl);
    cudaGetSymbolAddress((void**)&thh,   d_thh);
    cudaGetSymbolAddress((void**)&thl,   d_thl);
    cudaGetSymbolAddress((void**)&phh,   d_phh);
    cudaGetSymbolAddress((void**)&phl,   d_phl);
    cudaGetSymbolAddress((void**)&gTh,   d_gTh);
    cudaGetSymbolAddress((void**)&agh,   d_agh);
    cudaGetSymbolAddress((void**)&agl,   d_agl);
    cudaGetSymbolAddress((void**)&phifull, d_phifull);
    cudaGetSymbolAddress((void**)&gfull,   d_gfull);

    cudaFuncSetAttribute(gemm2<0>, cudaFuncAttributeMaxDynamicSharedMemorySize, GEMM_SMEM);
    cudaFuncSetAttribute(gemm2<1>, cudaFuncAttributeMaxDynamicSharedMemorySize, GEMM_SMEM);
    cudaFuncSetAttribute(gemm2<2>, cudaFuncAttributeMaxDynamicSharedMemorySize, GEMM_SMEM);
    cudaFuncSetAttribute(attn2,    cudaFuncAttributeMaxDynamicSharedMemorySize, ATTN_SMEM);

    prep_w<<<640, 256>>>(k_theta, k_phi, k_g, k_attn,
                         wtpTh, wtpTl, wgTh, wgTl, waTh, waTl);
    prep_x<<<16384, 256>>>(x, xh, xl);
    spectral4_kernel<<<4, 256>>>(k_theta, u_theta, k_phi, u_phi,
                                 k_g, u_g, k_attn, u_attn);
    gemm2<0><<<dim3(1, MTOT / 128), 256, GEMM_SMEM>>>(
        xh, xl, wtpTh, wtpTl, thh, thl, phifull, nullptr, nullptr, 128, 256);
    pool_phi<<<2048, 256>>>(phifull, phh, phl);
    gemm2<1><<<dim3(2, MTOT / 128), 256, GEMM_SMEM>>>(
        xh, xl, wgTh, wgTl, nullptr, nullptr, gfull, nullptr, nullptr, 256, 256);
    pool_g<<<8192, 256>>>(gfull, gTh);
    attn2<<<dim3(LOC / 32, B_), 256, ATTN_SMEM>>>(thh, thl, phh, phl, gTh, agh, agl);
    gemm2<2><<<dim3(4, MTOT / 128), 256, GEMM_SMEM>>>(
        agh, agl, waTh, waTl, nullptr, nullptr, out, x, sigma, 512, 128);
}

// round 7
// speedup vs baseline: 3.9941x; 1.2162x over previous
#include <cuda_runtime.h>
#include <cuda_bf16.h>
#include <cuda_fp16.h>
#include <math.h>
#include <stdint.h>

#define B_   16
#define CC   512
#define C8   64
#define C2   256
#define LOC  4096
#define DOWN 1024
#define MTOT 65536

// ---------------------------------------------------------------------------
// Device scratch
// bf16 hi/lo planes feed the x3 path (theta/phi conv + scores);
// fp16 planes feed the x1 path (g conv, PV, output conv).
// ---------------------------------------------------------------------------
__device__ float d_invs[4];
__device__ uint32_t d_xh   [MTOT * 256];         // x bf16 hi plane
__device__ uint32_t d_xl   [MTOT * 256];         // x bf16 lo plane
__device__ uint32_t d_xfh  [MTOT * 256];         // x fp16 plane
__device__ uint32_t d_wtpTh[128 * 256];          // theta|phi weights bf16 hi (transposed)
__device__ uint32_t d_wtpTl[128 * 256];
__device__ uint32_t d_wgTf [256 * 256];          // g weights fp16 (transposed)
__device__ uint32_t d_waTf [512 * 128];          // attn weights fp16 (transposed)
__device__ uint32_t d_thh  [MTOT * 32];          // theta bf16 hi
__device__ uint32_t d_thl  [MTOT * 32];
__device__ float    d_phifull[MTOT * C8];
__device__ uint32_t d_phh  [B_ * DOWN * 32];     // pooled phi bf16 hi
__device__ uint32_t d_phl  [B_ * DOWN * 32];
__device__ float    d_gfull[MTOT * C2];
__device__ uint32_t d_gTf  [B_ * C2 * 512];      // pooled g fp16, transposed [b][c][down/2]
__device__ uint32_t d_agf  [MTOT * 128];         // attn_g fp16 plane

// ---------------------------------------------------------------------------
// helpers
// ---------------------------------------------------------------------------
__device__ __forceinline__ uint32_t pack2(float a, float b) {
    __nv_bfloat162 h = __floats2bfloat162_rn(a, b);
    return *(uint32_t*)&h;
}
__device__ __forceinline__ uint32_t pack2h(float a, float b) {
    __half2 h = __floats2half2_rn(a, b);
    return *(uint32_t*)&h;
}
__device__ __forceinline__ void split2(float a, float b, uint32_t& hi, uint32_t& lo) {
    float ha = __bfloat162float(__float2bfloat16_rn(a));
    float hb = __bfloat162float(__float2bfloat16_rn(b));
    hi = pack2(ha, hb);
    lo = pack2(a - ha, b - hb);
}
__device__ __forceinline__ void mma_bf16(float4& d,
    uint32_t a0, uint32_t a1, uint32_t a2, uint32_t a3, uint32_t b0, uint32_t b1)
{
    asm volatile("mma.sync.aligned.m16n8k16.row.col.f32.bf16.bf16.f32 "
        "{%0,%1,%2,%3}, {%4,%5,%6,%7}, {%8,%9}, {%0,%1,%2,%3};"
        : "+f"(d.x), "+f"(d.y), "+f"(d.z), "+f"(d.w)
        : "r"(a0), "r"(a1), "r"(a2), "r"(a3), "r"(b0), "r"(b1));
}
__device__ __forceinline__ void mma_f16(float4& d,
    uint32_t a0, uint32_t a1, uint32_t a2, uint32_t a3, uint32_t b0, uint32_t b1)
{
    asm volatile("mma.sync.aligned.m16n8k16.row.col.f32.f16.f16.f32 "
        "{%0,%1,%2,%3}, {%4,%5,%6,%7}, {%8,%9}, {%0,%1,%2,%3};"
        : "+f"(d.x), "+f"(d.y), "+f"(d.z), "+f"(d.w)
        : "r"(a0), "r"(a1), "r"(a2), "r"(a3), "r"(b0), "r"(b1));
}
__device__ __forceinline__ void mma_x3(float4& d,
    const uint32_t ah[4], const uint32_t al[4],
    uint32_t bh0, uint32_t bh1, uint32_t bl0, uint32_t bl1)
{
    mma_bf16(d, ah[0], ah[1], ah[2], ah[3], bh0, bh1);
    mma_bf16(d, ah[0], ah[1], ah[2], ah[3], bl0, bl1);
    mma_bf16(d, al[0], al[1], al[2], al[3], bh0, bh1);
}
__device__ __forceinline__ void ldsm4(uint32_t r[4], uint32_t addr) {
    asm volatile("ldmatrix.sync.aligned.m8n8.x4.shared.b16 {%0,%1,%2,%3}, [%4];"
        : "=r"(r[0]), "=r"(r[1]), "=r"(r[2]), "=r"(r[3]) : "r"(addr));
}
__device__ __forceinline__ void cp16(uint32_t dst_saddr, const uint32_t* src) {
    asm volatile("cp.async.cg.shared.global [%0], [%1], 16;\n" :: "r"(dst_saddr), "l"(src));
}
__device__ __forceinline__ void cp_commit() {
    asm volatile("cp.async.commit_group;\n" ::: "memory");
}
__device__ __forceinline__ void cp_wait0() {
    asm volatile("cp.async.wait_group 0;\n" ::: "memory");
}

// ---------------------------------------------------------------------------
// prep kernels
// ---------------------------------------------------------------------------
__global__ void prep_x(const float* __restrict__ x,
                       uint32_t* __restrict__ xh, uint32_t* __restrict__ xl,
                       uint32_t* __restrict__ xf)
{
    size_t idx = (size_t)blockIdx.x * 256 + threadIdx.x;
    const float4* p = (const float4*)(x + idx * 8);
    float4 v0 = p[0], v1 = p[1];
    uint32_t h0,l0,h1,l1,h2,l2,h3,l3;
    split2(v0.x, v0.y, h0, l0); split2(v0.z, v0.w, h1, l1);
    split2(v1.x, v1.y, h2, l2); split2(v1.z, v1.w, h3, l3);
    *(uint4*)&xh[idx * 4] = make_uint4(h0, h1, h2, h3);
    *(uint4*)&xl[idx * 4] = make_uint4(l0, l1, l2, l3);
    *(uint4*)&xf[idx * 4] = make_uint4(pack2h(v0.x, v0.y), pack2h(v0.z, v0.w),
                                       pack2h(v1.x, v1.y), pack2h(v1.z, v1.w));
}

__global__ void prep_w(const float* __restrict__ kt, const float* __restrict__ kp,
                       const float* __restrict__ kg, const float* __restrict__ ka,
                       uint32_t* __restrict__ tpTh, uint32_t* __restrict__ tpTl,
                       uint32_t* __restrict__ gTf,  uint32_t* __restrict__ aTf)
{
    int i = blockIdx.x * 256 + threadIdx.x;
    if (i < 32768) {
        int n = i >> 8, j = i & 255;
        float a, b;
        if (n < 64) { a = kt[(2*j)*64 + n];      b = kt[(2*j+1)*64 + n]; }
        else        { a = kp[(2*j)*64 + n - 64]; b = kp[(2*j+1)*64 + n - 64]; }
        uint32_t h, l; split2(a, b, h, l);
        tpTh[i] = h; tpTl[i] = l;
    } else if (i < 98304) {
        int i2 = i - 32768; int n = i2 >> 8, j = i2 & 255;
        gTf[i2] = pack2h(kg[(2*j)*256 + n], kg[(2*j+1)*256 + n]);
    } else if (i < 163840) {
        int i2 = i - 98304; int n = i2 >> 7, j = i2 & 127;
        aTf[i2] = pack2h(ka[(2*j)*512 + n], ka[(2*j+1)*512 + n]);
    }
}

// ---------------------------------------------------------------------------
// Spectral norms: 4 blocks -> 1/sigma
// ---------------------------------------------------------------------------
__global__ void spectral4_kernel(const float* __restrict__ kt, const float* __restrict__ ut,
                                 const float* __restrict__ kp, const float* __restrict__ up,
                                 const float* __restrict__ kg, const float* __restrict__ ug,
                                 const float* __restrict__ ka, const float* __restrict__ ua)
{
    const float* W; const float* u; int Cin, Cout;
    switch (blockIdx.x) {
        case 0:  W = kt; u = ut; Cin = 512; Cout = 64;  break;
        case 1:  W = kp; u = up; Cin = 512; Cout = 64;  break;
        case 2:  W = kg; u = ug; Cin = 512; Cout = 256; break;
        default: W = ka; u = ua; Cin = 256; Cout = 512; break;
    }
    __shared__ float us[512];
    __shared__ float v[512];
    __shared__ float red[256];
    const int t = threadIdx.x;

    for (int j = t; j < Cout; j += 256) us[j] = u[j];
    __syncthreads();
    for (int i = t; i < Cin; i += 256) {
        const float4* wr = (const float4*)(W + (size_t)i * Cout);
        float s = 0.f;
        for (int j = 0; j < Cout / 4; j++) {
            float4 w4 = wr[j];
            s += us[4*j]*w4.x + us[4*j+1]*w4.y + us[4*j+2]*w4.z + us[4*j+3]*w4.w;
        }
        v[i] = s;
    }
    __syncthreads();
    float ss = 0.f;
    for (int i = t; i < Cin; i += 256) ss += v[i] * v[i];
    red[t] = ss; __syncthreads();
    for (int o = 128; o; o >>= 1) { if (t < o) red[t] += red[t + o]; __syncthreads(); }
    float inv_vn = 1.0f / (sqrtf(red[0]) + 1e-12f);
    __syncthreads();
    float rr = 0.f;
    for (int j = t; j < Cout; j += 256) {
        float s = 0.f;
        for (int i = 0; i < Cin; i++) s += v[i] * W[(size_t)i * Cout + j];
        s *= inv_vn;
        rr += s * s;
    }
    red[t] = rr; __syncthreads();
    for (int o = 128; o; o >>= 1) { if (t < o) red[t] += red[t + o]; __syncthreads(); }
    if (t == 0) {
        float rn = red[0];
        d_invs[blockIdx.x] = (sqrtf(rn) + 1e-12f) / rn;
    }
}

// ---------------------------------------------------------------------------
// bf16x3 GEMM (theta/phi conv only): 128x128 tile, 8 warps, warp 32x64
// ---------------------------------------------------------------------------
#define PLANE 2560
#define GEMM_SMEM (8 * PLANE * 4)

__global__ __launch_bounds__(256)
void gemm_x3(const uint32_t* __restrict__ Ah, const uint32_t* __restrict__ Al,
             const uint32_t* __restrict__ Bh, const uint32_t* __restrict__ Bl,
             uint32_t* __restrict__ oph, uint32_t* __restrict__ opl,
             float* __restrict__ of, int KP)
{
    extern __shared__ uint32_t smg[];
    const uint32_t smb = (uint32_t)__cvta_generic_to_shared(smg);

    const int bm = blockIdx.y * 128;
    const int t = threadIdx.x;
    const int warp = t >> 5, lane = t & 31, g = lane >> 2, tg = lane & 3;
    const int wm = (warp >> 1) * 32, wn = (warp & 1) * 64;

    const int ar = (lane & 7) + ((lane >> 3) & 1) * 8;
    const int ak = (lane >> 4) * 4;
    const int br = (lane & 7) + (lane >> 4) * 8;
    const int bk = ((lane >> 3) & 1) * 4;
    uint32_t aoff[2], boff[4];
    #pragma unroll
    for (int mf = 0; mf < 2; mf++) aoff[mf] = ((wm + mf*16 + ar) * 20 + ak) * 4;
    #pragma unroll
    for (int p = 0; p < 4; p++)    boff[p]  = ((wn + p*16 + br) * 20 + bk) * 4;

    const int rs = t >> 1;
    const int hf = (t & 1) * 8;
    const int sidx = rs * 20 + hf;
    const uint32_t* pAh = Ah + (size_t)(bm + rs) * KP + hf;
    const uint32_t* pAl = Al + (size_t)(bm + rs) * KP + hf;
    const uint32_t* pBh = Bh + (size_t)rs * KP + hf;
    const uint32_t* pBl = Bl + (size_t)rs * KP + hf;

    float4 acc[2][8];
    #pragma unroll
    for (int i = 0; i < 2; i++)
        #pragma unroll
        for (int j = 0; j < 8; j++) acc[i][j] = make_float4(0.f, 0.f, 0.f, 0.f);

    const int nt = KP / 16;

    #define PREF(kt_, buf_) do {                                       \
        size_t off = (size_t)(kt_) * 16;                                \
        uint32_t d0 = smb + ((buf_) * 4 * PLANE + sidx) * 4;            \
        cp16(d0,              pAh + off); cp16(d0 + 16,             pAh + off + 4); \
        cp16(d0 + PLANE*4,    pAl + off); cp16(d0 + PLANE*4 + 16,   pAl + off + 4); \
        cp16(d0 + 2*PLANE*4,  pBh + off); cp16(d0 + 2*PLANE*4 + 16, pBh + off + 4); \
        cp16(d0 + 3*PLANE*4,  pBl + off); cp16(d0 + 3*PLANE*4 + 16, pBl + off + 4); \
    } while (0)

    PREF(0, 0);
    cp_commit();

    for (int kt = 0; kt < nt; kt++) {
        cp_wait0();
        __syncthreads();
        if (kt + 1 < nt) { PREF(kt + 1, (kt + 1) & 1); cp_commit(); }

        const uint32_t base = smb + ((kt & 1) * 4 * PLANE) * 4;
        #pragma unroll
        for (int s = 0; s < 2; s++) {
            uint32_t ah0[4], ah1[4], al0[4], al1[4];
            ldsm4(ah0, base + aoff[0] + s*32);
            ldsm4(ah1, base + aoff[1] + s*32);
            ldsm4(al0, base + PLANE*4 + aoff[0] + s*32);
            ldsm4(al1, base + PLANE*4 + aoff[1] + s*32);
            #pragma unroll
            for (int p = 0; p < 4; p++) {
                uint32_t bh[4], bl[4];
                ldsm4(bh, base + 2*PLANE*4 + boff[p] + s*32);
                ldsm4(bl, base + 3*PLANE*4 + boff[p] + s*32);
                mma_x3(acc[0][2*p],   ah0, al0, bh[0], bh[1], bl[0], bl[1]);
                mma_x3(acc[0][2*p+1], ah0, al0, bh[2], bh[3], bl[2], bl[3]);
                mma_x3(acc[1][2*p],   ah1, al1, bh[0], bh[1], bl[0], bl[1]);
                mma_x3(acc[1][2*p+1], ah1, al1, bh[2], bh[3], bl[2], bl[3]);
            }
        }
        __syncthreads();
    }
    #undef PREF

    const float s0 = d_invs[0], s1 = d_invs[1];

    #pragma unroll
    for (int mf = 0; mf < 2; mf++) {
        int row = bm + wm + mf * 16 + g;
        #pragma unroll
        for (int nf = 0; nf < 8; nf++) {
            int coln = wn + nf * 8 + 2 * tg;
            float4 c = acc[mf][nf];
            if (coln < 64) {
                int colp = nf * 4 + tg;
                uint32_t h0, l0, h1, l1;
                split2(c.x * s0, c.y * s0, h0, l0);
                split2(c.z * s0, c.w * s0, h1, l1);
                oph[(size_t)row * 32 + colp]       = h0;
                opl[(size_t)row * 32 + colp]       = l0;
                oph[(size_t)(row + 8) * 32 + colp] = h1;
                opl[(size_t)(row + 8) * 32 + colp] = l1;
            } else {
                int col = coln - 64;
                *(float2*)&of[(size_t)row * 64 + col]       = make_float2(c.x * s1, c.y * s1);
                *(float2*)&of[(size_t)(row + 8) * 64 + col] = make_float2(c.z * s1, c.w * s1);
            }
        }
    }
}

// ---------------------------------------------------------------------------
// fp16 x1 GEMM: 128(M)x64(N) tile, 8 warps (4m x 2n), warp 32x32
// MODE 1: of = acc*invs[2];  MODE 2: of = X + sigma*invs[3]*acc
// ---------------------------------------------------------------------------
#define G1BUF 3840                      // u32 per buffer: A 128*20 + B 64*20
#define GEMM1_SMEM (2 * G1BUF * 4)

template<int MODE>
__global__ __launch_bounds__(256)
void gemm1(const uint32_t* __restrict__ Ah, const uint32_t* __restrict__ Bh,
           float* __restrict__ of,
           const float* __restrict__ X, const float* __restrict__ sigma_ptr,
           int N, int KP)
{
    extern __shared__ uint32_t smg[];
    const uint32_t smb = (uint32_t)__cvta_generic_to_shared(smg);

    const int bm = blockIdx.y * 128;
    const int bn = blockIdx.x * 64;
    const int t = threadIdx.x;
    const int warp = t >> 5, lane = t & 31, g = lane >> 2, tg = lane & 3;
    const int wm = (warp >> 1) * 32, wn = (warp & 1) * 32;

    const int ar = (lane & 7) + ((lane >> 3) & 1) * 8;
    const int ak = (lane >> 4) * 4;
    const int br = (lane & 7) + (lane >> 4) * 8;
    const int bk = ((lane >> 3) & 1) * 4;
    uint32_t aoff[2], boff[2];
    #pragma unroll
    for (int mf = 0; mf < 2; mf++) aoff[mf] = ((wm + mf*16 + ar) * 20 + ak) * 4;
    #pragma unroll
    for (int p = 0; p < 2; p++)    boff[p]  = (2560 + (wn + p*16 + br) * 20 + bk) * 4;

    // staging: A 128 rows x 16 u32, B 64 rows x 16 u32
    const int rsA = t >> 1, hfA = (t & 1) * 8;
    const int rsB = t >> 2, hfB = (t & 3) * 4;
    const uint32_t* pA = Ah + (size_t)(bm + rsA) * KP + hfA;
    const uint32_t* pB = Bh + (size_t)(bn + rsB) * KP + hfB;
    const uint32_t sA = (rsA * 20 + hfA) * 4;
    const uint32_t sB = (2560 + rsB * 20 + hfB) * 4;

    float4 acc[2][4];
    #pragma unroll
    for (int i = 0; i < 2; i++)
        #pragma unroll
        for (int j = 0; j < 4; j++) acc[i][j] = make_float4(0.f, 0.f, 0.f, 0.f);

    const int nt = KP / 16;

    #define PREF1(kt_, buf_) do {                                   \
        size_t off = (size_t)(kt_) * 16;                             \
        uint32_t da = smb + (buf_) * G1BUF * 4 + sA;                 \
        cp16(da, pA + off); cp16(da + 16, pA + off + 4);             \
        uint32_t db = smb + (buf_) * G1BUF * 4 + sB;                 \
        cp16(db, pB + off);                                          \
    } while (0)

    PREF1(0, 0);
    cp_commit();

    for (int kt = 0; kt < nt; kt++) {
        cp_wait0();
        __syncthreads();
        if (kt + 1 < nt) { PREF1(kt + 1, (kt + 1) & 1); cp_commit(); }

        const uint32_t base = smb + ((kt & 1) * G1BUF) * 4;
        #pragma unroll
        for (int s = 0; s < 2; s++) {
            uint32_t a0[4], a1[4];
            ldsm4(a0, base + aoff[0] + s*32);
            ldsm4(a1, base + aoff[1] + s*32);
            #pragma unroll
            for (int p = 0; p < 2; p++) {
                uint32_t bf[4];
                ldsm4(bf, base + boff[p] + s*32);
                mma_f16(acc[0][2*p],   a0[0], a0[1], a0[2], a0[3], bf[0], bf[1]);
                mma_f16(acc[0][2*p+1], a0[0], a0[1], a0[2], a0[3], bf[2], bf[3]);
                mma_f16(acc[1][2*p],   a1[0], a1[1], a1[2], a1[3], bf[0], bf[1]);
                mma_f16(acc[1][2*p+1], a1[0], a1[1], a1[2], a1[3], bf[2], bf[3]);
            }
        }
        __syncthreads();
    }
    #undef PREF1

    const float s0 = (MODE == 1) ? d_invs[2] : d_invs[3] * __ldg(sigma_ptr);

    #pragma unroll
    for (int mf = 0; mf < 2; mf++) {
        int row = bm + wm + mf * 16 + g;
        #pragma unroll
        for (int nf = 0; nf < 4; nf++) {
            int col = bn + wn + nf * 8 + 2 * tg;
            float4 c = acc[mf][nf];
            size_t i0 = (size_t)row * N + col;
            size_t i1 = (size_t)(row + 8) * N + col;
            if (MODE == 1) {
                *(float2*)&of[i0] = make_float2(c.x * s0, c.y * s0);
                *(float2*)&of[i1] = make_float2(c.z * s0, c.w * s0);
            } else {
                float2 x0 = *(const float2*)&X[i0];
                float2 x1 = *(const float2*)&X[i1];
                *(float2*)&of[i0] = make_float2(x0.x + s0 * c.x, x0.y + s0 * c.y);
                *(float2*)&of[i1] = make_float2(x1.x + s0 * c.z, x1.y + s0 * c.w);
            }
        }
    }
}

// ---------------------------------------------------------------------------
// pool kernels
// ---------------------------------------------------------------------------
__global__ void pool_phi(const float* __restrict__ pf,
                         uint32_t* __restrict__ oh, uint32_t* __restrict__ ol)
{
    int idx = blockIdx.x * 256 + threadIdx.x;
    int cp = idx & 31;
    int m  = (idx >> 5) & 1023;
    int b  = idx >> 15;
    int h2 = m >> 5, w2 = m & 31;
    size_t r = (size_t)b * 4096 + h2 * 128 + w2 * 2;
    const float* p = pf + r * 64 + cp * 2;
    float2 v00 = *(const float2*)(p);
    float2 v01 = *(const float2*)(p + 64);
    float2 v10 = *(const float2*)(p + 64 * 64);
    float2 v11 = *(const float2*)(p + 65 * 64);
    float m0 = fmaxf(fmaxf(v00.x, v01.x), fmaxf(v10.x, v11.x));
    float m1 = fmaxf(fmaxf(v00.y, v01.y), fmaxf(v10.y, v11.y));
    uint32_t h, l; split2(m0, m1, h, l);
    oh[idx] = h; ol[idx] = l;
}

__global__ void pool_g(const float* __restrict__ gf, uint32_t* __restrict__ oh)
{
    int idx = blockIdx.x * 256 + threadIdx.x;   // 2097152
    int c  = idx & 255;
    int mp = (idx >> 8) & 511;
    int b  = idx >> 17;
    int m0 = mp * 2;
    int h2 = m0 >> 5, w2 = m0 & 31;
    size_t base = ((size_t)b * 4096 + h2 * 128 + w2 * 2) * 256 + c;
    float a00 = gf[base],           a01 = gf[base + 256];
    float a02 = gf[base + 512],     a03 = gf[base + 768];
    float a10 = gf[base + 64*256],  a11 = gf[base + 65*256];
    float a12 = gf[base + 66*256],  a13 = gf[base + 67*256];
    float q0 = fmaxf(fmaxf(a00, a01), fmaxf(a10, a11));
    float q1 = fmaxf(fmaxf(a02, a03), fmaxf(a12, a13));
    oh[((size_t)b * 256 + c) * 512 + mp] = pack2h(q0, q1);
}

// ---------------------------------------------------------------------------
// Fused attention: scores bf16 x3, PV fp16 x1
// ---------------------------------------------------------------------------
#define SSTR 1028
#define STBASE (2304 + 32 * SSTR)
#define STBUF  9216
#define ATTN_SMEM ((STBASE + 2 * STBUF) * 4)

__global__ __launch_bounds__(256)
void attn2(const uint32_t* __restrict__ th_h, const uint32_t* __restrict__ th_l,
           const uint32_t* __restrict__ ph_h, const uint32_t* __restrict__ ph_l,
           const uint32_t* __restrict__ gT_f,
           uint32_t* __restrict__ ag_f)
{
    extern __shared__ uint32_t sma[];
    const uint32_t smb = (uint32_t)__cvta_generic_to_shared(sma);
    uint32_t* qh = sma;                       // [32][36]
    uint32_t* ql = sma + 1152;
    float* scores = (float*)(sma + 2304);     // [32][1028]

    const int b  = blockIdx.y;
    const int n0 = blockIdx.x * 32;
    const int t  = threadIdx.x;
    const int warp = t >> 5, lane = t & 31;
    const int g_ = lane >> 2, tg = lane & 3;
    const int wm = (warp >> 2) * 16;
    const int wq = warp & 3;

    const int ar = (lane & 7) + ((lane >> 3) & 1) * 8;
    const int ak = (lane >> 4) * 4;
    const int br = (lane & 7) + (lane >> 4) * 8;
    const int bk = ((lane >> 3) & 1) * 4;
    const uint32_t qoff = ((wm + ar) * 36 + ak) * 4;

    {
        int row = t >> 3, off = (t & 7) * 4;
        size_t src = ((size_t)b * LOC + n0 + row) * 32 + off;
        *(uint4*)&qh[row * 36 + off] = *(const uint4*)&th_h[src];
        *(uint4*)&ql[row * 36 + off] = *(const uint4*)&th_l[src];
    }

    // ---- scores (x3) ----
    const int srow = t >> 1, shalf = (t & 1) * 16;
    #define PREFS(mb_, buf_) do {                                              \
        size_t src = ((size_t)b * DOWN + (mb_) + srow) * 32 + shalf;           \
        uint32_t d = smb + (STBASE + (buf_) * STBUF + srow * 36 + shalf) * 4;  \
        cp16(d,      ph_h + src);      cp16(d + 16, ph_h + src + 4);           \
        cp16(d + 32, ph_h + src + 8);  cp16(d + 48, ph_h + src + 12);          \
        uint32_t dl = d + 4608 * 4;                                            \
        cp16(dl,      ph_l + src);     cp16(dl + 16, ph_l + src + 4);          \
        cp16(dl + 32, ph_l + src + 8); cp16(dl + 48, ph_l + src + 12);         \
    } while (0)

    PREFS(0, 0);
    cp_commit();

    for (int c = 0; c < 8; c++) {
        cp_wait0();
        __syncthreads();
        if (c + 1 < 8) { PREFS((c + 1) * 128, (c + 1) & 1); cp_commit(); }

        const uint32_t bb = smb + (STBASE + (c & 1) * STBUF) * 4;
        float4 sc[4];
        #pragma unroll
        for (int nf = 0; nf < 4; nf++) sc[nf] = make_float4(0.f, 0.f, 0.f, 0.f);

        #pragma unroll
        for (int s = 0; s < 4; s++) {
            uint32_t ah[4], al[4];
            ldsm4(ah, smb + qoff + s*32);
            ldsm4(al, smb + 1152*4 + qoff + s*32);
            #pragma unroll
            for (int p = 0; p < 2; p++) {
                uint32_t boffb = ((wq*32 + p*16 + br) * 36 + bk) * 4;
                uint32_t bh[4], bl[4];
                ldsm4(bh, bb + boffb + s*32);
                ldsm4(bl, bb + 4608*4 + boffb + s*32);
                mma_x3(sc[2*p],   ah, al, bh[0], bh[1], bl[0], bl[1]);
                mma_x3(sc[2*p+1], ah, al, bh[2], bh[3], bl[2], bl[3]);
            }
        }
        int mb = c * 128;
        #pragma unroll
        for (int nf = 0; nf < 4; nf++) {
            int n = mb + wq * 32 + nf * 8 + 2 * tg;
            *(float2*)&scores[(wm + g_) * SSTR + n]     = make_float2(sc[nf].x, sc[nf].y);
            *(float2*)&scores[(wm + 8 + g_) * SSTR + n] = make_float2(sc[nf].z, sc[nf].w);
        }
        __syncthreads();
    }
    #undef PREFS

    const int grow = t;
    #define PREFG(kb_, buf_) do {                                              \
        size_t src = ((size_t)b * 256 + grow) * 512 + ((kb_) >> 1);            \
        uint32_t d = smb + (STBASE + (buf_) * STBUF + grow * 36) * 4;          \
        cp16(d,      gT_f + src);      cp16(d + 16, gT_f + src + 4);           \
        cp16(d + 32, gT_f + src + 8);  cp16(d + 48, gT_f + src + 12);          \
        cp16(d + 64, gT_f + src + 16); cp16(d + 80, gT_f + src + 20);          \
        cp16(d + 96, gT_f + src + 24); cp16(d + 112, gT_f + src + 28);         \
    } while (0)
    PREFG(0, 0);
    cp_commit();

    // ---- softmax ----
    {
        const int r  = t >> 3;
        const int l8 = t & 7;
        float* srow2 = scores + r * SSTR;
        float mx = -1e30f;
        for (int j = l8; j < DOWN; j += 8) mx = fmaxf(mx, srow2[j]);
        #pragma unroll
        for (int o = 4; o; o >>= 1) mx = fmaxf(mx, __shfl_xor_sync(0xffffffffu, mx, o));
        float sum = 0.f;
        for (int j = l8; j < DOWN; j += 8) {
            float e = __expf(srow2[j] - mx);
            srow2[j] = e;
            sum += e;
        }
        #pragma unroll
        for (int o = 4; o; o >>= 1) sum += __shfl_xor_sync(0xffffffffu, sum, o);
        float inv = 1.0f / sum;
        for (int j = l8; j < DOWN; j += 8) srow2[j] *= inv;
    }

    // ---- PV (fp16 x1) ----
    const int wn2 = (warp & 3) * 64;
    float4 oc[8];
    #pragma unroll
    for (int nf = 0; nf < 8; nf++) oc[nf] = make_float4(0.f, 0.f, 0.f, 0.f);

    for (int ki = 0; ki < 16; ki++) {
        cp_wait0();
        __syncthreads();
        if (ki + 1 < 16) { PREFG((ki + 1) * 64, (ki + 1) & 1); cp_commit(); }

        const uint32_t bb = smb + (STBASE + (ki & 1) * STBUF) * 4;
        int kb = ki * 64;
        #pragma unroll
        for (int s = 0; s < 4; s++) {
            int kk = kb + s * 16;
            float2 p00 = *(const float2*)&scores[(wm + g_) * SSTR + kk + 2*tg];
            float2 p08 = *(const float2*)&scores[(wm + 8 + g_) * SSTR + kk + 2*tg];
            float2 p80 = *(const float2*)&scores[(wm + g_) * SSTR + kk + 2*tg + 8];
            float2 p88 = *(const float2*)&scores[(wm + 8 + g_) * SSTR + kk + 2*tg + 8];
            uint32_t a0 = pack2h(p00.x, p00.y);
            uint32_t a1 = pack2h(p08.x, p08.y);
            uint32_t a2 = pack2h(p80.x, p80.y);
            uint32_t a3 = pack2h(p88.x, p88.y);
            #pragma unroll
            for (int p = 0; p < 4; p++) {
                uint32_t boffb = ((wn2 + p*16 + br) * 36 + bk) * 4;
                uint32_t bh[4];
                ldsm4(bh, bb + boffb + s*32);
                mma_f16(oc[2*p],   a0, a1, a2, a3, bh[0], bh[1]);
                mma_f16(oc[2*p+1], a0, a1, a2, a3, bh[2], bh[3]);
            }
        }
        __syncthreads();
    }
    #undef PREFG

    #pragma unroll
    for (int nf = 0; nf < 8; nf++) {
        int colp = (wn2 + nf * 8) / 2 + tg;
        size_t r0 = ((size_t)b * LOC + n0 + wm + g_) * 128 + colp;
        size_t r1 = ((size_t)b * LOC + n0 + wm + 8 + g_) * 128 + colp;
        ag_f[r0] = pack2h(oc[nf].x, oc[nf].y);
        ag_f[r1] = pack2h(oc[nf].z, oc[nf].w);
    }
}

// ---------------------------------------------------------------------------
// kernel_launch
// ---------------------------------------------------------------------------
extern "C" void kernel_launch(void* const* d_in, const int* in_sizes, int n_in,
                              void* d_out, int out_size)
{
    const float* x       = (const float*)d_in[0];
    const float* k_theta = (const float*)d_in[1];
    const float* u_theta = (const float*)d_in[2];
    const float* k_phi   = (const float*)d_in[3];
    const float* u_phi   = (const float*)d_in[4];
    const float* k_g     = (const float*)d_in[5];
    const float* u_g     = (const float*)d_in[6];
    const float* k_attn  = (const float*)d_in[7];
    const float* u_attn  = (const float*)d_in[8];
    const float* sigma   = (const float*)d_in[9];
    float* out = (float*)d_out;

    uint32_t *xh, *xl, *xfh, *wtpTh, *wtpTl, *wgTf, *waTf;
    uint32_t *thh, *thl, *phh, *phl, *gTf, *agf;
    float *phifull, *gfull;
    cudaGetSymbolAddress((void**)&xh,    d_xh);
    cudaGetSymbolAddress((void**)&xl,    d_xl);
    cudaGetSymbolAddress((void**)&xfh,   d_xfh);
    cudaGetSymbolAddress((void**)&wtpTh, d_wtpTh);
    cudaGetSymbolAddress((void**)&wtpTl, d_wtpTl);
    cudaGetSymbolAddress((void**)&wgTf,  d_wgTf);
    cudaGetSymbolAddress((void**)&waTf,  d_waTf);
    cudaGetSymbolAddress((void**)&thh,   d_thh);
    cudaGetSymbolAddress((void**)&thl,   d_thl);
    cudaGetSymbolAddress((void**)&phh,   d_phh);
    cudaGetSymbolAddress((void**)&phl,   d_phl);
    cudaGetSymbolAddress((void**)&gTf,   d_gTf);
    cudaGetSymbolAddress((void**)&agf,   d_agf);
    cudaGetSymbolAddress((void**)&phifull, d_phifull);
    cudaGetSymbolAddress((void**)&gfull,   d_gfull);

    cudaFuncSetAttribute(gemm_x3,  cudaFuncAttributeMaxDynamicSharedMemorySize, GEMM_SMEM);
    cudaFuncSetAttribute(gemm1<1>, cudaFuncAttributeMaxDynamicSharedMemorySize, GEMM1_SMEM);
    cudaFuncSetAttribute(gemm1<2>, cudaFuncAttributeMaxDynamicSharedMemorySize, GEMM1_SMEM);
    cudaFuncSetAttribute(attn2,    cudaFuncAttributeMaxDynamicSharedMemorySize, ATTN_SMEM);

    prep_w<<<640, 256>>>(k_theta, k_phi, k_g, k_attn, wtpTh, wtpTl, wgTf, waTf);
    prep_x<<<16384, 256>>>(x, xh, xl, xfh);
    spectral4_kernel<<<4, 256>>>(k_theta, u_theta, k_phi, u_phi,
                                 k_g, u_g, k_attn, u_attn);
    // theta+phi conv (bf16 x3, dual output)
    gemm_x3<<<dim3(1, MTOT / 128), 256, GEMM_SMEM>>>(
        xh, xl, wtpTh, wtpTl, thh, thl, phifull, 256);
    pool_phi<<<2048, 256>>>(phifull, phh, phl);
    // g conv (fp16 x1)
    gemm1<1><<<dim3(4, MTOT / 128), 256, GEMM1_SMEM>>>(
        xfh, wgTf, gfull, nullptr, nullptr, 256, 256);
    pool_g<<<8192, 256>>>(gfull, gTf);
    // fused attention
    attn2<<<dim3(LOC / 32, B_), 256, ATTN_SMEM>>>(thh, thl, phh, phl, gTf, agf);
    // output conv + residual (fp16 x1)
    gemm1<2><<<dim3(8, MTOT / 128), 256, GEMM1_SMEM>>>(
        agf, waTf, out, x, sigma, 512, 128);
}

// round 8
// speedup vs baseline: 5.2775x; 1.3213x over previous
#include <cuda_runtime.h>
#include <cuda_bf16.h>
#include <cuda_fp16.h>
#include <math.h>
#include <stdint.h>

#define B_   16
#define CC   512
#define C8   64
#define C2   256
#define LOC  4096
#define DOWN 1024
#define MTOT 65536

// ---------------------------------------------------------------------------
// Device scratch
// ---------------------------------------------------------------------------
__device__ float d_invs[4];
__device__ uint32_t d_xh   [MTOT * 256];         // x bf16 hi plane
__device__ uint32_t d_xl   [MTOT * 256];         // x bf16 lo plane
__device__ uint32_t d_xfh  [MTOT * 256];         // x fp16 plane
__device__ uint32_t d_wtpTh[128 * 256];
__device__ uint32_t d_wtpTl[128 * 256];
__device__ uint32_t d_wgTf [256 * 256];
__device__ uint32_t d_waTf [512 * 128];
__device__ uint32_t d_thh  [MTOT * 32];
__device__ uint32_t d_thl  [MTOT * 32];
__device__ float    d_phifull[MTOT * C8];
__device__ uint32_t d_phh  [B_ * DOWN * 32];
__device__ uint32_t d_phl  [B_ * DOWN * 32];
__device__ float    d_gfull[MTOT * C2];
__device__ uint32_t d_gTf  [B_ * C2 * 512];      // pooled g fp16, transposed
__device__ uint32_t d_agf  [MTOT * 128];         // attn_g fp16 plane

// ---------------------------------------------------------------------------
// helpers
// ---------------------------------------------------------------------------
__device__ __forceinline__ uint32_t pack2(float a, float b) {
    __nv_bfloat162 h = __floats2bfloat162_rn(a, b);
    return *(uint32_t*)&h;
}
__device__ __forceinline__ uint32_t pack2h(float a, float b) {
    __half2 h = __floats2half2_rn(a, b);
    return *(uint32_t*)&h;
}
__device__ __forceinline__ void split2(float a, float b, uint32_t& hi, uint32_t& lo) {
    float ha = __bfloat162float(__float2bfloat16_rn(a));
    float hb = __bfloat162float(__float2bfloat16_rn(b));
    hi = pack2(ha, hb);
    lo = pack2(a - ha, b - hb);
}
__device__ __forceinline__ void mma_bf16(float4& d,
    uint32_t a0, uint32_t a1, uint32_t a2, uint32_t a3, uint32_t b0, uint32_t b1)
{
    asm volatile("mma.sync.aligned.m16n8k16.row.col.f32.bf16.bf16.f32 "
        "{%0,%1,%2,%3}, {%4,%5,%6,%7}, {%8,%9}, {%0,%1,%2,%3};"
        : "+f"(d.x), "+f"(d.y), "+f"(d.z), "+f"(d.w)
        : "r"(a0), "r"(a1), "r"(a2), "r"(a3), "r"(b0), "r"(b1));
}
__device__ __forceinline__ void mma_f16(float4& d,
    uint32_t a0, uint32_t a1, uint32_t a2, uint32_t a3, uint32_t b0, uint32_t b1)
{
    asm volatile("mma.sync.aligned.m16n8k16.row.col.f32.f16.f16.f32 "
        "{%0,%1,%2,%3}, {%4,%5,%6,%7}, {%8,%9}, {%0,%1,%2,%3};"
        : "+f"(d.x), "+f"(d.y), "+f"(d.z), "+f"(d.w)
        : "r"(a0), "r"(a1), "r"(a2), "r"(a3), "r"(b0), "r"(b1));
}
__device__ __forceinline__ void mma_x3(float4& d,
    const uint32_t ah[4], const uint32_t al[4],
    uint32_t bh0, uint32_t bh1, uint32_t bl0, uint32_t bl1)
{
    mma_bf16(d, ah[0], ah[1], ah[2], ah[3], bh0, bh1);
    mma_bf16(d, ah[0], ah[1], ah[2], ah[3], bl0, bl1);
    mma_bf16(d, al[0], al[1], al[2], al[3], bh0, bh1);
}
__device__ __forceinline__ void ldsm4(uint32_t r[4], uint32_t addr) {
    asm volatile("ldmatrix.sync.aligned.m8n8.x4.shared.b16 {%0,%1,%2,%3}, [%4];"
        : "=r"(r[0]), "=r"(r[1]), "=r"(r[2]), "=r"(r[3]) : "r"(addr));
}
__device__ __forceinline__ void cp16(uint32_t dst_saddr, const uint32_t* src) {
    asm volatile("cp.async.cg.shared.global [%0], [%1], 16;\n" :: "r"(dst_saddr), "l"(src));
}
__device__ __forceinline__ void cp_commit() {
    asm volatile("cp.async.commit_group;\n" ::: "memory");
}
__device__ __forceinline__ void cp_wait0() {
    asm volatile("cp.async.wait_group 0;\n" ::: "memory");
}
__device__ __forceinline__ void cp_wait1() {
    asm volatile("cp.async.wait_group 1;\n" ::: "memory");
}

// ---------------------------------------------------------------------------
// prep kernels
// ---------------------------------------------------------------------------
__global__ void prep_x(const float* __restrict__ x,
                       uint32_t* __restrict__ xh, uint32_t* __restrict__ xl,
                       uint32_t* __restrict__ xf)
{
    size_t idx = (size_t)blockIdx.x * 256 + threadIdx.x;
    const float4* p = (const float4*)(x + idx * 8);
    float4 v0 = p[0], v1 = p[1];
    uint32_t h0,l0,h1,l1,h2,l2,h3,l3;
    split2(v0.x, v0.y, h0, l0); split2(v0.z, v0.w, h1, l1);
    split2(v1.x, v1.y, h2, l2); split2(v1.z, v1.w, h3, l3);
    *(uint4*)&xh[idx * 4] = make_uint4(h0, h1, h2, h3);
    *(uint4*)&xl[idx * 4] = make_uint4(l0, l1, l2, l3);
    *(uint4*)&xf[idx * 4] = make_uint4(pack2h(v0.x, v0.y), pack2h(v0.z, v0.w),
                                       pack2h(v1.x, v1.y), pack2h(v1.z, v1.w));
}

__global__ void prep_w(const float* __restrict__ kt, const float* __restrict__ kp,
                       const float* __restrict__ kg, const float* __restrict__ ka,
                       uint32_t* __restrict__ tpTh, uint32_t* __restrict__ tpTl,
                       uint32_t* __restrict__ gTf,  uint32_t* __restrict__ aTf)
{
    int i = blockIdx.x * 256 + threadIdx.x;
    if (i < 32768) {
        int n = i >> 8, j = i & 255;
        float a, b;
        if (n < 64) { a = kt[(2*j)*64 + n];      b = kt[(2*j+1)*64 + n]; }
        else        { a = kp[(2*j)*64 + n - 64]; b = kp[(2*j+1)*64 + n - 64]; }
        uint32_t h, l; split2(a, b, h, l);
        tpTh[i] = h; tpTl[i] = l;
    } else if (i < 98304) {
        int i2 = i - 32768; int n = i2 >> 8, j = i2 & 255;
        gTf[i2] = pack2h(kg[(2*j)*256 + n], kg[(2*j+1)*256 + n]);
    } else if (i < 163840) {
        int i2 = i - 98304; int n = i2 >> 7, j = i2 & 127;
        aTf[i2] = pack2h(ka[(2*j)*512 + n], ka[(2*j+1)*512 + n]);
    }
}

// ---------------------------------------------------------------------------
// Spectral norms: 4 blocks -> 1/sigma
// ---------------------------------------------------------------------------
__global__ void spectral4_kernel(const float* __restrict__ kt, const float* __restrict__ ut,
                                 const float* __restrict__ kp, const float* __restrict__ up,
                                 const float* __restrict__ kg, const float* __restrict__ ug,
                                 const float* __restrict__ ka, const float* __restrict__ ua)
{
    const float* W; const float* u; int Cin, Cout;
    switch (blockIdx.x) {
        case 0:  W = kt; u = ut; Cin = 512; Cout = 64;  break;
        case 1:  W = kp; u = up; Cin = 512; Cout = 64;  break;
        case 2:  W = kg; u = ug; Cin = 512; Cout = 256; break;
        default: W = ka; u = ua; Cin = 256; Cout = 512; break;
    }
    __shared__ float us[512];
    __shared__ float v[512];
    __shared__ float red[256];
    const int t = threadIdx.x;

    for (int j = t; j < Cout; j += 256) us[j] = u[j];
    __syncthreads();
    for (int i = t; i < Cin; i += 256) {
        const float4* wr = (const float4*)(W + (size_t)i * Cout);
        float s = 0.f;
        for (int j = 0; j < Cout / 4; j++) {
            float4 w4 = wr[j];
            s += us[4*j]*w4.x + us[4*j+1]*w4.y + us[4*j+2]*w4.z + us[4*j+3]*w4.w;
        }
        v[i] = s;
    }
    __syncthreads();
    float ss = 0.f;
    for (int i = t; i < Cin; i += 256) ss += v[i] * v[i];
    red[t] = ss; __syncthreads();
    for (int o = 128; o; o >>= 1) { if (t < o) red[t] += red[t + o]; __syncthreads(); }
    float inv_vn = 1.0f / (sqrtf(red[0]) + 1e-12f);
    __syncthreads();
    float rr = 0.f;
    for (int j = t; j < Cout; j += 256) {
        float s = 0.f;
        for (int i = 0; i < Cin; i++) s += v[i] * W[(size_t)i * Cout + j];
        s *= inv_vn;
        rr += s * s;
    }
    red[t] = rr; __syncthreads();
    for (int o = 128; o; o >>= 1) { if (t < o) red[t] += red[t + o]; __syncthreads(); }
    if (t == 0) {
        float rn = red[0];
        d_invs[blockIdx.x] = (sqrtf(rn) + 1e-12f) / rn;
    }
}

// ---------------------------------------------------------------------------
// bf16x3 GEMM (theta/phi conv): 3-stage cp.async, single sync per k-tile
// ---------------------------------------------------------------------------
#define PLANE 2560
#define GEMM_SMEM (12 * PLANE * 4)

__global__ __launch_bounds__(256)
void gemm_x3(const uint32_t* __restrict__ Ah, const uint32_t* __restrict__ Al,
             const uint32_t* __restrict__ Bh, const uint32_t* __restrict__ Bl,
             uint32_t* __restrict__ oph, uint32_t* __restrict__ opl,
             float* __restrict__ of, int KP)
{
    extern __shared__ uint32_t smg[];
    const uint32_t smb = (uint32_t)__cvta_generic_to_shared(smg);

    const int bm = blockIdx.y * 128;
    const int t = threadIdx.x;
    const int warp = t >> 5, lane = t & 31, g = lane >> 2, tg = lane & 3;
    const int wm = (warp >> 1) * 32, wn = (warp & 1) * 64;

    const int ar = (lane & 7) + ((lane >> 3) & 1) * 8;
    const int ak = (lane >> 4) * 4;
    const int br = (lane & 7) + (lane >> 4) * 8;
    const int bk = ((lane >> 3) & 1) * 4;
    uint32_t aoff[2], boff[4];
    #pragma unroll
    for (int mf = 0; mf < 2; mf++) aoff[mf] = ((wm + mf*16 + ar) * 20 + ak) * 4;
    #pragma unroll
    for (int p = 0; p < 4; p++)    boff[p]  = ((wn + p*16 + br) * 20 + bk) * 4;

    const int rs = t >> 1;
    const int hf = (t & 1) * 8;
    const int sidx = rs * 20 + hf;
    const uint32_t* pAh = Ah + (size_t)(bm + rs) * KP + hf;
    const uint32_t* pAl = Al + (size_t)(bm + rs) * KP + hf;
    const uint32_t* pBh = Bh + (size_t)rs * KP + hf;
    const uint32_t* pBl = Bl + (size_t)rs * KP + hf;

    float4 acc[2][8];
    #pragma unroll
    for (int i = 0; i < 2; i++)
        #pragma unroll
        for (int j = 0; j < 8; j++) acc[i][j] = make_float4(0.f, 0.f, 0.f, 0.f);

    const int nt = KP / 16;

    #define PREF(kt_, buf_) do {                                       \
        size_t off = (size_t)(kt_) * 16;                                \
        uint32_t d0 = smb + ((buf_) * 4 * PLANE + sidx) * 4;            \
        cp16(d0,              pAh + off); cp16(d0 + 16,             pAh + off + 4); \
        cp16(d0 + PLANE*4,    pAl + off); cp16(d0 + PLANE*4 + 16,   pAl + off + 4); \
        cp16(d0 + 2*PLANE*4,  pBh + off); cp16(d0 + 2*PLANE*4 + 16, pBh + off + 4); \
        cp16(d0 + 3*PLANE*4,  pBl + off); cp16(d0 + 3*PLANE*4 + 16, pBl + off + 4); \
    } while (0)

    PREF(0, 0); cp_commit();
    PREF(1, 1); cp_commit();

    for (int kt = 0; kt < nt; kt++) {
        if (kt == nt - 1) cp_wait0(); else cp_wait1();
        __syncthreads();
        if (kt + 2 < nt) { PREF(kt + 2, (kt + 2) % 3); cp_commit(); }

        const uint32_t base = smb + ((kt % 3) * 4 * PLANE) * 4;
        #pragma unroll
        for (int s = 0; s < 2; s++) {
            uint32_t ah0[4], ah1[4], al0[4], al1[4];
            ldsm4(ah0, base + aoff[0] + s*32);
            ldsm4(ah1, base + aoff[1] + s*32);
            ldsm4(al0, base + PLANE*4 + aoff[0] + s*32);
            ldsm4(al1, base + PLANE*4 + aoff[1] + s*32);
            #pragma unroll
            for (int p = 0; p < 4; p++) {
                uint32_t bh[4], bl[4];
                ldsm4(bh, base + 2*PLANE*4 + boff[p] + s*32);
                ldsm4(bl, base + 3*PLANE*4 + boff[p] + s*32);
                mma_x3(acc[0][2*p],   ah0, al0, bh[0], bh[1], bl[0], bl[1]);
                mma_x3(acc[0][2*p+1], ah0, al0, bh[2], bh[3], bl[2], bl[3]);
                mma_x3(acc[1][2*p],   ah1, al1, bh[0], bh[1], bl[0], bl[1]);
                mma_x3(acc[1][2*p+1], ah1, al1, bh[2], bh[3], bl[2], bl[3]);
            }
        }
    }
    #undef PREF

    const float s0 = d_invs[0], s1 = d_invs[1];

    #pragma unroll
    for (int mf = 0; mf < 2; mf++) {
        int row = bm + wm + mf * 16 + g;
        #pragma unroll
        for (int nf = 0; nf < 8; nf++) {
            int coln = wn + nf * 8 + 2 * tg;
            float4 c = acc[mf][nf];
            if (coln < 64) {
                int colp = nf * 4 + tg;
                uint32_t h0, l0, h1, l1;
                split2(c.x * s0, c.y * s0, h0, l0);
                split2(c.z * s0, c.w * s0, h1, l1);
                oph[(size_t)row * 32 + colp]       = h0;
                opl[(size_t)row * 32 + colp]       = l0;
                oph[(size_t)(row + 8) * 32 + colp] = h1;
                opl[(size_t)(row + 8) * 32 + colp] = l1;
            } else {
                int col = coln - 64;
                *(float2*)&of[(size_t)row * 64 + col]       = make_float2(c.x * s1, c.y * s1);
                *(float2*)&of[(size_t)(row + 8) * 64 + col] = make_float2(c.z * s1, c.w * s1);
            }
        }
    }
}

// ---------------------------------------------------------------------------
// fp16 x1 GEMM: 128x64 tile, 3-stage cp.async
// ---------------------------------------------------------------------------
#define G1BUF 3840
#define GEMM1_SMEM (3 * G1BUF * 4)

template<int MODE>
__global__ __launch_bounds__(256)
void gemm1(const uint32_t* __restrict__ Ah, const uint32_t* __restrict__ Bh,
           float* __restrict__ of,
           const float* __restrict__ X, const float* __restrict__ sigma_ptr,
           int N, int KP)
{
    extern __shared__ uint32_t smg[];
    const uint32_t smb = (uint32_t)__cvta_generic_to_shared(smg);

    const int bm = blockIdx.y * 128;
    const int bn = blockIdx.x * 64;
    const int t = threadIdx.x;
    const int warp = t >> 5, lane = t & 31, g = lane >> 2, tg = lane & 3;
    const int wm = (warp >> 1) * 32, wn = (warp & 1) * 32;

    const int ar = (lane & 7) + ((lane >> 3) & 1) * 8;
    const int ak = (lane >> 4) * 4;
    const int br = (lane & 7) + (lane >> 4) * 8;
    const int bk = ((lane >> 3) & 1) * 4;
    uint32_t aoff[2], boff[2];
    #pragma unroll
    for (int mf = 0; mf < 2; mf++) aoff[mf] = ((wm + mf*16 + ar) * 20 + ak) * 4;
    #pragma unroll
    for (int p = 0; p < 2; p++)    boff[p]  = (2560 + (wn + p*16 + br) * 20 + bk) * 4;

    const int rsA = t >> 1, hfA = (t & 1) * 8;
    const int rsB = t >> 2, hfB = (t & 3) * 4;
    const uint32_t* pA = Ah + (size_t)(bm + rsA) * KP + hfA;
    const uint32_t* pB = Bh + (size_t)(bn + rsB) * KP + hfB;
    const uint32_t sA = (rsA * 20 + hfA) * 4;
    const uint32_t sB = (2560 + rsB * 20 + hfB) * 4;

    float4 acc[2][4];
    #pragma unroll
    for (int i = 0; i < 2; i++)
        #pragma unroll
        for (int j = 0; j < 4; j++) acc[i][j] = make_float4(0.f, 0.f, 0.f, 0.f);

    const int nt = KP / 16;

    #define PREF1(kt_, buf_) do {                                   \
        size_t off = (size_t)(kt_) * 16;                             \
        uint32_t da = smb + (buf_) * G1BUF * 4 + sA;                 \
        cp16(da, pA + off); cp16(da + 16, pA + off + 4);             \
        uint32_t db = smb + (buf_) * G1BUF * 4 + sB;                 \
        cp16(db, pB + off);                                          \
    } while (0)

    PREF1(0, 0); cp_commit();
    PREF1(1, 1); cp_commit();

    for (int kt = 0; kt < nt; kt++) {
        if (kt == nt - 1) cp_wait0(); else cp_wait1();
        __syncthreads();
        if (kt + 2 < nt) { PREF1(kt + 2, (kt + 2) % 3); cp_commit(); }

        const uint32_t base = smb + ((kt % 3) * G1BUF) * 4;
        #pragma unroll
        for (int s = 0; s < 2; s++) {
            uint32_t a0[4], a1[4];
            ldsm4(a0, base + aoff[0] + s*32);
            ldsm4(a1, base + aoff[1] + s*32);
            #pragma unroll
            for (int p = 0; p < 2; p++) {
                uint32_t bf[4];
                ldsm4(bf, base + boff[p] + s*32);
                mma_f16(acc[0][2*p],   a0[0], a0[1], a0[2], a0[3], bf[0], bf[1]);
                mma_f16(acc[0][2*p+1], a0[0], a0[1], a0[2], a0[3], bf[2], bf[3]);
                mma_f16(acc[1][2*p],   a1[0], a1[1], a1[2], a1[3], bf[0], bf[1]);
                mma_f16(acc[1][2*p+1], a1[0], a1[1], a1[2], a1[3], bf[2], bf[3]);
            }
        }
    }
    #undef PREF1

    const float s0 = (MODE == 1) ? d_invs[2] : d_invs[3] * __ldg(sigma_ptr);

    #pragma unroll
    for (int mf = 0; mf < 2; mf++) {
        int row = bm + wm + mf * 16 + g;
        #pragma unroll
        for (int nf = 0; nf < 4; nf++) {
            int col = bn + wn + nf * 8 + 2 * tg;
            float4 c = acc[mf][nf];
            size_t i0 = (size_t)row * N + col;
            size_t i1 = (size_t)(row + 8) * N + col;
            if (MODE == 1) {
                *(float2*)&of[i0] = make_float2(c.x * s0, c.y * s0);
                *(float2*)&of[i1] = make_float2(c.z * s0, c.w * s0);
            } else {
                float2 x0 = *(const float2*)&X[i0];
                float2 x1 = *(const float2*)&X[i1];
                *(float2*)&of[i0] = make_float2(x0.x + s0 * c.x, x0.y + s0 * c.y);
                *(float2*)&of[i1] = make_float2(x1.x + s0 * c.z, x1.y + s0 * c.w);
            }
        }
    }
}

// ---------------------------------------------------------------------------
// pool kernels
// ---------------------------------------------------------------------------
__global__ void pool_phi(const float* __restrict__ pf,
                         uint32_t* __restrict__ oh, uint32_t* __restrict__ ol)
{
    int idx = blockIdx.x * 256 + threadIdx.x;
    int cp = idx & 31;
    int m  = (idx >> 5) & 1023;
    int b  = idx >> 15;
    int h2 = m >> 5, w2 = m & 31;
    size_t r = (size_t)b * 4096 + h2 * 128 + w2 * 2;
    const float* p = pf + r * 64 + cp * 2;
    float2 v00 = *(const float2*)(p);
    float2 v01 = *(const float2*)(p + 64);
    float2 v10 = *(const float2*)(p + 64 * 64);
    float2 v11 = *(const float2*)(p + 65 * 64);
    float m0 = fmaxf(fmaxf(v00.x, v01.x), fmaxf(v10.x, v11.x));
    float m1 = fmaxf(fmaxf(v00.y, v01.y), fmaxf(v10.y, v11.y));
    uint32_t h, l; split2(m0, m1, h, l);
    oh[idx] = h; ol[idx] = l;
}

__global__ void pool_g(const float* __restrict__ gf, uint32_t* __restrict__ oh)
{
    int idx = blockIdx.x * 256 + threadIdx.x;
    int c  = idx & 255;
    int mp = (idx >> 8) & 511;
    int b  = idx >> 17;
    int m0 = mp * 2;
    int h2 = m0 >> 5, w2 = m0 & 31;
    size_t base = ((size_t)b * 4096 + h2 * 128 + w2 * 2) * 256 + c;
    float a00 = gf[base],           a01 = gf[base + 256];
    float a02 = gf[base + 512],     a03 = gf[base + 768];
    float a10 = gf[base + 64*256],  a11 = gf[base + 65*256];
    float a12 = gf[base + 66*256],  a13 = gf[base + 67*256];
    float q0 = fmaxf(fmaxf(a00, a01), fmaxf(a10, a11));
    float q1 = fmaxf(fmaxf(a02, a03), fmaxf(a12, a13));
    oh[((size_t)b * 256 + c) * 512 + mp] = pack2h(q0, q1);
}

// ---------------------------------------------------------------------------
// attn3: 64 q-rows/block, q frags in regs, P = unnormalized exp (fp16) in smem,
// flash-lite rescale, PV fp16 x1, normalization in epilogue.
// ---------------------------------------------------------------------------
#define PSTR 516
#define MC_OFF  (64 * PSTR)             // 33024: m_c[64][8][2] floats
#define INV_OFF (MC_OFF + 1024)         // 34048: inv[64]
#define SOFF    (INV_OFF + 64)          // 34112: staging, 2 x 9216
#define STBUF2  9216
#define ATTN_SMEM ((SOFF + 2 * STBUF2) * 4)   // 210176 bytes

__global__ __launch_bounds__(256)
void attn3(const uint32_t* __restrict__ th_h, const uint32_t* __restrict__ th_l,
           const uint32_t* __restrict__ ph_h, const uint32_t* __restrict__ ph_l,
           const uint32_t* __restrict__ gT_f,
           uint32_t* __restrict__ ag_f)
{
    extern __shared__ uint32_t sma[];
    const uint32_t smb = (uint32_t)__cvta_generic_to_shared(sma);

    const int b  = blockIdx.y;
    const int n0 = blockIdx.x * 64;
    const int t  = threadIdx.x;
    const int warp = t >> 5, lane = t & 31;
    const int g_ = lane >> 2, tg = lane & 3;
    const int mw = warp >> 1;          // 0..3 (16 rows each)
    const int nw = warp & 1;           // 0..1
    const int rows0 = mw * 16;

    const int ar = (lane & 7) + ((lane >> 3) & 1) * 8;
    const int ak = (lane >> 4) * 4;
    const int br = (lane & 7) + (lane >> 4) * 8;
    const int bk = ((lane >> 3) & 1) * 4;

    // ---- stage q temporarily in staging buf 0, hoist fragments to regs ----
    {
        int row = t >> 2, off = (t & 3) * 8;
        size_t src = ((size_t)b * LOC + n0 + row) * 32 + off;
        *(uint4*)&sma[SOFF + row * 36 + off]     = *(const uint4*)&th_h[src];
        *(uint4*)&sma[SOFF + row * 36 + off + 4] = *(const uint4*)&th_h[src + 4];
        *(uint4*)&sma[SOFF + 2304 + row * 36 + off]     = *(const uint4*)&th_l[src];
        *(uint4*)&sma[SOFF + 2304 + row * 36 + off + 4] = *(const uint4*)&th_l[src + 4];
    }
    __syncthreads();
    uint32_t qh[4][4], ql[4][4];
    {
        uint32_t qoff = smb + (SOFF + (rows0 + ar) * 36 + ak) * 4;
        #pragma unroll
        for (int s = 0; s < 4; s++) ldsm4(qh[s], qoff + s*32);
        #pragma unroll
        for (int s = 0; s < 4; s++) ldsm4(ql[s], qoff + 2304*4 + s*32);
    }
    __syncthreads();

    // ---- scores: 8 chunks of 128 phi rows, exp-fp16 into P ----
    const int srow = t >> 1, shalf = (t & 1) * 16;
    #define PREFS(mb_, buf_) do {                                              \
        size_t src = ((size_t)b * DOWN + (mb_) + srow) * 32 + shalf;           \
        uint32_t d = smb + (SOFF + (buf_) * STBUF2 + srow * 36 + shalf) * 4;   \
        cp16(d,      ph_h + src);      cp16(d + 16, ph_h + src + 4);           \
        cp16(d + 32, ph_h + src + 8);  cp16(d + 48, ph_h + src + 12);          \
        uint32_t dl = d + 4608 * 4;                                            \
        cp16(dl,      ph_l + src);     cp16(dl + 16, ph_l + src + 4);          \
        cp16(dl + 32, ph_l + src + 8); cp16(dl + 48, ph_l + src + 12);         \
    } while (0)

    PREFS(0, 0);
    cp_commit();

    for (int c = 0; c < 8; c++) {
        cp_wait0();
        __syncthreads();
        if (c + 1 < 8) { PREFS((c + 1) * 128, (c + 1) & 1); cp_commit(); }

        const uint32_t bb = smb + (SOFF + (c & 1) * STBUF2) * 4;
        float4 sc[8];
        #pragma unroll
        for (int nf = 0; nf < 8; nf++) sc[nf] = make_float4(0.f, 0.f, 0.f, 0.f);

        #pragma unroll
        for (int s = 0; s < 4; s++) {
            #pragma unroll
            for (int p = 0; p < 4; p++) {
                uint32_t boffb = ((nw * 64 + p * 16 + br) * 36 + bk) * 4;
                uint32_t bh[4], bl[4];
                ldsm4(bh, bb + boffb + s*32);
                ldsm4(bl, bb + 4608*4 + boffb + s*32);
                mma_x3(sc[2*p],   qh[s], ql[s], bh[0], bh[1], bl[0], bl[1]);
                mma_x3(sc[2*p+1], qh[s], ql[s], bh[2], bh[3], bl[2], bl[3]);
            }
        }

        // per-(row, chunk, half) max over this warp's 64 cols
        float m0 = -1e30f, m1 = -1e30f;
        #pragma unroll
        for (int nf = 0; nf < 8; nf++) {
            m0 = fmaxf(m0, fmaxf(sc[nf].x, sc[nf].y));
            m1 = fmaxf(m1, fmaxf(sc[nf].z, sc[nf].w));
        }
        m0 = fmaxf(m0, __shfl_xor_sync(0xffffffffu, m0, 1));
        m0 = fmaxf(m0, __shfl_xor_sync(0xffffffffu, m0, 2));
        m1 = fmaxf(m1, __shfl_xor_sync(0xffffffffu, m1, 1));
        m1 = fmaxf(m1, __shfl_xor_sync(0xffffffffu, m1, 2));
        if (tg == 0) {
            ((float*)sma)[MC_OFF + (rows0 + g_) * 16 + c*2 + nw]     = m0;
            ((float*)sma)[MC_OFF + (rows0 + 8 + g_) * 16 + c*2 + nw] = m1;
        }
        // exp + store P (unnormalized)
        #pragma unroll
        for (int nf = 0; nf < 8; nf++) {
            int pairidx = c*64 + nw*32 + nf*4 + tg;
            float4 v = sc[nf];
            sma[(rows0 + g_) * PSTR + pairidx]     = pack2h(__expf(v.x - m0), __expf(v.y - m0));
            sma[(rows0 + 8 + g_) * PSTR + pairidx] = pack2h(__expf(v.z - m1), __expf(v.w - m1));
        }
    }
    #undef PREFS

    // prefetch first PV g-chunk; flies during rescale
    const int grow = t;
    #define PREFG(kb_, buf_) do {                                              \
        size_t src = ((size_t)b * 256 + grow) * 512 + ((kb_) >> 1);            \
        uint32_t d = smb + (SOFF + (buf_) * STBUF2 + grow * 36) * 4;           \
        cp16(d,      gT_f + src);      cp16(d + 16, gT_f + src + 4);           \
        cp16(d + 32, gT_f + src + 8);  cp16(d + 48, gT_f + src + 12);          \
        cp16(d + 64, gT_f + src + 16); cp16(d + 80, gT_f + src + 20);          \
        cp16(d + 96, gT_f + src + 24); cp16(d + 112, gT_f + src + 28);         \
    } while (0)
    PREFG(0, 0);
    cp_commit();
    __syncthreads();   // P + m_c visible

    // ---- rescale pass: P *= exp(m_chunk - m_final); sum; inv per row ----
    {
        int r = t >> 2, l4 = t & 3;
        const float* mc = (const float*)sma + MC_OFF + r * 16;
        float mf = -1e30f;
        #pragma unroll
        for (int i = 0; i < 16; i++) mf = fmaxf(mf, mc[i]);
        float sum = 0.f;
        #pragma unroll
        for (int c8 = 0; c8 < 8; c8++) {
            #pragma unroll
            for (int nn = 0; nn < 2; nn++) {
                float f = __expf(mc[c8*2 + nn] - mf);
                int jb = c8*64 + nn*32;
                for (int j = jb + l4; j < jb + 32; j += 4) {
                    uint32_t u = sma[r * PSTR + j];
                    __half2 h = *(__half2*)&u;
                    float f0 = __half2float(h.x) * f;
                    float f1 = __half2float(h.y) * f;
                    sum += f0 + f1;
                    sma[r * PSTR + j] = pack2h(f0, f1);
                }
            }
        }
        sum += __shfl_xor_sync(0xffffffffu, sum, 1);
        sum += __shfl_xor_sync(0xffffffffu, sum, 2);
        if (l4 == 0) ((float*)sma)[INV_OFF + r] = 1.0f / sum;
    }
    __syncthreads();

    // ---- PV (fp16 x1): out[64][256] ----
    float4 oc[16];
    #pragma unroll
    for (int nf = 0; nf < 16; nf++) oc[nf] = make_float4(0.f, 0.f, 0.f, 0.f);

    for (int ki = 0; ki < 16; ki++) {
        cp_wait0();
        __syncthreads();
        if (ki + 1 < 16) { PREFG((ki + 1) * 64, (ki + 1) & 1); cp_commit(); }

        const uint32_t bb = smb + (SOFF + (ki & 1) * STBUF2) * 4;
        #pragma unroll
        for (int s = 0; s < 4; s++) {
            int kp = ki * 32 + s * 8;
            uint32_t a0 = sma[(rows0 + g_) * PSTR + kp + tg];
            uint32_t a1 = sma[(rows0 + 8 + g_) * PSTR + kp + tg];
            uint32_t a2 = sma[(rows0 + g_) * PSTR + kp + tg + 4];
            uint32_t a3 = sma[(rows0 + 8 + g_) * PSTR + kp + tg + 4];
            #pragma unroll
            for (int p = 0; p < 8; p++) {
                uint32_t boffg = ((nw * 128 + p * 16 + br) * 36 + bk) * 4;
                uint32_t bg[4];
                ldsm4(bg, bb + boffg + s*32);
                mma_f16(oc[2*p],   a0, a1, a2, a3, bg[0], bg[1]);
                mma_f16(oc[2*p+1], a0, a1, a2, a3, bg[2], bg[3]);
            }
        }
    }
    #undef PREFG

    // epilogue: normalize rows by inv, write fp16 pairs
    const float i0 = ((const float*)sma)[INV_OFF + rows0 + g_];
    const float i1 = ((const float*)sma)[INV_OFF + rows0 + 8 + g_];
    #pragma unroll
    for (int nf = 0; nf < 16; nf++) {
        int colp = nw * 64 + nf * 4 + tg;
        size_t r0 = ((size_t)b * LOC + n0 + rows0 + g_) * 128 + colp;
        size_t r1 = ((size_t)b * LOC + n0 + rows0 + 8 + g_) * 128 + colp;
        ag_f[r0] = pack2h(oc[nf].x * i0, oc[nf].y * i0);
        ag_f[r1] = pack2h(oc[nf].z * i1, oc[nf].w * i1);
    }
}

// ---------------------------------------------------------------------------
// kernel_launch
// ---------------------------------------------------------------------------
extern "C" void kernel_launch(void* const* d_in, const int* in_sizes, int n_in,
                              void* d_out, int out_size)
{
    const float* x       = (const float*)d_in[0];
    const float* k_theta = (const float*)d_in[1];
    const float* u_theta = (const float*)d_in[2];
    const float* k_phi   = (const float*)d_in[3];
    const float* u_phi   = (const float*)d_in[4];
    const float* k_g     = (const float*)d_in[5];
    const float* u_g     = (const float*)d_in[6];
    const float* k_attn  = (const float*)d_in[7];
    const float* u_attn  = (const float*)d_in[8];
    const float* sigma   = (const float*)d_in[9];
    float* out = (float*)d_out;

    uint32_t *xh, *xl, *xfh, *wtpTh, *wtpTl, *wgTf, *waTf;
    uint32_t *thh, *thl, *phh, *phl, *gTf, *agf;
    float *phifull, *gfull;
    cudaGetSymbolAddress((void**)&xh,    d_xh);
    cudaGetSymbolAddress((void**)&xl,    d_xl);
    cudaGetSymbolAddress((void**)&xfh,   d_xfh);
    cudaGetSymbolAddress((void**)&wtpTh, d_wtpTh);
    cudaGetSymbolAddress((void**)&wtpTl, d_wtpTl);
    cudaGetSymbolAddress((void**)&wgTf,  d_wgTf);
    cudaGetSymbolAddress((void**)&waTf,  d_waTf);
    cudaGetSymbolAddress((void**)&thh,   d_thh);
    cudaGetSymbolAddress((void**)&thl,   d_thl);
    cudaGetSymbolAddress((void**)&phh,   d_phh);
    cudaGetSymbolAddress((void**)&phl,   d_phl);
    cudaGetSymbolAddress((void**)&gTf,   d_gTf);
    cudaGetSymbolAddress((void**)&agf,   d_agf);
    cudaGetSymbolAddress((void**)&phifull, d_phifull);
    cudaGetSymbolAddress((void**)&gfull,   d_gfull);

    cudaFuncSetAttribute(gemm_x3,  cudaFuncAttributeMaxDynamicSharedMemorySize, GEMM_SMEM);
    cudaFuncSetAttribute(gemm1<1>, cudaFuncAttributeMaxDynamicSharedMemorySize, GEMM1_SMEM);
    cudaFuncSetAttribute(gemm1<2>, cudaFuncAttributeMaxDynamicSharedMemorySize, GEMM1_SMEM);
    cudaFuncSetAttribute(attn3,    cudaFuncAttributeMaxDynamicSharedMemorySize, ATTN_SMEM);

    prep_w<<<640, 256>>>(k_theta, k_phi, k_g, k_attn, wtpTh, wtpTl, wgTf, waTf);
    prep_x<<<16384, 256>>>(x, xh, xl, xfh);
    spectral4_kernel<<<4, 256>>>(k_theta, u_theta, k_phi, u_phi,
                                 k_g, u_g, k_attn, u_attn);
    gemm_x3<<<dim3(1, MTOT / 128), 256, GEMM_SMEM>>>(
        xh, xl, wtpTh, wtpTl, thh, thl, phifull, 256);
    pool_phi<<<2048, 256>>>(phifull, phh, phl);
    gemm1<1><<<dim3(4, MTOT / 128), 256, GEMM1_SMEM>>>(
        xfh, wgTf, gfull, nullptr, nullptr, 256, 256);
    pool_g<<<8192, 256>>>(gfull, gTf);
    attn3<<<dim3(LOC / 64, B_), 256, ATTN_SMEM>>>(thh, thl, phh, phl, gTf, agf);
    gemm1<2><<<dim3(8, MTOT / 128), 256, GEMM1_SMEM>>>(
        agf, waTf, out, x, sigma, 512, 128);
}

// round 9
// speedup vs baseline: 5.3777x; 1.0190x over previous
#include <cuda_runtime.h>
#include <cuda_bf16.h>
#include <cuda_fp16.h>
#include <math.h>
#include <stdint.h>

#define B_   16
#define CC   512
#define C8   64
#define C2   256
#define LOC  4096
#define DOWN 1024
#define MTOT 65536

// ---------------------------------------------------------------------------
// Device scratch
// ---------------------------------------------------------------------------
__device__ float d_invs[4];
__device__ uint32_t d_xh   [MTOT * 256];         // x bf16 hi plane
__device__ uint32_t d_xl   [MTOT * 256];         // x bf16 lo plane
__device__ uint32_t d_xfh  [MTOT * 256];         // x fp16 plane
__device__ uint32_t d_wtpTh[128 * 256];
__device__ uint32_t d_wtpTl[128 * 256];
__device__ uint32_t d_wgTf [256 * 256];
__device__ uint32_t d_waTf [512 * 128];
__device__ uint32_t d_thh  [MTOT * 32];
__device__ uint32_t d_thl  [MTOT * 32];
__device__ uint32_t d_phh  [B_ * DOWN * 32];     // pooled phi bf16 hi
__device__ uint32_t d_phl  [B_ * DOWN * 32];
__device__ uint32_t d_gTf  [B_ * C2 * 512];      // pooled g fp16, transposed
__device__ uint32_t d_agf  [MTOT * 128];         // attn_g fp16 plane

// ---------------------------------------------------------------------------
// helpers
// ---------------------------------------------------------------------------
__device__ __forceinline__ uint32_t pack2(float a, float b) {
    __nv_bfloat162 h = __floats2bfloat162_rn(a, b);
    return *(uint32_t*)&h;
}
__device__ __forceinline__ uint32_t pack2h(float a, float b) {
    __half2 h = __floats2half2_rn(a, b);
    return *(uint32_t*)&h;
}
__device__ __forceinline__ void split2(float a, float b, uint32_t& hi, uint32_t& lo) {
    float ha = __bfloat162float(__float2bfloat16_rn(a));
    float hb = __bfloat162float(__float2bfloat16_rn(b));
    hi = pack2(ha, hb);
    lo = pack2(a - ha, b - hb);
}
__device__ __forceinline__ void mma_bf16(float4& d,
    uint32_t a0, uint32_t a1, uint32_t a2, uint32_t a3, uint32_t b0, uint32_t b1)
{
    asm volatile("mma.sync.aligned.m16n8k16.row.col.f32.bf16.bf16.f32 "
        "{%0,%1,%2,%3}, {%4,%5,%6,%7}, {%8,%9}, {%0,%1,%2,%3};"
        : "+f"(d.x), "+f"(d.y), "+f"(d.z), "+f"(d.w)
        : "r"(a0), "r"(a1), "r"(a2), "r"(a3), "r"(b0), "r"(b1));
}
__device__ __forceinline__ void mma_f16(float4& d,
    uint32_t a0, uint32_t a1, uint32_t a2, uint32_t a3, uint32_t b0, uint32_t b1)
{
    asm volatile("mma.sync.aligned.m16n8k16.row.col.f32.f16.f16.f32 "
        "{%0,%1,%2,%3}, {%4,%5,%6,%7}, {%8,%9}, {%0,%1,%2,%3};"
        : "+f"(d.x), "+f"(d.y), "+f"(d.z), "+f"(d.w)
        : "r"(a0), "r"(a1), "r"(a2), "r"(a3), "r"(b0), "r"(b1));
}
__device__ __forceinline__ void mma_x3(float4& d,
    const uint32_t ah[4], const uint32_t al[4],
    uint32_t bh0, uint32_t bh1, uint32_t bl0, uint32_t bl1)
{
    mma_bf16(d, ah[0], ah[1], ah[2], ah[3], bh0, bh1);
    mma_bf16(d, ah[0], ah[1], ah[2], ah[3], bl0, bl1);
    mma_bf16(d, al[0], al[1], al[2], al[3], bh0, bh1);
}
__device__ __forceinline__ void ldsm4(uint32_t r[4], uint32_t addr) {
    asm volatile("ldmatrix.sync.aligned.m8n8.x4.shared.b16 {%0,%1,%2,%3}, [%4];"
        : "=r"(r[0]), "=r"(r[1]), "=r"(r[2]), "=r"(r[3]) : "r"(addr));
}
__device__ __forceinline__ void cp16(uint32_t dst_saddr, const uint32_t* src) {
    asm volatile("cp.async.cg.shared.global [%0], [%1], 16;\n" :: "r"(dst_saddr), "l"(src));
}
__device__ __forceinline__ void cp_commit() {
    asm volatile("cp.async.commit_group;\n" ::: "memory");
}
__device__ __forceinline__ void cp_wait0() {
    asm volatile("cp.async.wait_group 0;\n" ::: "memory");
}
__device__ __forceinline__ void cp_wait1() {
    asm volatile("cp.async.wait_group 1;\n" ::: "memory");
}

// ---------------------------------------------------------------------------
// prep kernels
// ---------------------------------------------------------------------------
__global__ void prep_x(const float* __restrict__ x,
                       uint32_t* __restrict__ xh, uint32_t* __restrict__ xl,
                       uint32_t* __restrict__ xf)
{
    size_t idx = (size_t)blockIdx.x * 256 + threadIdx.x;
    const float4* p = (const float4*)(x + idx * 8);
    float4 v0 = p[0], v1 = p[1];
    uint32_t h0,l0,h1,l1,h2,l2,h3,l3;
    split2(v0.x, v0.y, h0, l0); split2(v0.z, v0.w, h1, l1);
    split2(v1.x, v1.y, h2, l2); split2(v1.z, v1.w, h3, l3);
    *(uint4*)&xh[idx * 4] = make_uint4(h0, h1, h2, h3);
    *(uint4*)&xl[idx * 4] = make_uint4(l0, l1, l2, l3);
    *(uint4*)&xf[idx * 4] = make_uint4(pack2h(v0.x, v0.y), pack2h(v0.z, v0.w),
                                       pack2h(v1.x, v1.y), pack2h(v1.z, v1.w));
}

__global__ void prep_w(const float* __restrict__ kt, const float* __restrict__ kp,
                       const float* __restrict__ kg, const float* __restrict__ ka,
                       uint32_t* __restrict__ tpTh, uint32_t* __restrict__ tpTl,
                       uint32_t* __restrict__ gTf,  uint32_t* __restrict__ aTf)
{
    int i = blockIdx.x * 256 + threadIdx.x;
    if (i < 32768) {
        int n = i >> 8, j = i & 255;
        float a, b;
        if (n < 64) { a = kt[(2*j)*64 + n];      b = kt[(2*j+1)*64 + n]; }
        else        { a = kp[(2*j)*64 + n - 64]; b = kp[(2*j+1)*64 + n - 64]; }
        uint32_t h, l; split2(a, b, h, l);
        tpTh[i] = h; tpTl[i] = l;
    } else if (i < 98304) {
        int i2 = i - 32768; int n = i2 >> 8, j = i2 & 255;
        gTf[i2] = pack2h(kg[(2*j)*256 + n], kg[(2*j+1)*256 + n]);
    } else if (i < 163840) {
        int i2 = i - 98304; int n = i2 >> 7, j = i2 & 127;
        aTf[i2] = pack2h(ka[(2*j)*512 + n], ka[(2*j+1)*512 + n]);
    }
}

// ---------------------------------------------------------------------------
// Spectral norms: 4 blocks -> 1/sigma
// ---------------------------------------------------------------------------
__global__ void spectral4_kernel(const float* __restrict__ kt, const float* __restrict__ ut,
                                 const float* __restrict__ kp, const float* __restrict__ up,
                                 const float* __restrict__ kg, const float* __restrict__ ug,
                                 const float* __restrict__ ka, const float* __restrict__ ua)
{
    const float* W; const float* u; int Cin, Cout;
    switch (blockIdx.x) {
        case 0:  W = kt; u = ut; Cin = 512; Cout = 64;  break;
        case 1:  W = kp; u = up; Cin = 512; Cout = 64;  break;
        case 2:  W = kg; u = ug; Cin = 512; Cout = 256; break;
        default: W = ka; u = ua; Cin = 256; Cout = 512; break;
    }
    __shared__ float us[512];
    __shared__ float v[512];
    __shared__ float red[256];
    const int t = threadIdx.x;

    for (int j = t; j < Cout; j += 256) us[j] = u[j];
    __syncthreads();
    for (int i = t; i < Cin; i += 256) {
        const float4* wr = (const float4*)(W + (size_t)i * Cout);
        float s = 0.f;
        for (int j = 0; j < Cout / 4; j++) {
            float4 w4 = wr[j];
            s += us[4*j]*w4.x + us[4*j+1]*w4.y + us[4*j+2]*w4.z + us[4*j+3]*w4.w;
        }
        v[i] = s;
    }
    __syncthreads();
    float ss = 0.f;
    for (int i = t; i < Cin; i += 256) ss += v[i] * v[i];
    red[t] = ss; __syncthreads();
    for (int o = 128; o; o >>= 1) { if (t < o) red[t] += red[t + o]; __syncthreads(); }
    float inv_vn = 1.0f / (sqrtf(red[0]) + 1e-12f);
    __syncthreads();
    float rr = 0.f;
    for (int j = t; j < Cout; j += 256) {
        float s = 0.f;
        for (int i = 0; i < Cin; i++) s += v[i] * W[(size_t)i * Cout + j];
        s *= inv_vn;
        rr += s * s;
    }
    red[t] = rr; __syncthreads();
    for (int o = 128; o; o >>= 1) { if (t < o) red[t] += red[t + o]; __syncthreads(); }
    if (t == 0) {
        float rn = red[0];
        d_invs[blockIdx.x] = (sqrtf(rn) + 1e-12f) / rn;
    }
}

// ---------------------------------------------------------------------------
// bf16x3 GEMM (theta/phi conv): 2-stage cp.async, 2 CTAs/SM target.
// theta (cols 0-63) -> bf16 planes; phi (cols 64-127) -> POOLED bf16 planes,
// pooling fused into the epilogue (tile covers exactly one spatial row pair).
// ---------------------------------------------------------------------------
#define PLANE 2560
#define GEMM_SMEM (8 * PLANE * 4)    // 80 KB, 2 buffers

__global__ __launch_bounds__(256, 2)
void gemm_x3(const uint32_t* __restrict__ Ah, const uint32_t* __restrict__ Al,
             const uint32_t* __restrict__ Bh, const uint32_t* __restrict__ Bl,
             uint32_t* __restrict__ oph, uint32_t* __restrict__ opl,
             uint32_t* __restrict__ phh, uint32_t* __restrict__ phl, int KP)
{
    extern __shared__ uint32_t smg[];
    const uint32_t smb = (uint32_t)__cvta_generic_to_shared(smg);

    const int bm = blockIdx.y * 128;
    const int t = threadIdx.x;
    const int warp = t >> 5, lane = t & 31, g = lane >> 2, tg = lane & 3;
    const int wm = (warp >> 1) * 32, wn = (warp & 1) * 64;

    const int ar = (lane & 7) + ((lane >> 3) & 1) * 8;
    const int ak = (lane >> 4) * 4;
    const int br = (lane & 7) + (lane >> 4) * 8;
    const int bk = ((lane >> 3) & 1) * 4;
    uint32_t aoff[2], boff[4];
    #pragma unroll
    for (int mf = 0; mf < 2; mf++) aoff[mf] = ((wm + mf*16 + ar) * 20 + ak) * 4;
    #pragma unroll
    for (int p = 0; p < 4; p++)    boff[p]  = ((wn + p*16 + br) * 20 + bk) * 4;

    const int rs = t >> 1;
    const int hf = (t & 1) * 8;
    const int sidx = rs * 20 + hf;
    const uint32_t* pAh = Ah + (size_t)(bm + rs) * KP + hf;
    const uint32_t* pAl = Al + (size_t)(bm + rs) * KP + hf;
    const uint32_t* pBh = Bh + (size_t)rs * KP + hf;
    const uint32_t* pBl = Bl + (size_t)rs * KP + hf;

    float4 acc[2][8];
    #pragma unroll
    for (int i = 0; i < 2; i++)
        #pragma unroll
        for (int j = 0; j < 8; j++) acc[i][j] = make_float4(0.f, 0.f, 0.f, 0.f);

    const int nt = KP / 16;

    #define PREF(kt_, buf_) do {                                       \
        size_t off = (size_t)(kt_) * 16;                                \
        uint32_t d0 = smb + ((buf_) * 4 * PLANE + sidx) * 4;            \
        cp16(d0,              pAh + off); cp16(d0 + 16,             pAh + off + 4); \
        cp16(d0 + PLANE*4,    pAl + off); cp16(d0 + PLANE*4 + 16,   pAl + off + 4); \
        cp16(d0 + 2*PLANE*4,  pBh + off); cp16(d0 + 2*PLANE*4 + 16, pBh + off + 4); \
        cp16(d0 + 3*PLANE*4,  pBl + off); cp16(d0 + 3*PLANE*4 + 16, pBl + off + 4); \
    } while (0)

    PREF(0, 0);
    cp_commit();

    for (int kt = 0; kt < nt; kt++) {
        cp_wait0();
        __syncthreads();
        if (kt + 1 < nt) { PREF(kt + 1, (kt + 1) & 1); cp_commit(); }

        const uint32_t base = smb + ((kt & 1) * 4 * PLANE) * 4;
        #pragma unroll
        for (int s = 0; s < 2; s++) {
            uint32_t ah0[4], ah1[4], al0[4], al1[4];
            ldsm4(ah0, base + aoff[0] + s*32);
            ldsm4(ah1, base + aoff[1] + s*32);
            ldsm4(al0, base + PLANE*4 + aoff[0] + s*32);
            ldsm4(al1, base + PLANE*4 + aoff[1] + s*32);
            #pragma unroll
            for (int p = 0; p < 4; p++) {
                uint32_t bh[4], bl[4];
                ldsm4(bh, base + 2*PLANE*4 + boff[p] + s*32);
                ldsm4(bl, base + 3*PLANE*4 + boff[p] + s*32);
                mma_x3(acc[0][2*p],   ah0, al0, bh[0], bh[1], bl[0], bl[1]);
                mma_x3(acc[0][2*p+1], ah0, al0, bh[2], bh[3], bl[2], bl[3]);
                mma_x3(acc[1][2*p],   ah1, al1, bh[0], bh[1], bl[0], bl[1]);
                mma_x3(acc[1][2*p+1], ah1, al1, bh[2], bh[3], bl[2], bl[3]);
            }
        }
        __syncthreads();
    }
    #undef PREF

    const float s0 = d_invs[0], s1 = d_invs[1];
    float* smf = (float*)smg;    // reuse staging: 128 x 68 fp32 phi tile

    #pragma unroll
    for (int mf = 0; mf < 2; mf++) {
        int rl = wm + mf * 16 + g;          // local row
        int row = bm + rl;
        #pragma unroll
        for (int nf = 0; nf < 8; nf++) {
            int coln = wn + nf * 8 + 2 * tg;
            float4 c = acc[mf][nf];
            if (coln < 64) {
                int colp = nf * 4 + tg;
                uint32_t h0, l0, h1, l1;
                split2(c.x * s0, c.y * s0, h0, l0);
                split2(c.z * s0, c.w * s0, h1, l1);
                oph[(size_t)row * 32 + colp]       = h0;
                opl[(size_t)row * 32 + colp]       = l0;
                oph[(size_t)(row + 8) * 32 + colp] = h1;
                opl[(size_t)(row + 8) * 32 + colp] = l1;
            } else {
                int col = coln - 64;
                smf[rl * 68 + col]           = c.x * s1;
                smf[rl * 68 + col + 1]       = c.y * s1;
                smf[(rl + 8) * 68 + col]     = c.z * s1;
                smf[(rl + 8) * 68 + col + 1] = c.w * s1;
            }
        }
    }
    __syncthreads();

    // fused 2x2 phi pool: tile covers spatial rows h=2*h2, 2*h2+1 fully
    {
        int b  = blockIdx.y >> 5;
        int h2 = blockIdx.y & 31;
        #pragma unroll
        for (int i = 0; i < 4; i++) {
            int idx = t * 4 + i;              // 0..1023
            int w2 = idx >> 5, cp = idx & 31;
            int c0 = cp * 2;
            int r0 = 2 * w2;
            float a0 = fmaxf(fmaxf(smf[r0*68 + c0],      smf[(r0+1)*68 + c0]),
                             fmaxf(smf[(r0+64)*68 + c0], smf[(r0+65)*68 + c0]));
            float a1 = fmaxf(fmaxf(smf[r0*68 + c0+1],      smf[(r0+1)*68 + c0+1]),
                             fmaxf(smf[(r0+64)*68 + c0+1], smf[(r0+65)*68 + c0+1]));
            uint32_t h, l; split2(a0, a1, h, l);
            size_t o = ((size_t)b * 1024 + h2 * 32 + w2) * 32 + cp;
            phh[o] = h; phl[o] = l;
        }
    }
}

// ---------------------------------------------------------------------------
// fp16 x1 GEMM: 128x64 tile, 3-stage cp.async
// MODE 1: g conv -> fused 2x2 pool -> transposed fp16 gTf
// MODE 2: residual: of = X + sigma*invs[3]*acc
// ---------------------------------------------------------------------------
#define G1BUF 3840
#define GEMM1_SMEM (3 * G1BUF * 4)

template<int MODE>
__global__ __launch_bounds__(256, 2)
void gemm1(const uint32_t* __restrict__ Ah, const uint32_t* __restrict__ Bh,
           float* __restrict__ of, uint32_t* __restrict__ gTf,
           const float* __restrict__ X, const float* __restrict__ sigma_ptr,
           int N, int KP)
{
    extern __shared__ uint32_t smg[];
    const uint32_t smb = (uint32_t)__cvta_generic_to_shared(smg);

    const int bm = blockIdx.y * 128;
    const int bn = blockIdx.x * 64;
    const int t = threadIdx.x;
    const int warp = t >> 5, lane = t & 31, g = lane >> 2, tg = lane & 3;
    const int wm = (warp >> 1) * 32, wn = (warp & 1) * 32;

    const int ar = (lane & 7) + ((lane >> 3) & 1) * 8;
    const int ak = (lane >> 4) * 4;
    const int br = (lane & 7) + (lane >> 4) * 8;
    const int bk = ((lane >> 3) & 1) * 4;
    uint32_t aoff[2], boff[2];
    #pragma unroll
    for (int mf = 0; mf < 2; mf++) aoff[mf] = ((wm + mf*16 + ar) * 20 + ak) * 4;
    #pragma unroll
    for (int p = 0; p < 2; p++)    boff[p]  = (2560 + (wn + p*16 + br) * 20 + bk) * 4;

    const int rsA = t >> 1, hfA = (t & 1) * 8;
    const int rsB = t >> 2, hfB = (t & 3) * 4;
    const uint32_t* pA = Ah + (size_t)(bm + rsA) * KP + hfA;
    const uint32_t* pB = Bh + (size_t)(bn + rsB) * KP + hfB;
    const uint32_t sA = (rsA * 20 + hfA) * 4;
    const uint32_t sB = (2560 + rsB * 20 + hfB) * 4;

    float4 acc[2][4];
    #pragma unroll
    for (int i = 0; i < 2; i++)
        #pragma unroll
        for (int j = 0; j < 4; j++) acc[i][j] = make_float4(0.f, 0.f, 0.f, 0.f);

    const int nt = KP / 16;

    #define PREF1(kt_, buf_) do {                                   \
        size_t off = (size_t)(kt_) * 16;                             \
        uint32_t da = smb + (buf_) * G1BUF * 4 + sA;                 \
        cp16(da, pA + off); cp16(da + 16, pA + off + 4);             \
        uint32_t db = smb + (buf_) * G1BUF * 4 + sB;                 \
        cp16(db, pB + off);                                          \
    } while (0)

    PREF1(0, 0); cp_commit();
    PREF1(1, 1); cp_commit();

    for (int kt = 0; kt < nt; kt++) {
        if (kt == nt - 1) cp_wait0(); else cp_wait1();
        __syncthreads();
        if (kt + 2 < nt) { PREF1(kt + 2, (kt + 2) % 3); cp_commit(); }

        const uint32_t base = smb + ((kt % 3) * G1BUF) * 4;
        #pragma unroll
        for (int s = 0; s < 2; s++) {
            uint32_t a0[4], a1[4];
            ldsm4(a0, base + aoff[0] + s*32);
            ldsm4(a1, base + aoff[1] + s*32);
            #pragma unroll
            for (int p = 0; p < 2; p++) {
                uint32_t bf[4];
                ldsm4(bf, base + boff[p] + s*32);
                mma_f16(acc[0][2*p],   a0[0], a0[1], a0[2], a0[3], bf[0], bf[1]);
                mma_f16(acc[0][2*p+1], a0[0], a0[1], a0[2], a0[3], bf[2], bf[3]);
                mma_f16(acc[1][2*p],   a1[0], a1[1], a1[2], a1[3], bf[0], bf[1]);
                mma_f16(acc[1][2*p+1], a1[0], a1[1], a1[2], a1[3], bf[2], bf[3]);
            }
        }
    }
    #undef PREF1

    const float s0 = (MODE == 1) ? d_invs[2] : d_invs[3] * __ldg(sigma_ptr);

    if (MODE == 1) {
        // scaled fp32 tile into smem, then fused 2x2 pool + transpose -> gTf
        __syncthreads();
        float* smf = (float*)smg;   // 128 x 68
        #pragma unroll
        for (int mf = 0; mf < 2; mf++) {
            int rl = wm + mf * 16 + g;
            #pragma unroll
            for (int nf = 0; nf < 4; nf++) {
                int col = wn + nf * 8 + 2 * tg;
                float4 c = acc[mf][nf];
                smf[rl * 68 + col]           = c.x * s0;
                smf[rl * 68 + col + 1]       = c.y * s0;
                smf[(rl + 8) * 68 + col]     = c.z * s0;
                smf[(rl + 8) * 68 + col + 1] = c.w * s0;
            }
        }
        __syncthreads();
        int b  = blockIdx.y >> 5;
        int h2 = blockIdx.y & 31;
        #pragma unroll
        for (int i = 0; i < 4; i++) {
            int idx = t * 4 + i;               // 0..1023
            int c = idx >> 4, w2p = idx & 15;
            int r0 = 4 * w2p;
            float p0 = fmaxf(fmaxf(smf[r0*68 + c],      smf[(r0+1)*68 + c]),
                             fmaxf(smf[(r0+64)*68 + c], smf[(r0+65)*68 + c]));
            float p1 = fmaxf(fmaxf(smf[(r0+2)*68 + c],  smf[(r0+3)*68 + c]),
                             fmaxf(smf[(r0+66)*68 + c], smf[(r0+67)*68 + c]));
            gTf[((size_t)b * 256 + bn + c) * 512 + h2 * 16 + w2p] = pack2h(p0, p1);
        }
    } else {
        #pragma unroll
        for (int mf = 0; mf < 2; mf++) {
            int row = bm + wm + mf * 16 + g;
            #pragma unroll
            for (int nf = 0; nf < 4; nf++) {
                int col = bn + wn + nf * 8 + 2 * tg;
                float4 c = acc[mf][nf];
                size_t i0 = (size_t)row * N + col;
                size_t i1 = (size_t)(row + 8) * N + col;
                float2 x0 = *(const float2*)&X[i0];
                float2 x1 = *(const float2*)&X[i1];
                *(float2*)&of[i0] = make_float2(x0.x + s0 * c.x, x0.y + s0 * c.y);
                *(float2*)&of[i1] = make_float2(x1.x + s0 * c.z, x1.y + s0 * c.w);
            }
        }
    }
}

// ---------------------------------------------------------------------------
// attn3: 64 q-rows/block, P = unnormalized exp (fp16), flash-lite rescale
// ---------------------------------------------------------------------------
#define PSTR 516
#define MC_OFF  (64 * PSTR)
#define INV_OFF (MC_OFF + 1024)
#define SOFF    (INV_OFF + 64)
#define STBUF2  9216
#define ATTN_SMEM ((SOFF + 2 * STBUF2) * 4)

__global__ __launch_bounds__(256)
void attn3(const uint32_t* __restrict__ th_h, const uint32_t* __restrict__ th_l,
           const uint32_t* __restrict__ ph_h, const uint32_t* __restrict__ ph_l,
           const uint32_t* __restrict__ gT_f,
           uint32_t* __restrict__ ag_f)
{
    extern __shared__ uint32_t sma[];
    const uint32_t smb = (uint32_t)__cvta_generic_to_shared(sma);

    const int b  = blockIdx.y;
    const int n0 = blockIdx.x * 64;
    const int t  = threadIdx.x;
    const int warp = t >> 5, lane = t & 31;
    const int g_ = lane >> 2, tg = lane & 3;
    const int mw = warp >> 1;
    const int nw = warp & 1;
    const int rows0 = mw * 16;

    const int ar = (lane & 7) + ((lane >> 3) & 1) * 8;
    const int ak = (lane >> 4) * 4;
    const int br = (lane & 7) + (lane >> 4) * 8;
    const int bk = ((lane >> 3) & 1) * 4;

    {
        int row = t >> 2, off = (t & 3) * 8;
        size_t src = ((size_t)b * LOC + n0 + row) * 32 + off;
        *(uint4*)&sma[SOFF + row * 36 + off]     = *(const uint4*)&th_h[src];
        *(uint4*)&sma[SOFF + row * 36 + off + 4] = *(const uint4*)&th_h[src + 4];
        *(uint4*)&sma[SOFF + 2304 + row * 36 + off]     = *(const uint4*)&th_l[src];
        *(uint4*)&sma[SOFF + 2304 + row * 36 + off + 4] = *(const uint4*)&th_l[src + 4];
    }
    __syncthreads();
    uint32_t qh[4][4], ql[4][4];
    {
        uint32_t qoff = smb + (SOFF + (rows0 + ar) * 36 + ak) * 4;
        #pragma unroll
        for (int s = 0; s < 4; s++) ldsm4(qh[s], qoff + s*32);
        #pragma unroll
        for (int s = 0; s < 4; s++) ldsm4(ql[s], qoff + 2304*4 + s*32);
    }
    __syncthreads();

    const int srow = t >> 1, shalf = (t & 1) * 16;
    #define PREFS(mb_, buf_) do {                                              \
        size_t src = ((size_t)b * DOWN + (mb_) + srow) * 32 + shalf;           \
        uint32_t d = smb + (SOFF + (buf_) * STBUF2 + srow * 36 + shalf) * 4;   \
        cp16(d,      ph_h + src);      cp16(d + 16, ph_h + src + 4);           \
        cp16(d + 32, ph_h + src + 8);  cp16(d + 48, ph_h + src + 12);          \
        uint32_t dl = d + 4608 * 4;                                            \
        cp16(dl,      ph_l + src);     cp16(dl + 16, ph_l + src + 4);          \
        cp16(dl + 32, ph_l + src + 8); cp16(dl + 48, ph_l + src + 12);         \
    } while (0)

    PREFS(0, 0);
    cp_commit();

    for (int c = 0; c < 8; c++) {
        cp_wait0();
        __syncthreads();
        if (c + 1 < 8) { PREFS((c + 1) * 128, (c + 1) & 1); cp_commit(); }

        const uint32_t bb = smb + (SOFF + (c & 1) * STBUF2) * 4;
        float4 sc[8];
        #pragma unroll
        for (int nf = 0; nf < 8; nf++) sc[nf] = make_float4(0.f, 0.f, 0.f, 0.f);

        #pragma unroll
        for (int s = 0; s < 4; s++) {
            #pragma unroll
            for (int p = 0; p < 4; p++) {
                uint32_t boffb = ((nw * 64 + p * 16 + br) * 36 + bk) * 4;
                uint32_t bh[4], bl[4];
                ldsm4(bh, bb + boffb + s*32);
                ldsm4(bl, bb + 4608*4 + boffb + s*32);
                mma_x3(sc[2*p],   qh[s], ql[s], bh[0], bh[1], bl[0], bl[1]);
                mma_x3(sc[2*p+1], qh[s], ql[s], bh[2], bh[3], bl[2], bl[3]);
            }
        }

        float m0 = -1e30f, m1 = -1e30f;
        #pragma unroll
        for (int nf = 0; nf < 8; nf++) {
            m0 = fmaxf(m0, fmaxf(sc[nf].x, sc[nf].y));
            m1 = fmaxf(m1, fmaxf(sc[nf].z, sc[nf].w));
        }
        m0 = fmaxf(m0, __shfl_xor_sync(0xffffffffu, m0, 1));
        m0 = fmaxf(m0, __shfl_xor_sync(0xffffffffu, m0, 2));
        m1 = fmaxf(m1, __shfl_xor_sync(0xffffffffu, m1, 1));
        m1 = fmaxf(m1, __shfl_xor_sync(0xffffffffu, m1, 2));
        if (tg == 0) {
            ((float*)sma)[MC_OFF + (rows0 + g_) * 16 + c*2 + nw]     = m0;
            ((float*)sma)[MC_OFF + (rows0 + 8 + g_) * 16 + c*2 + nw] = m1;
        }
        #pragma unroll
        for (int nf = 0; nf < 8; nf++) {
            int pairidx = c*64 + nw*32 + nf*4 + tg;
            float4 v = sc[nf];
            sma[(rows0 + g_) * PSTR + pairidx]     = pack2h(__expf(v.x - m0), __expf(v.y - m0));
            sma[(rows0 + 8 + g_) * PSTR + pairidx] = pack2h(__expf(v.z - m1), __expf(v.w - m1));
        }
    }
    #undef PREFS

    const int grow = t;
    #define PREFG(kb_, buf_) do {                                              \
        size_t src = ((size_t)b * 256 + grow) * 512 + ((kb_) >> 1);            \
        uint32_t d = smb + (SOFF + (buf_) * STBUF2 + grow * 36) * 4;           \
        cp16(d,      gT_f + src);      cp16(d + 16, gT_f + src + 4);           \
        cp16(d + 32, gT_f + src + 8);  cp16(d + 48, gT_f + src + 12);          \
        cp16(d + 64, gT_f + src + 16); cp16(d + 80, gT_f + src + 20);          \
        cp16(d + 96, gT_f + src + 24); cp16(d + 112, gT_f + src + 28);         \
    } while (0)
    PREFG(0, 0);
    cp_commit();
    __syncthreads();

    {
        int r = t >> 2, l4 = t & 3;
        const float* mc = (const float*)sma + MC_OFF + r * 16;
        float mf = -1e30f;
        #pragma unroll
        for (int i = 0; i < 16; i++) mf = fmaxf(mf, mc[i]);
        float sum = 0.f;
        #pragma unroll
        for (int c8 = 0; c8 < 8; c8++) {
            #pragma unroll
            for (int nn = 0; nn < 2; nn++) {
                float f = __expf(mc[c8*2 + nn] - mf);
                int jb = c8*64 + nn*32;
                for (int j = jb + l4; j < jb + 32; j += 4) {
                    uint32_t u = sma[r * PSTR + j];
                    __half2 h = *(__half2*)&u;
                    float f0 = __half2float(h.x) * f;
                    float f1 = __half2float(h.y) * f;
                    sum += f0 + f1;
                    sma[r * PSTR + j] = pack2h(f0, f1);
                }
            }
        }
        sum += __shfl_xor_sync(0xffffffffu, sum, 1);
        sum += __shfl_xor_sync(0xffffffffu, sum, 2);
        if (l4 == 0) ((float*)sma)[INV_OFF + r] = 1.0f / sum;
    }
    __syncthreads();

    float4 oc[16];
    #pragma unroll
    for (int nf = 0; nf < 16; nf++) oc[nf] = make_float4(0.f, 0.f, 0.f, 0.f);

    for (int ki = 0; ki < 16; ki++) {
        cp_wait0();
        __syncthreads();
        if (ki + 1 < 16) { PREFG((ki + 1) * 64, (ki + 1) & 1); cp_commit(); }

        const uint32_t bb = smb + (SOFF + (ki & 1) * STBUF2) * 4;
        #pragma unroll
        for (int s = 0; s < 4; s++) {
            int kp = ki * 32 + s * 8;
            uint32_t a0 = sma[(rows0 + g_) * PSTR + kp + tg];
            uint32_t a1 = sma[(rows0 + 8 + g_) * PSTR + kp + tg];
            uint32_t a2 = sma[(rows0 + g_) * PSTR + kp + tg + 4];
            uint32_t a3 = sma[(rows0 + 8 + g_) * PSTR + kp + tg + 4];
            #pragma unroll
            for (int p = 0; p < 8; p++) {
                uint32_t boffg = ((nw * 128 + p * 16 + br) * 36 + bk) * 4;
                uint32_t bg[4];
                ldsm4(bg, bb + boffg + s*32);
                mma_f16(oc[2*p],   a0, a1, a2, a3, bg[0], bg[1]);
                mma_f16(oc[2*p+1], a0, a1, a2, a3, bg[2], bg[3]);
            }
        }
    }
    #undef PREFG

    const float i0 = ((const float*)sma)[INV_OFF + rows0 + g_];
    const float i1 = ((const float*)sma)[INV_OFF + rows0 + 8 + g_];
    #pragma unroll
    for (int nf = 0; nf < 16; nf++) {
        int colp = nw * 64 + nf * 4 + tg;
        size_t r0 = ((size_t)b * LOC + n0 + rows0 + g_) * 128 + colp;
        size_t r1 = ((size_t)b * LOC + n0 + rows0 + 8 + g_) * 128 + colp;
        ag_f[r0] = pack2h(oc[nf].x * i0, oc[nf].y * i0);
        ag_f[r1] = pack2h(oc[nf].z * i1, oc[nf].w * i1);
    }
}

// ---------------------------------------------------------------------------
// kernel_launch
// ---------------------------------------------------------------------------
extern "C" void kernel_launch(void* const* d_in, const int* in_sizes, int n_in,
                              void* d_out, int out_size)
{
    const float* x       = (const float*)d_in[0];
    const float* k_theta = (const float*)d_in[1];
    const float* u_theta = (const float*)d_in[2];
    const float* k_phi   = (const float*)d_in[3];
    const float* u_phi   = (const float*)d_in[4];
    const float* k_g     = (const float*)d_in[5];
    const float* u_g     = (const float*)d_in[6];
    const float* k_attn  = (const float*)d_in[7];
    const float* u_attn  = (const float*)d_in[8];
    const float* sigma   = (const float*)d_in[9];
    float* out = (float*)d_out;

    uint32_t *xh, *xl, *xfh, *wtpTh, *wtpTl, *wgTf, *waTf;
    uint32_t *thh, *thl, *phh, *phl, *gTf, *agf;
    cudaGetSymbolAddress((void**)&xh,    d_xh);
    cudaGetSymbolAddress((void**)&xl,    d_xl);
    cudaGetSymbolAddress((void**)&xfh,   d_xfh);
    cudaGetSymbolAddress((void**)&wtpTh, d_wtpTh);
    cudaGetSymbolAddress((void**)&wtpTl, d_wtpTl);
    cudaGetSymbolAddress((void**)&wgTf,  d_wgTf);
    cudaGetSymbolAddress((void**)&waTf,  d_waTf);
    cudaGetSymbolAddress((void**)&thh,   d_thh);
    cudaGetSymbolAddress((void**)&thl,   d_thl);
    cudaGetSymbolAddress((void**)&phh,   d_phh);
    cudaGetSymbolAddress((void**)&phl,   d_phl);
    cudaGetSymbolAddress((void**)&gTf,   d_gTf);
    cudaGetSymbolAddress((void**)&agf,   d_agf);

    cudaFuncSetAttribute(gemm_x3,  cudaFuncAttributeMaxDynamicSharedMemorySize, GEMM_SMEM);
    cudaFuncSetAttribute(gemm1<1>, cudaFuncAttributeMaxDynamicSharedMemorySize, GEMM1_SMEM);
    cudaFuncSetAttribute(gemm1<2>, cudaFuncAttributeMaxDynamicSharedMemorySize, GEMM1_SMEM);
    cudaFuncSetAttribute(attn3,    cudaFuncAttributeMaxDynamicSharedMemorySize, ATTN_SMEM);

    prep_w<<<640, 256>>>(k_theta, k_phi, k_g, k_attn, wtpTh, wtpTl, wgTf, waTf);
    prep_x<<<16384, 256>>>(x, xh, xl, xfh);
    spectral4_kernel<<<4, 256>>>(k_theta, u_theta, k_phi, u_phi,
                                 k_g, u_g, k_attn, u_attn);
    // theta conv + phi conv with fused phi pooling
    gemm_x3<<<dim3(1, MTOT / 128), 256, GEMM_SMEM>>>(
        xh, xl, wtpTh, wtpTl, thh, thl, phh, phl, 256);
    // g conv with fused pooling -> transposed fp16 gTf
    gemm1<1><<<dim3(4, MTOT / 128), 256, GEMM1_SMEM>>>(
        xfh, wgTf, nullptr, gTf, nullptr, nullptr, 256, 256);
    // fused attention
    attn3<<<dim3(LOC / 64, B_), 256, ATTN_SMEM>>>(thh, thl, phh, phl, gTf, agf);
    // output conv + residual
    gemm1<2><<<dim3(8, MTOT / 128), 256, GEMM1_SMEM>>>(
        agf, waTf, out, nullptr, x, sigma, 512, 128);
}

// round 10
// speedup vs baseline: 5.4506x; 1.0135x over previous
#include <cuda_runtime.h>
#include <cuda_fp16.h>
#include <math.h>
#include <stdint.h>

#define B_   16
#define CC   512
#define C8   64
#define C2   256
#define LOC  4096
#define DOWN 1024
#define MTOT 65536

// ---------------------------------------------------------------------------
// Device scratch: unified fp16 planes (packed half2 u32, pairs along k)
// ---------------------------------------------------------------------------
__device__ float d_invs[4];
__device__ uint32_t d_xh   [MTOT * 256];         // x fp16 hi plane
__device__ uint32_t d_xl   [MTOT * 256];         // x fp16 lo plane
__device__ uint32_t d_wtpTh[128 * 256];          // theta|phi weights fp16 hi (transposed)
__device__ uint32_t d_wtpTl[128 * 256];
__device__ uint32_t d_wgTf [256 * 256];          // g weights fp16 (transposed)
__device__ uint32_t d_waTf [512 * 128];          // attn weights fp16 (transposed)
__device__ uint32_t d_thh  [MTOT * 32];          // theta fp16 hi
__device__ uint32_t d_thl  [MTOT * 32];
__device__ uint32_t d_phh  [B_ * DOWN * 32];     // pooled phi fp16 hi
__device__ uint32_t d_phl  [B_ * DOWN * 32];
__device__ uint32_t d_gTf  [B_ * C2 * 512];      // pooled g fp16, transposed
__device__ uint32_t d_agf  [MTOT * 128];         // attn_g fp16 plane

// ---------------------------------------------------------------------------
// helpers
// ---------------------------------------------------------------------------
__device__ __forceinline__ uint32_t pack2h(float a, float b) {
    __half2 h = __floats2half2_rn(a, b);
    return *(uint32_t*)&h;
}
__device__ __forceinline__ void split2h(float a, float b, uint32_t& hi, uint32_t& lo) {
    float ha = __half2float(__float2half_rn(a));
    float hb = __half2float(__float2half_rn(b));
    hi = pack2h(ha, hb);
    lo = pack2h(a - ha, b - hb);
}
__device__ __forceinline__ void mma_f16(float4& d,
    uint32_t a0, uint32_t a1, uint32_t a2, uint32_t a3, uint32_t b0, uint32_t b1)
{
    asm volatile("mma.sync.aligned.m16n8k16.row.col.f32.f16.f16.f32 "
        "{%0,%1,%2,%3}, {%4,%5,%6,%7}, {%8,%9}, {%0,%1,%2,%3};"
        : "+f"(d.x), "+f"(d.y), "+f"(d.z), "+f"(d.w)
        : "r"(a0), "r"(a1), "r"(a2), "r"(a3), "r"(b0), "r"(b1));
}
__device__ __forceinline__ void mma_x3(float4& d,
    const uint32_t ah[4], const uint32_t al[4],
    uint32_t bh0, uint32_t bh1, uint32_t bl0, uint32_t bl1)
{
    mma_f16(d, ah[0], ah[1], ah[2], ah[3], bh0, bh1);
    mma_f16(d, ah[0], ah[1], ah[2], ah[3], bl0, bl1);
    mma_f16(d, al[0], al[1], al[2], al[3], bh0, bh1);
}
__device__ __forceinline__ void ldsm4(uint32_t r[4], uint32_t addr) {
    asm volatile("ldmatrix.sync.aligned.m8n8.x4.shared.b16 {%0,%1,%2,%3}, [%4];"
        : "=r"(r[0]), "=r"(r[1]), "=r"(r[2]), "=r"(r[3]) : "r"(addr));
}
__device__ __forceinline__ void cp16(uint32_t dst_saddr, const uint32_t* src) {
    asm volatile("cp.async.cg.shared.global [%0], [%1], 16;\n" :: "r"(dst_saddr), "l"(src));
}
__device__ __forceinline__ void cp_commit() {
    asm volatile("cp.async.commit_group;\n" ::: "memory");
}
__device__ __forceinline__ void cp_wait0() {
    asm volatile("cp.async.wait_group 0;\n" ::: "memory");
}
__device__ __forceinline__ void cp_wait1() {
    asm volatile("cp.async.wait_group 1;\n" ::: "memory");
}

// ---------------------------------------------------------------------------
// prep kernels
// ---------------------------------------------------------------------------
__global__ void prep_x(const float* __restrict__ x,
                       uint32_t* __restrict__ xh, uint32_t* __restrict__ xl)
{
    size_t idx = (size_t)blockIdx.x * 256 + threadIdx.x;
    const float4* p = (const float4*)(x + idx * 8);
    float4 v0 = p[0], v1 = p[1];
    uint32_t h0,l0,h1,l1,h2,l2,h3,l3;
    split2h(v0.x, v0.y, h0, l0); split2h(v0.z, v0.w, h1, l1);
    split2h(v1.x, v1.y, h2, l2); split2h(v1.z, v1.w, h3, l3);
    *(uint4*)&xh[idx * 4] = make_uint4(h0, h1, h2, h3);
    *(uint4*)&xl[idx * 4] = make_uint4(l0, l1, l2, l3);
}

__global__ void prep_w(const float* __restrict__ kt, const float* __restrict__ kp,
                       const float* __restrict__ kg, const float* __restrict__ ka,
                       uint32_t* __restrict__ tpTh, uint32_t* __restrict__ tpTl,
                       uint32_t* __restrict__ gTf,  uint32_t* __restrict__ aTf)
{
    int i = blockIdx.x * 256 + threadIdx.x;
    if (i < 32768) {
        int n = i >> 8, j = i & 255;
        float a, b;
        if (n < 64) { a = kt[(2*j)*64 + n];      b = kt[(2*j+1)*64 + n]; }
        else        { a = kp[(2*j)*64 + n - 64]; b = kp[(2*j+1)*64 + n - 64]; }
        uint32_t h, l; split2h(a, b, h, l);
        tpTh[i] = h; tpTl[i] = l;
    } else if (i < 98304) {
        int i2 = i - 32768; int n = i2 >> 8, j = i2 & 255;
        gTf[i2] = pack2h(kg[(2*j)*256 + n], kg[(2*j+1)*256 + n]);
    } else if (i < 163840) {
        int i2 = i - 98304; int n = i2 >> 7, j = i2 & 127;
        aTf[i2] = pack2h(ka[(2*j)*512 + n], ka[(2*j+1)*512 + n]);
    }
}

// ---------------------------------------------------------------------------
// Spectral norms: 4 blocks -> 1/sigma
// ---------------------------------------------------------------------------
__global__ void spectral4_kernel(const float* __restrict__ kt, const float* __restrict__ ut,
                                 const float* __restrict__ kp, const float* __restrict__ up,
                                 const float* __restrict__ kg, const float* __restrict__ ug,
                                 const float* __restrict__ ka, const float* __restrict__ ua)
{
    const float* W; const float* u; int Cin, Cout;
    switch (blockIdx.x) {
        case 0:  W = kt; u = ut; Cin = 512; Cout = 64;  break;
        case 1:  W = kp; u = up; Cin = 512; Cout = 64;  break;
        case 2:  W = kg; u = ug; Cin = 512; Cout = 256; break;
        default: W = ka; u = ua; Cin = 256; Cout = 512; break;
    }
    __shared__ float us[512];
    __shared__ float v[512];
    __shared__ float red[256];
    const int t = threadIdx.x;

    for (int j = t; j < Cout; j += 256) us[j] = u[j];
    __syncthreads();
    for (int i = t; i < Cin; i += 256) {
        const float4* wr = (const float4*)(W + (size_t)i * Cout);
        float s = 0.f;
        for (int j = 0; j < Cout / 4; j++) {
            float4 w4 = wr[j];
            s += us[4*j]*w4.x + us[4*j+1]*w4.y + us[4*j+2]*w4.z + us[4*j+3]*w4.w;
        }
        v[i] = s;
    }
    __syncthreads();
    float ss = 0.f;
    for (int i = t; i < Cin; i += 256) ss += v[i] * v[i];
    red[t] = ss; __syncthreads();
    for (int o = 128; o; o >>= 1) { if (t < o) red[t] += red[t + o]; __syncthreads(); }
    float inv_vn = 1.0f / (sqrtf(red[0]) + 1e-12f);
    __syncthreads();
    float rr = 0.f;
    for (int j = t; j < Cout; j += 256) {
        float s = 0.f;
        for (int i = 0; i < Cin; i++) s += v[i] * W[(size_t)i * Cout + j];
        s *= inv_vn;
        rr += s * s;
    }
    red[t] = rr; __syncthreads();
    for (int o = 128; o; o >>= 1) { if (t < o) red[t] += red[t + o]; __syncthreads(); }
    if (t == 0) {
        float rn = red[0];
        d_invs[blockIdx.x] = (sqrtf(rn) + 1e-12f) / rn;
    }
}

// ---------------------------------------------------------------------------
// fp16 x3 GEMM (theta/phi conv): 2-stage cp.async, ONE sync per k-tile.
// theta (cols 0-63) -> fp16 planes; phi (cols 64-127) -> fused-pooled planes.
// ---------------------------------------------------------------------------
#define PLANE 2560
#define GEMM_SMEM (8 * PLANE * 4)    // 80 KB, 2 buffers -> 2 CTAs/SM

__global__ __launch_bounds__(256, 2)
void gemm_x3(const uint32_t* __restrict__ Ah, const uint32_t* __restrict__ Al,
             const uint32_t* __restrict__ Bh, const uint32_t* __restrict__ Bl,
             uint32_t* __restrict__ oph, uint32_t* __restrict__ opl,
             uint32_t* __restrict__ phh, uint32_t* __restrict__ phl, int KP)
{
    extern __shared__ uint32_t smg[];
    const uint32_t smb = (uint32_t)__cvta_generic_to_shared(smg);

    const int bm = blockIdx.y * 128;
    const int t = threadIdx.x;
    const int warp = t >> 5, lane = t & 31, g = lane >> 2, tg = lane & 3;
    const int wm = (warp >> 1) * 32, wn = (warp & 1) * 64;

    const int ar = (lane & 7) + ((lane >> 3) & 1) * 8;
    const int ak = (lane >> 4) * 4;
    const int br = (lane & 7) + (lane >> 4) * 8;
    const int bk = ((lane >> 3) & 1) * 4;
    uint32_t aoff[2], boff[4];
    #pragma unroll
    for (int mf = 0; mf < 2; mf++) aoff[mf] = ((wm + mf*16 + ar) * 20 + ak) * 4;
    #pragma unroll
    for (int p = 0; p < 4; p++)    boff[p]  = ((wn + p*16 + br) * 20 + bk) * 4;

    const int rs = t >> 1;
    const int hf = (t & 1) * 8;
    const int sidx = rs * 20 + hf;
    const uint32_t* pAh = Ah + (size_t)(bm + rs) * KP + hf;
    const uint32_t* pAl = Al + (size_t)(bm + rs) * KP + hf;
    const uint32_t* pBh = Bh + (size_t)rs * KP + hf;
    const uint32_t* pBl = Bl + (size_t)rs * KP + hf;

    float4 acc[2][8];
    #pragma unroll
    for (int i = 0; i < 2; i++)
        #pragma unroll
        for (int j = 0; j < 8; j++) acc[i][j] = make_float4(0.f, 0.f, 0.f, 0.f);

    const int nt = KP / 16;

    #define PREF(kt_, buf_) do {                                       \
        size_t off = (size_t)(kt_) * 16;                                \
        uint32_t d0 = smb + ((buf_) * 4 * PLANE + sidx) * 4;            \
        cp16(d0,              pAh + off); cp16(d0 + 16,             pAh + off + 4); \
        cp16(d0 + PLANE*4,    pAl + off); cp16(d0 + PLANE*4 + 16,   pAl + off + 4); \
        cp16(d0 + 2*PLANE*4,  pBh + off); cp16(d0 + 2*PLANE*4 + 16, pBh + off + 4); \
        cp16(d0 + 3*PLANE*4,  pBl + off); cp16(d0 + 3*PLANE*4 + 16, pBl + off + 4); \
    } while (0)

    PREF(0, 0);
    cp_commit();

    for (int kt = 0; kt < nt; kt++) {
        cp_wait0();
        __syncthreads();   // single barrier: staging visible AND prior compute done
        if (kt + 1 < nt) { PREF(kt + 1, (kt + 1) & 1); cp_commit(); }

        const uint32_t base = smb + ((kt & 1) * 4 * PLANE) * 4;
        #pragma unroll
        for (int s = 0; s < 2; s++) {
            uint32_t ah0[4], ah1[4], al0[4], al1[4];
            ldsm4(ah0, base + aoff[0] + s*32);
            ldsm4(ah1, base + aoff[1] + s*32);
            ldsm4(al0, base + PLANE*4 + aoff[0] + s*32);
            ldsm4(al1, base + PLANE*4 + aoff[1] + s*32);
            #pragma unroll
            for (int p = 0; p < 4; p++) {
                uint32_t bh[4], bl[4];
                ldsm4(bh, base + 2*PLANE*4 + boff[p] + s*32);
                ldsm4(bl, base + 3*PLANE*4 + boff[p] + s*32);
                mma_x3(acc[0][2*p],   ah0, al0, bh[0], bh[1], bl[0], bl[1]);
                mma_x3(acc[0][2*p+1], ah0, al0, bh[2], bh[3], bl[2], bl[3]);
                mma_x3(acc[1][2*p],   ah1, al1, bh[0], bh[1], bl[0], bl[1]);
                mma_x3(acc[1][2*p+1], ah1, al1, bh[2], bh[3], bl[2], bl[3]);
            }
        }
        // no trailing sync: next iteration's top barrier guards buffer reuse
    }
    #undef PREF
    __syncthreads();   // all compute done before smem reuse in epilogue

    const float s0 = d_invs[0], s1 = d_invs[1];
    float* smf = (float*)smg;    // reuse staging: 128 x 68 fp32 phi tile

    #pragma unroll
    for (int mf = 0; mf < 2; mf++) {
        int rl = wm + mf * 16 + g;
        int row = bm + rl;
        #pragma unroll
        for (int nf = 0; nf < 8; nf++) {
            int coln = wn + nf * 8 + 2 * tg;
            float4 c = acc[mf][nf];
            if (coln < 64) {
                int colp = nf * 4 + tg;
                uint32_t h0, l0, h1, l1;
                split2h(c.x * s0, c.y * s0, h0, l0);
                split2h(c.z * s0, c.w * s0, h1, l1);
                oph[(size_t)row * 32 + colp]       = h0;
                opl[(size_t)row * 32 + colp]       = l0;
                oph[(size_t)(row + 8) * 32 + colp] = h1;
                opl[(size_t)(row + 8) * 32 + colp] = l1;
            } else {
                int col = coln - 64;
                smf[rl * 68 + col]           = c.x * s1;
                smf[rl * 68 + col + 1]       = c.y * s1;
                smf[(rl + 8) * 68 + col]     = c.z * s1;
                smf[(rl + 8) * 68 + col + 1] = c.w * s1;
            }
        }
    }
    __syncthreads();

    // fused 2x2 phi pool
    {
        int b  = blockIdx.y >> 5;
        int h2 = blockIdx.y & 31;
        #pragma unroll
        for (int i = 0; i < 4; i++) {
            int idx = t * 4 + i;
            int w2 = idx >> 5, cp = idx & 31;
            int c0 = cp * 2;
            int r0 = 2 * w2;
            float a0 = fmaxf(fmaxf(smf[r0*68 + c0],      smf[(r0+1)*68 + c0]),
                             fmaxf(smf[(r0+64)*68 + c0], smf[(r0+65)*68 + c0]));
            float a1 = fmaxf(fmaxf(smf[r0*68 + c0+1],      smf[(r0+1)*68 + c0+1]),
                             fmaxf(smf[(r0+64)*68 + c0+1], smf[(r0+65)*68 + c0+1]));
            uint32_t h, l; split2h(a0, a1, h, l);
            size_t o = ((size_t)b * 1024 + h2 * 32 + w2) * 32 + cp;
            phh[o] = h; phl[o] = l;
        }
    }
}

// ---------------------------------------------------------------------------
// fp16 x1 GEMM: 128x64 tile, 3-stage cp.async
// MODE 1: g conv -> fused 2x2 pool -> transposed fp16 gTf
// MODE 2: residual: of = X + sigma*invs[3]*acc
// ---------------------------------------------------------------------------
#define G1BUF 3840
#define GEMM1_SMEM (3 * G1BUF * 4)

template<int MODE>
__global__ __launch_bounds__(256, 2)
void gemm1(const uint32_t* __restrict__ Ah, const uint32_t* __restrict__ Bh,
           float* __restrict__ of, uint32_t* __restrict__ gTf,
           const float* __restrict__ X, const float* __restrict__ sigma_ptr,
           int N, int KP)
{
    extern __shared__ uint32_t smg[];
    const uint32_t smb = (uint32_t)__cvta_generic_to_shared(smg);

    const int bm = blockIdx.y * 128;
    const int bn = blockIdx.x * 64;
    const int t = threadIdx.x;
    const int warp = t >> 5, lane = t & 31, g = lane >> 2, tg = lane & 3;
    const int wm = (warp >> 1) * 32, wn = (warp & 1) * 32;

    const int ar = (lane & 7) + ((lane >> 3) & 1) * 8;
    const int ak = (lane >> 4) * 4;
    const int br = (lane & 7) + (lane >> 4) * 8;
    const int bk = ((lane >> 3) & 1) * 4;
    uint32_t aoff[2], boff[2];
    #pragma unroll
    for (int mf = 0; mf < 2; mf++) aoff[mf] = ((wm + mf*16 + ar) * 20 + ak) * 4;
    #pragma unroll
    for (int p = 0; p < 2; p++)    boff[p]  = (2560 + (wn + p*16 + br) * 20 + bk) * 4;

    const int rsA = t >> 1, hfA = (t & 1) * 8;
    const int rsB = t >> 2, hfB = (t & 3) * 4;
    const uint32_t* pA = Ah + (size_t)(bm + rsA) * KP + hfA;
    const uint32_t* pB = Bh + (size_t)(bn + rsB) * KP + hfB;
    const uint32_t sA = (rsA * 20 + hfA) * 4;
    const uint32_t sB = (2560 + rsB * 20 + hfB) * 4;

    float4 acc[2][4];
    #pragma unroll
    for (int i = 0; i < 2; i++)
        #pragma unroll
        for (int j = 0; j < 4; j++) acc[i][j] = make_float4(0.f, 0.f, 0.f, 0.f);

    const int nt = KP / 16;

    #define PREF1(kt_, buf_) do {                                   \
        size_t off = (size_t)(kt_) * 16;                             \
        uint32_t da = smb + (buf_) * G1BUF * 4 + sA;                 \
        cp16(da, pA + off); cp16(da + 16, pA + off + 4);             \
        uint32_t db = smb + (buf_) * G1BUF * 4 + sB;                 \
        cp16(db, pB + off);                                          \
    } while (0)

    PREF1(0, 0); cp_commit();
    PREF1(1, 1); cp_commit();

    for (int kt = 0; kt < nt; kt++) {
        if (kt == nt - 1) cp_wait0(); else cp_wait1();
        __syncthreads();
        if (kt + 2 < nt) { PREF1(kt + 2, (kt + 2) % 3); cp_commit(); }

        const uint32_t base = smb + ((kt % 3) * G1BUF) * 4;
        #pragma unroll
        for (int s = 0; s < 2; s++) {
            uint32_t a0[4], a1[4];
            ldsm4(a0, base + aoff[0] + s*32);
            ldsm4(a1, base + aoff[1] + s*32);
            #pragma unroll
            for (int p = 0; p < 2; p++) {
                uint32_t bf[4];
                ldsm4(bf, base + boff[p] + s*32);
                mma_f16(acc[0][2*p],   a0[0], a0[1], a0[2], a0[3], bf[0], bf[1]);
                mma_f16(acc[0][2*p+1], a0[0], a0[1], a0[2], a0[3], bf[2], bf[3]);
                mma_f16(acc[1][2*p],   a1[0], a1[1], a1[2], a1[3], bf[0], bf[1]);
                mma_f16(acc[1][2*p+1], a1[0], a1[1], a1[2], a1[3], bf[2], bf[3]);
            }
        }
    }
    #undef PREF1

    const float s0 = (MODE == 1) ? d_invs[2] : d_invs[3] * __ldg(sigma_ptr);

    if (MODE == 1) {
        __syncthreads();
        float* smf = (float*)smg;   // 128 x 68
        #pragma unroll
        for (int mf = 0; mf < 2; mf++) {
            int rl = wm + mf * 16 + g;
            #pragma unroll
            for (int nf = 0; nf < 4; nf++) {
                int col = wn + nf * 8 + 2 * tg;
                float4 c = acc[mf][nf];
                smf[rl * 68 + col]           = c.x * s0;
                smf[rl * 68 + col + 1]       = c.y * s0;
                smf[(rl + 8) * 68 + col]     = c.z * s0;
                smf[(rl + 8) * 68 + col + 1] = c.w * s0;
            }
        }
        __syncthreads();
        int b  = blockIdx.y >> 5;
        int h2 = blockIdx.y & 31;
        #pragma unroll
        for (int i = 0; i < 4; i++) {
            int idx = t * 4 + i;
            int c = idx >> 4, w2p = idx & 15;
            int r0 = 4 * w2p;
            float p0 = fmaxf(fmaxf(smf[r0*68 + c],      smf[(r0+1)*68 + c]),
                             fmaxf(smf[(r0+64)*68 + c], smf[(r0+65)*68 + c]));
            float p1 = fmaxf(fmaxf(smf[(r0+2)*68 + c],  smf[(r0+3)*68 + c]),
                             fmaxf(smf[(r0+66)*68 + c], smf[(r0+67)*68 + c]));
            gTf[((size_t)b * 256 + bn + c) * 512 + h2 * 16 + w2p] = pack2h(p0, p1);
        }
    } else {
        #pragma unroll
        for (int mf = 0; mf < 2; mf++) {
            int row = bm + wm + mf * 16 + g;
            #pragma unroll
            for (int nf = 0; nf < 4; nf++) {
                int col = bn + wn + nf * 8 + 2 * tg;
                float4 c = acc[mf][nf];
                size_t i0 = (size_t)row * N + col;
                size_t i1 = (size_t)(row + 8) * N + col;
                float2 x0 = *(const float2*)&X[i0];
                float2 x1 = *(const float2*)&X[i1];
                *(float2*)&of[i0] = make_float2(x0.x + s0 * c.x, x0.y + s0 * c.y);
                *(float2*)&of[i1] = make_float2(x1.x + s0 * c.z, x1.y + s0 * c.w);
            }
        }
    }
}

// ---------------------------------------------------------------------------
// attn3: 64 q-rows/block, scores fp16 x3, P = unnormalized exp (fp16),
// flash-lite rescale, PV fp16 x1. Single barrier per pipeline iteration.
// ---------------------------------------------------------------------------
#define PSTR 516
#define MC_OFF  (64 * PSTR)
#define INV_OFF (MC_OFF + 1024)
#define SOFF    (INV_OFF + 64)
#define STBUF2  9216
#define ATTN_SMEM ((SOFF + 2 * STBUF2) * 4)

__global__ __launch_bounds__(256)
void attn3(const uint32_t* __restrict__ th_h, const uint32_t* __restrict__ th_l,
           const uint32_t* __restrict__ ph_h, const uint32_t* __restrict__ ph_l,
           const uint32_t* __restrict__ gT_f,
           uint32_t* __restrict__ ag_f)
{
    extern __shared__ uint32_t sma[];
    const uint32_t smb = (uint32_t)__cvta_generic_to_shared(sma);

    const int b  = blockIdx.y;
    const int n0 = blockIdx.x * 64;
    const int t  = threadIdx.x;
    const int warp = t >> 5, lane = t & 31;
    const int g_ = lane >> 2, tg = lane & 3;
    const int mw = warp >> 1;
    const int nw = warp & 1;
    const int rows0 = mw * 16;

    const int ar = (lane & 7) + ((lane >> 3) & 1) * 8;
    const int ak = (lane >> 4) * 4;
    const int br = (lane & 7) + (lane >> 4) * 8;
    const int bk = ((lane >> 3) & 1) * 4;

    {
        int row = t >> 2, off = (t & 3) * 8;
        size_t src = ((size_t)b * LOC + n0 + row) * 32 + off;
        *(uint4*)&sma[SOFF + row * 36 + off]     = *(const uint4*)&th_h[src];
        *(uint4*)&sma[SOFF + row * 36 + off + 4] = *(const uint4*)&th_h[src + 4];
        *(uint4*)&sma[SOFF + 2304 + row * 36 + off]     = *(const uint4*)&th_l[src];
        *(uint4*)&sma[SOFF + 2304 + row * 36 + off + 4] = *(const uint4*)&th_l[src + 4];
    }
    __syncthreads();
    uint32_t qh[4][4], ql[4][4];
    {
        uint32_t qoff = smb + (SOFF + (rows0 + ar) * 36 + ak) * 4;
        #pragma unroll
        for (int s = 0; s < 4; s++) ldsm4(qh[s], qoff + s*32);
        #pragma unroll
        for (int s = 0; s < 4; s++) ldsm4(ql[s], qoff + 2304*4 + s*32);
    }
    __syncthreads();

    const int srow = t >> 1, shalf = (t & 1) * 16;
    #define PREFS(mb_, buf_) do {                                              \
        size_t src = ((size_t)b * DOWN + (mb_) + srow) * 32 + shalf;           \
        uint32_t d = smb + (SOFF + (buf_) * STBUF2 + srow * 36 + shalf) * 4;   \
        cp16(d,      ph_h + src);      cp16(d + 16, ph_h + src + 4);           \
        cp16(d + 32, ph_h + src + 8);  cp16(d + 48, ph_h + src + 12);          \
        uint32_t dl = d + 4608 * 4;                                            \
        cp16(dl,      ph_l + src);     cp16(dl + 16, ph_l + src + 4);          \
        cp16(dl + 32, ph_l + src + 8); cp16(dl + 48, ph_l + src + 12);         \
    } while (0)

    PREFS(0, 0);
    cp_commit();

    for (int c = 0; c < 8; c++) {
        cp_wait0();
        __syncthreads();
        if (c + 1 < 8) { PREFS((c + 1) * 128, (c + 1) & 1); cp_commit(); }

        const uint32_t bb = smb + (SOFF + (c & 1) * STBUF2) * 4;
        float4 sc[8];
        #pragma unroll
        for (int nf = 0; nf < 8; nf++) sc[nf] = make_float4(0.f, 0.f, 0.f, 0.f);

        #pragma unroll
        for (int s = 0; s < 4; s++) {
            #pragma unroll
            for (int p = 0; p < 4; p++) {
                uint32_t boffb = ((nw * 64 + p * 16 + br) * 36 + bk) * 4;
                uint32_t bh[4], bl[4];
                ldsm4(bh, bb + boffb + s*32);
                ldsm4(bl, bb + 4608*4 + boffb + s*32);
                mma_x3(sc[2*p],   qh[s], ql[s], bh[0], bh[1], bl[0], bl[1]);
                mma_x3(sc[2*p+1], qh[s], ql[s], bh[2], bh[3], bl[2], bl[3]);
            }
        }

        float m0 = -1e30f, m1 = -1e30f;
        #pragma unroll
        for (int nf = 0; nf < 8; nf++) {
            m0 = fmaxf(m0, fmaxf(sc[nf].x, sc[nf].y));
            m1 = fmaxf(m1, fmaxf(sc[nf].z, sc[nf].w));
        }
        m0 = fmaxf(m0, __shfl_xor_sync(0xffffffffu, m0, 1));
        m0 = fmaxf(m0, __shfl_xor_sync(0xffffffffu, m0, 2));
        m1 = fmaxf(m1, __shfl_xor_sync(0xffffffffu, m1, 1));
        m1 = fmaxf(m1, __shfl_xor_sync(0xffffffffu, m1, 2));
        if (tg == 0) {
            ((float*)sma)[MC_OFF + (rows0 + g_) * 16 + c*2 + nw]     = m0;
            ((float*)sma)[MC_OFF + (rows0 + 8 + g_) * 16 + c*2 + nw] = m1;
        }
        #pragma unroll
        for (int nf = 0; nf < 8; nf++) {
            int pairidx = c*64 + nw*32 + nf*4 + tg;
            float4 v = sc[nf];
            sma[(rows0 + g_) * PSTR + pairidx]     = pack2h(__expf(v.x - m0), __expf(v.y - m0));
            sma[(rows0 + 8 + g_) * PSTR + pairidx] = pack2h(__expf(v.z - m1), __expf(v.w - m1));
        }
        // no trailing sync: next top barrier guards staging buffer reuse
    }
    #undef PREFS

    const int grow = t;
    #define PREFG(kb_, buf_) do {                                              \
        size_t src = ((size_t)b * 256 + grow) * 512 + ((kb_) >> 1);            \
        uint32_t d = smb + (SOFF + (buf_) * STBUF2 + grow * 36) * 4;           \
        cp16(d,      gT_f + src);      cp16(d + 16, gT_f + src + 4);           \
        cp16(d + 32, gT_f + src + 8);  cp16(d + 48, gT_f + src + 12);          \
        cp16(d + 64, gT_f + src + 16); cp16(d + 80, gT_f + src + 20);          \
        cp16(d + 96, gT_f + src + 24); cp16(d + 112, gT_f + src + 28);         \
    } while (0)
    PREFG(0, 0);
    cp_commit();
    __syncthreads();   // P + m_c visible to all

    {
        int r = t >> 2, l4 = t & 3;
        const float* mc = (const float*)sma + MC_OFF + r * 16;
        float mf = -1e30f;
        #pragma unroll
        for (int i = 0; i < 16; i++) mf = fmaxf(mf, mc[i]);
        float sum = 0.f;
        #pragma unroll
        for (int c8 = 0; c8 < 8; c8++) {
            #pragma unroll
            for (int nn = 0; nn < 2; nn++) {
                float f = __expf(mc[c8*2 + nn] - mf);
                int jb = c8*64 + nn*32;
                for (int j = jb + l4; j < jb + 32; j += 4) {
                    uint32_t u = sma[r * PSTR + j];
                    __half2 h = *(__half2*)&u;
                    float f0 = __half2float(h.x) * f;
                    float f1 = __half2float(h.y) * f;
                    sum += f0 + f1;
                    sma[r * PSTR + j] = pack2h(f0, f1);
                }
            }
        }
        sum += __shfl_xor_sync(0xffffffffu, sum, 1);
        sum += __shfl_xor_sync(0xffffffffu, sum, 2);
        if (l4 == 0) ((float*)sma)[INV_OFF + r] = 1.0f / sum;
    }
    __syncthreads();

    float4 oc[16];
    #pragma unroll
    for (int nf = 0; nf < 16; nf++) oc[nf] = make_float4(0.f, 0.f, 0.f, 0.f);

    for (int ki = 0; ki < 16; ki++) {
        cp_wait0();
        __syncthreads();
        if (ki + 1 < 16) { PREFG((ki + 1) * 64, (ki + 1) & 1); cp_commit(); }

        const uint32_t bb = smb + (SOFF + (ki & 1) * STBUF2) * 4;
        #pragma unroll
        for (int s = 0; s < 4; s++) {
            int kp = ki * 32 + s * 8;
            uint32_t a0 = sma[(rows0 + g_) * PSTR + kp + tg];
            uint32_t a1 = sma[(rows0 + 8 + g_) * PSTR + kp + tg];
            uint32_t a2 = sma[(rows0 + g_) * PSTR + kp + tg + 4];
            uint32_t a3 = sma[(rows0 + 8 + g_) * PSTR + kp + tg + 4];
            #pragma unroll
            for (int p = 0; p < 8; p++) {
                uint32_t boffg = ((nw * 128 + p * 16 + br) * 36 + bk) * 4;
                uint32_t bg[4];
                ldsm4(bg, bb + boffg + s*32);
                mma_f16(oc[2*p],   a0, a1, a2, a3, bg[0], bg[1]);
                mma_f16(oc[2*p+1], a0, a1, a2, a3, bg[2], bg[3]);
            }
        }
        // no trailing sync
    }
    #undef PREFG

    const float i0 = ((const float*)sma)[INV_OFF + rows0 + g_];
    const float i1 = ((const float*)sma)[INV_OFF + rows0 + 8 + g_];
    #pragma unroll
    for (int nf = 0; nf < 16; nf++) {
        int colp = nw * 64 + nf * 4 + tg;
        size_t r0 = ((size_t)b * LOC + n0 + rows0 + g_) * 128 + colp;
        size_t r1 = ((size_t)b * LOC + n0 + rows0 + 8 + g_) * 128 + colp;
        ag_f[r0] = pack2h(oc[nf].x * i0, oc[nf].y * i0);
        ag_f[r1] = pack2h(oc[nf].z * i1, oc[nf].w * i1);
    }
}

// ---------------------------------------------------------------------------
// kernel_launch
// ---------------------------------------------------------------------------
extern "C" void kernel_launch(void* const* d_in, const int* in_sizes, int n_in,
                              void* d_out, int out_size)
{
    const float* x       = (const float*)d_in[0];
    const float* k_theta = (const float*)d_in[1];
    const float* u_theta = (const float*)d_in[2];
    const float* k_phi   = (const float*)d_in[3];
    const float* u_phi   = (const float*)d_in[4];
    const float* k_g     = (const float*)d_in[5];
    const float* u_g     = (const float*)d_in[6];
    const float* k_attn  = (const float*)d_in[7];
    const float* u_attn  = (const float*)d_in[8];
    const float* sigma   = (const float*)d_in[9];
    float* out = (float*)d_out;

    uint32_t *xh, *xl, *wtpTh, *wtpTl, *wgTf, *waTf;
    uint32_t *thh, *thl, *phh, *phl, *gTf, *agf;
    cudaGetSymbolAddress((void**)&xh,    d_xh);
    cudaGetSymbolAddress((void**)&xl,    d_xl);
    cudaGetSymbolAddress((void**)&wtpTh, d_wtpTh);
    cudaGetSymbolAddress((void**)&wtpTl, d_wtpTl);
    cudaGetSymbolAddress((void**)&wgTf,  d_wgTf);
    cudaGetSymbolAddress((void**)&waTf,  d_waTf);
    cudaGetSymbolAddress((void**)&thh,   d_thh);
    cudaGetSymbolAddress((void**)&thl,   d_thl);
    cudaGetSymbolAddress((void**)&phh,   d_phh);
    cudaGetSymbolAddress((void**)&phl,   d_phl);
    cudaGetSymbolAddress((void**)&gTf,   d_gTf);
    cudaGetSymbolAddress((void**)&agf,   d_agf);

    cudaFuncSetAttribute(gemm_x3,  cudaFuncAttributeMaxDynamicSharedMemorySize, GEMM_SMEM);
    cudaFuncSetAttribute(gemm1<1>, cudaFuncAttributeMaxDynamicSharedMemorySize, GEMM1_SMEM);
    cudaFuncSetAttribute(gemm1<2>, cudaFuncAttributeMaxDynamicSharedMemorySize, GEMM1_SMEM);
    cudaFuncSetAttribute(attn3,    cudaFuncAttributeMaxDynamicSharedMemorySize, ATTN_SMEM);

    prep_w<<<640, 256>>>(k_theta, k_phi, k_g, k_attn, wtpTh, wtpTl, wgTf, waTf);
    prep_x<<<16384, 256>>>(x, xh, xl);
    spectral4_kernel<<<4, 256>>>(k_theta, u_theta, k_phi, u_phi,
                                 k_g, u_g, k_attn, u_attn);
    // theta conv + phi conv with fused phi pooling (fp16 x3)
    gemm_x3<<<dim3(1, MTOT / 128), 256, GEMM_SMEM>>>(
        xh, xl, wtpTh, wtpTl, thh, thl, phh, phl, 256);
    // g conv with fused pooling -> transposed fp16 gTf
    gemm1<1><<<dim3(4, MTOT / 128), 256, GEMM1_SMEM>>>(
        xh, wgTf, nullptr, gTf, nullptr, nullptr, 256, 256);
    // fused attention
    attn3<<<dim3(LOC / 64, B_), 256, ATTN_SMEM>>>(thh, thl, phh, phl, gTf, agf);
    // output conv + residual
    gemm1<2><<<dim3(8, MTOT / 128), 256, GEMM1_SMEM>>>(
        agf, waTf, out, nullptr, x, sigma, 512, 128);
}

// round 11
// speedup vs baseline: 5.8311x; 1.0698x over previous
#include <cuda_runtime.h>
#include <cuda_fp16.h>
#include <math.h>
#include <stdint.h>

#define B_   16
#define CC   512
#define C8   64
#define C2   256
#define LOC  4096
#define DOWN 1024
#define MTOT 65536

// ---------------------------------------------------------------------------
// Device scratch: unified fp16 planes (packed half2 u32, pairs along k)
// ---------------------------------------------------------------------------
__device__ float d_invs[4];
__device__ uint32_t d_xh   [MTOT * 256];
__device__ uint32_t d_xl   [MTOT * 256];
__device__ uint32_t d_wtpTh[128 * 256];
__device__ uint32_t d_wtpTl[128 * 256];
__device__ uint32_t d_wgTf [256 * 256];
__device__ uint32_t d_waTf [512 * 128];
__device__ uint32_t d_thh  [MTOT * 32];
__device__ uint32_t d_thl  [MTOT * 32];
__device__ uint32_t d_phh  [B_ * DOWN * 32];
__device__ uint32_t d_phl  [B_ * DOWN * 32];
__device__ uint32_t d_gTf  [B_ * C2 * 512];
__device__ uint32_t d_agf  [MTOT * 128];

// ---------------------------------------------------------------------------
// helpers
// ---------------------------------------------------------------------------
__device__ __forceinline__ uint32_t pack2h(float a, float b) {
    __half2 h = __floats2half2_rn(a, b);
    return *(uint32_t*)&h;
}
__device__ __forceinline__ void split2h(float a, float b, uint32_t& hi, uint32_t& lo) {
    float ha = __half2float(__float2half_rn(a));
    float hb = __half2float(__float2half_rn(b));
    hi = pack2h(ha, hb);
    lo = pack2h(a - ha, b - hb);
}
__device__ __forceinline__ void mma_f16(float4& d,
    uint32_t a0, uint32_t a1, uint32_t a2, uint32_t a3, uint32_t b0, uint32_t b1)
{
    asm volatile("mma.sync.aligned.m16n8k16.row.col.f32.f16.f16.f32 "
        "{%0,%1,%2,%3}, {%4,%5,%6,%7}, {%8,%9}, {%0,%1,%2,%3};"
        : "+f"(d.x), "+f"(d.y), "+f"(d.z), "+f"(d.w)
        : "r"(a0), "r"(a1), "r"(a2), "r"(a3), "r"(b0), "r"(b1));
}
__device__ __forceinline__ void mma_x3(float4& d,
    const uint32_t ah[4], const uint32_t al[4],
    uint32_t bh0, uint32_t bh1, uint32_t bl0, uint32_t bl1)
{
    mma_f16(d, ah[0], ah[1], ah[2], ah[3], bh0, bh1);
    mma_f16(d, ah[0], ah[1], ah[2], ah[3], bl0, bl1);
    mma_f16(d, al[0], al[1], al[2], al[3], bh0, bh1);
}
__device__ __forceinline__ void ldsm4(uint32_t r[4], uint32_t addr) {
    asm volatile("ldmatrix.sync.aligned.m8n8.x4.shared.b16 {%0,%1,%2,%3}, [%4];"
        : "=r"(r[0]), "=r"(r[1]), "=r"(r[2]), "=r"(r[3]) : "r"(addr));
}
__device__ __forceinline__ void cp16(uint32_t dst_saddr, const uint32_t* src) {
    asm volatile("cp.async.cg.shared.global [%0], [%1], 16;\n" :: "r"(dst_saddr), "l"(src));
}
__device__ __forceinline__ void cp_commit() {
    asm volatile("cp.async.commit_group;\n" ::: "memory");
}
__device__ __forceinline__ void cp_wait0() {
    asm volatile("cp.async.wait_group 0;\n" ::: "memory");
}
__device__ __forceinline__ void cp_wait1() {
    asm volatile("cp.async.wait_group 1;\n" ::: "memory");
}

// ---------------------------------------------------------------------------
// prep kernels
// ---------------------------------------------------------------------------
__global__ void prep_x(const float* __restrict__ x,
                       uint32_t* __restrict__ xh, uint32_t* __restrict__ xl)
{
    size_t idx = (size_t)blockIdx.x * 256 + threadIdx.x;
    const float4* p = (const float4*)(x + idx * 8);
    float4 v0 = p[0], v1 = p[1];
    uint32_t h0,l0,h1,l1,h2,l2,h3,l3;
    split2h(v0.x, v0.y, h0, l0); split2h(v0.z, v0.w, h1, l1);
    split2h(v1.x, v1.y, h2, l2); split2h(v1.z, v1.w, h3, l3);
    *(uint4*)&xh[idx * 4] = make_uint4(h0, h1, h2, h3);
    *(uint4*)&xl[idx * 4] = make_uint4(l0, l1, l2, l3);
}

__global__ void prep_w(const float* __restrict__ kt, const float* __restrict__ kp,
                       const float* __restrict__ kg, const float* __restrict__ ka,
                       uint32_t* __restrict__ tpTh, uint32_t* __restrict__ tpTl,
                       uint32_t* __restrict__ gTf,  uint32_t* __restrict__ aTf)
{
    int i = blockIdx.x * 256 + threadIdx.x;
    if (i < 32768) {
        int n = i >> 8, j = i & 255;
        float a, b;
        if (n < 64) { a = kt[(2*j)*64 + n];      b = kt[(2*j+1)*64 + n]; }
        else        { a = kp[(2*j)*64 + n - 64]; b = kp[(2*j+1)*64 + n - 64]; }
        uint32_t h, l; split2h(a, b, h, l);
        tpTh[i] = h; tpTl[i] = l;
    } else if (i < 98304) {
        int i2 = i - 32768; int n = i2 >> 8, j = i2 & 255;
        gTf[i2] = pack2h(kg[(2*j)*256 + n], kg[(2*j+1)*256 + n]);
    } else if (i < 163840) {
        int i2 = i - 98304; int n = i2 >> 7, j = i2 & 127;
        aTf[i2] = pack2h(ka[(2*j)*512 + n], ka[(2*j+1)*512 + n]);
    }
}

// ---------------------------------------------------------------------------
// Spectral norms: 4 blocks -> 1/sigma
// ---------------------------------------------------------------------------
__global__ void spectral4_kernel(const float* __restrict__ kt, const float* __restrict__ ut,
                                 const float* __restrict__ kp, const float* __restrict__ up,
                                 const float* __restrict__ kg, const float* __restrict__ ug,
                                 const float* __restrict__ ka, const float* __restrict__ ua)
{
    const float* W; const float* u; int Cin, Cout;
    switch (blockIdx.x) {
        case 0:  W = kt; u = ut; Cin = 512; Cout = 64;  break;
        case 1:  W = kp; u = up; Cin = 512; Cout = 64;  break;
        case 2:  W = kg; u = ug; Cin = 512; Cout = 256; break;
        default: W = ka; u = ua; Cin = 256; Cout = 512; break;
    }
    __shared__ float us[512];
    __shared__ float v[512];
    __shared__ float red[256];
    const int t = threadIdx.x;

    for (int j = t; j < Cout; j += 256) us[j] = u[j];
    __syncthreads();
    for (int i = t; i < Cin; i += 256) {
        const float4* wr = (const float4*)(W + (size_t)i * Cout);
        float s = 0.f;
        for (int j = 0; j < Cout / 4; j++) {
            float4 w4 = wr[j];
            s += us[4*j]*w4.x + us[4*j+1]*w4.y + us[4*j+2]*w4.z + us[4*j+3]*w4.w;
        }
        v[i] = s;
    }
    __syncthreads();
    float ss = 0.f;
    for (int i = t; i < Cin; i += 256) ss += v[i] * v[i];
    red[t] = ss; __syncthreads();
    for (int o = 128; o; o >>= 1) { if (t < o) red[t] += red[t + o]; __syncthreads(); }
    float inv_vn = 1.0f / (sqrtf(red[0]) + 1e-12f);
    __syncthreads();
    float rr = 0.f;
    for (int j = t; j < Cout; j += 256) {
        float s = 0.f;
        for (int i = 0; i < Cin; i++) s += v[i] * W[(size_t)i * Cout + j];
        s *= inv_vn;
        rr += s * s;
    }
    red[t] = rr; __syncthreads();
    for (int o = 128; o; o >>= 1) { if (t < o) red[t] += red[t + o]; __syncthreads(); }
    if (t == 0) {
        float rn = red[0];
        d_invs[blockIdx.x] = (sqrtf(rn) + 1e-12f) / rn;
    }
}

// ---------------------------------------------------------------------------
// fp16 x3 GEMM (theta/phi conv): unchanged from round 10
// ---------------------------------------------------------------------------
#define PLANE 2560
#define GEMM_SMEM (8 * PLANE * 4)

__global__ __launch_bounds__(256, 2)
void gemm_x3(const uint32_t* __restrict__ Ah, const uint32_t* __restrict__ Al,
             const uint32_t* __restrict__ Bh, const uint32_t* __restrict__ Bl,
             uint32_t* __restrict__ oph, uint32_t* __restrict__ opl,
             uint32_t* __restrict__ phh, uint32_t* __restrict__ phl, int KP)
{
    extern __shared__ uint32_t smg[];
    const uint32_t smb = (uint32_t)__cvta_generic_to_shared(smg);

    const int bm = blockIdx.y * 128;
    const int t = threadIdx.x;
    const int warp = t >> 5, lane = t & 31, g = lane >> 2, tg = lane & 3;
    const int wm = (warp >> 1) * 32, wn = (warp & 1) * 64;

    const int ar = (lane & 7) + ((lane >> 3) & 1) * 8;
    const int ak = (lane >> 4) * 4;
    const int br = (lane & 7) + (lane >> 4) * 8;
    const int bk = ((lane >> 3) & 1) * 4;
    uint32_t aoff[2], boff[4];
    #pragma unroll
    for (int mf = 0; mf < 2; mf++) aoff[mf] = ((wm + mf*16 + ar) * 20 + ak) * 4;
    #pragma unroll
    for (int p = 0; p < 4; p++)    boff[p]  = ((wn + p*16 + br) * 20 + bk) * 4;

    const int rs = t >> 1;
    const int hf = (t & 1) * 8;
    const int sidx = rs * 20 + hf;
    const uint32_t* pAh = Ah + (size_t)(bm + rs) * KP + hf;
    const uint32_t* pAl = Al + (size_t)(bm + rs) * KP + hf;
    const uint32_t* pBh = Bh + (size_t)rs * KP + hf;
    const uint32_t* pBl = Bl + (size_t)rs * KP + hf;

    float4 acc[2][8];
    #pragma unroll
    for (int i = 0; i < 2; i++)
        #pragma unroll
        for (int j = 0; j < 8; j++) acc[i][j] = make_float4(0.f, 0.f, 0.f, 0.f);

    const int nt = KP / 16;

    #define PREF(kt_, buf_) do {                                       \
        size_t off = (size_t)(kt_) * 16;                                \
        uint32_t d0 = smb + ((buf_) * 4 * PLANE + sidx) * 4;            \
        cp16(d0,              pAh + off); cp16(d0 + 16,             pAh + off + 4); \
        cp16(d0 + PLANE*4,    pAl + off); cp16(d0 + PLANE*4 + 16,   pAl + off + 4); \
        cp16(d0 + 2*PLANE*4,  pBh + off); cp16(d0 + 2*PLANE*4 + 16, pBh + off + 4); \
        cp16(d0 + 3*PLANE*4,  pBl + off); cp16(d0 + 3*PLANE*4 + 16, pBl + off + 4); \
    } while (0)

    PREF(0, 0);
    cp_commit();

    for (int kt = 0; kt < nt; kt++) {
        cp_wait0();
        __syncthreads();
        if (kt + 1 < nt) { PREF(kt + 1, (kt + 1) & 1); cp_commit(); }

        const uint32_t base = smb + ((kt & 1) * 4 * PLANE) * 4;
        #pragma unroll
        for (int s = 0; s < 2; s++) {
            uint32_t ah0[4], ah1[4], al0[4], al1[4];
            ldsm4(ah0, base + aoff[0] + s*32);
            ldsm4(ah1, base + aoff[1] + s*32);
            ldsm4(al0, base + PLANE*4 + aoff[0] + s*32);
            ldsm4(al1, base + PLANE*4 + aoff[1] + s*32);
            #pragma unroll
            for (int p = 0; p < 4; p++) {
                uint32_t bh[4], bl[4];
                ldsm4(bh, base + 2*PLANE*4 + boff[p] + s*32);
                ldsm4(bl, base + 3*PLANE*4 + boff[p] + s*32);
                mma_x3(acc[0][2*p],   ah0, al0, bh[0], bh[1], bl[0], bl[1]);
                mma_x3(acc[0][2*p+1], ah0, al0, bh[2], bh[3], bl[2], bl[3]);
                mma_x3(acc[1][2*p],   ah1, al1, bh[0], bh[1], bl[0], bl[1]);
                mma_x3(acc[1][2*p+1], ah1, al1, bh[2], bh[3], bl[2], bl[3]);
            }
        }
    }
    #undef PREF
    __syncthreads();

    const float s0 = d_invs[0], s1 = d_invs[1];
    float* smf = (float*)smg;

    #pragma unroll
    for (int mf = 0; mf < 2; mf++) {
        int rl = wm + mf * 16 + g;
        int row = bm + rl;
        #pragma unroll
        for (int nf = 0; nf < 8; nf++) {
            int coln = wn + nf * 8 + 2 * tg;
            float4 c = acc[mf][nf];
            if (coln < 64) {
                int colp = nf * 4 + tg;
                uint32_t h0, l0, h1, l1;
                split2h(c.x * s0, c.y * s0, h0, l0);
                split2h(c.z * s0, c.w * s0, h1, l1);
                oph[(size_t)row * 32 + colp]       = h0;
                opl[(size_t)row * 32 + colp]       = l0;
                oph[(size_t)(row + 8) * 32 + colp] = h1;
                opl[(size_t)(row + 8) * 32 + colp] = l1;
            } else {
                int col = coln - 64;
                smf[rl * 68 + col]           = c.x * s1;
                smf[rl * 68 + col + 1]       = c.y * s1;
                smf[(rl + 8) * 68 + col]     = c.z * s1;
                smf[(rl + 8) * 68 + col + 1] = c.w * s1;
            }
        }
    }
    __syncthreads();

    {
        int b  = blockIdx.y >> 5;
        int h2 = blockIdx.y & 31;
        #pragma unroll
        for (int i = 0; i < 4; i++) {
            int idx = t * 4 + i;
            int w2 = idx >> 5, cp = idx & 31;
            int c0 = cp * 2;
            int r0 = 2 * w2;
            float a0 = fmaxf(fmaxf(smf[r0*68 + c0],      smf[(r0+1)*68 + c0]),
                             fmaxf(smf[(r0+64)*68 + c0], smf[(r0+65)*68 + c0]));
            float a1 = fmaxf(fmaxf(smf[r0*68 + c0+1],      smf[(r0+1)*68 + c0+1]),
                             fmaxf(smf[(r0+64)*68 + c0+1], smf[(r0+65)*68 + c0+1]));
            uint32_t h, l; split2h(a0, a1, h, l);
            size_t o = ((size_t)b * 1024 + h2 * 32 + w2) * 32 + cp;
            phh[o] = h; phl[o] = l;
        }
    }
}

// ---------------------------------------------------------------------------
// fp16 x1 GEMM: unchanged from round 10
// ---------------------------------------------------------------------------
#define G1BUF 3840
#define GEMM1_SMEM (3 * G1BUF * 4)

template<int MODE>
__global__ __launch_bounds__(256, 2)
void gemm1(const uint32_t* __restrict__ Ah, const uint32_t* __restrict__ Bh,
           float* __restrict__ of, uint32_t* __restrict__ gTf,
           const float* __restrict__ X, const float* __restrict__ sigma_ptr,
           int N, int KP)
{
    extern __shared__ uint32_t smg[];
    const uint32_t smb = (uint32_t)__cvta_generic_to_shared(smg);

    const int bm = blockIdx.y * 128;
    const int bn = blockIdx.x * 64;
    const int t = threadIdx.x;
    const int warp = t >> 5, lane = t & 31, g = lane >> 2, tg = lane & 3;
    const int wm = (warp >> 1) * 32, wn = (warp & 1) * 32;

    const int ar = (lane & 7) + ((lane >> 3) & 1) * 8;
    const int ak = (lane >> 4) * 4;
    const int br = (lane & 7) + (lane >> 4) * 8;
    const int bk = ((lane >> 3) & 1) * 4;
    uint32_t aoff[2], boff[2];
    #pragma unroll
    for (int mf = 0; mf < 2; mf++) aoff[mf] = ((wm + mf*16 + ar) * 20 + ak) * 4;
    #pragma unroll
    for (int p = 0; p < 2; p++)    boff[p]  = (2560 + (wn + p*16 + br) * 20 + bk) * 4;

    const int rsA = t >> 1, hfA = (t & 1) * 8;
    const int rsB = t >> 2, hfB = (t & 3) * 4;
    const uint32_t* pA = Ah + (size_t)(bm + rsA) * KP + hfA;
    const uint32_t* pB = Bh + (size_t)(bn + rsB) * KP + hfB;
    const uint32_t sA = (rsA * 20 + hfA) * 4;
    const uint32_t sB = (2560 + rsB * 20 + hfB) * 4;

    float4 acc[2][4];
    #pragma unroll
    for (int i = 0; i < 2; i++)
        #pragma unroll
        for (int j = 0; j < 4; j++) acc[i][j] = make_float4(0.f, 0.f, 0.f, 0.f);

    const int nt = KP / 16;

    #define PREF1(kt_, buf_) do {                                   \
        size_t off = (size_t)(kt_) * 16;                             \
        uint32_t da = smb + (buf_) * G1BUF * 4 + sA;                 \
        cp16(da, pA + off); cp16(da + 16, pA + off + 4);             \
        uint32_t db = smb + (buf_) * G1BUF * 4 + sB;                 \
        cp16(db, pB + off);                                          \
    } while (0)

    PREF1(0, 0); cp_commit();
    PREF1(1, 1); cp_commit();

    for (int kt = 0; kt < nt; kt++) {
        if (kt == nt - 1) cp_wait0(); else cp_wait1();
        __syncthreads();
        if (kt + 2 < nt) { PREF1(kt + 2, (kt + 2) % 3); cp_commit(); }

        const uint32_t base = smb + ((kt % 3) * G1BUF) * 4;
        #pragma unroll
        for (int s = 0; s < 2; s++) {
            uint32_t a0[4], a1[4];
            ldsm4(a0, base + aoff[0] + s*32);
            ldsm4(a1, base + aoff[1] + s*32);
            #pragma unroll
            for (int p = 0; p < 2; p++) {
                uint32_t bf[4];
                ldsm4(bf, base + boff[p] + s*32);
                mma_f16(acc[0][2*p],   a0[0], a0[1], a0[2], a0[3], bf[0], bf[1]);
                mma_f16(acc[0][2*p+1], a0[0], a0[1], a0[2], a0[3], bf[2], bf[3]);
                mma_f16(acc[1][2*p],   a1[0], a1[1], a1[2], a1[3], bf[0], bf[1]);
                mma_f16(acc[1][2*p+1], a1[0], a1[1], a1[2], a1[3], bf[2], bf[3]);
            }
        }
    }
    #undef PREF1

    const float s0 = (MODE == 1) ? d_invs[2] : d_invs[3] * __ldg(sigma_ptr);

    if (MODE == 1) {
        __syncthreads();
        float* smf = (float*)smg;
        #pragma unroll
        for (int mf = 0; mf < 2; mf++) {
            int rl = wm + mf * 16 + g;
            #pragma unroll
            for (int nf = 0; nf < 4; nf++) {
                int col = wn + nf * 8 + 2 * tg;
                float4 c = acc[mf][nf];
                smf[rl * 68 + col]           = c.x * s0;
                smf[rl * 68 + col + 1]       = c.y * s0;
                smf[(rl + 8) * 68 + col]     = c.z * s0;
                smf[(rl + 8) * 68 + col + 1] = c.w * s0;
            }
        }
        __syncthreads();
        int b  = blockIdx.y >> 5;
        int h2 = blockIdx.y & 31;
        #pragma unroll
        for (int i = 0; i < 4; i++) {
            int idx = t * 4 + i;
            int c = idx >> 4, w2p = idx & 15;
            int r0 = 4 * w2p;
            float p0 = fmaxf(fmaxf(smf[r0*68 + c],      smf[(r0+1)*68 + c]),
                             fmaxf(smf[(r0+64)*68 + c], smf[(r0+65)*68 + c]));
            float p1 = fmaxf(fmaxf(smf[(r0+2)*68 + c],  smf[(r0+3)*68 + c]),
                             fmaxf(smf[(r0+66)*68 + c], smf[(r0+67)*68 + c]));
            gTf[((size_t)b * 256 + bn + c) * 512 + h2 * 16 + w2p] = pack2h(p0, p1);
        }
    } else {
        #pragma unroll
        for (int mf = 0; mf < 2; mf++) {
            int row = bm + wm + mf * 16 + g;
            #pragma unroll
            for (int nf = 0; nf < 4; nf++) {
                int col = bn + wn + nf * 8 + 2 * tg;
                float4 c = acc[mf][nf];
                size_t i0 = (size_t)row * N + col;
                size_t i1 = (size_t)(row + 8) * N + col;
                float2 x0 = *(const float2*)&X[i0];
                float2 x1 = *(const float2*)&X[i1];
                *(float2*)&of[i0] = make_float2(x0.x + s0 * c.x, x0.y + s0 * c.y);
                *(float2*)&of[i1] = make_float2(x1.x + s0 * c.z, x1.y + s0 * c.w);
            }
        }
    }
}

// ---------------------------------------------------------------------------
// attn4: 512 threads (16 warps). 64 q-rows/block.
// Scores fp16 x3 (warp grid 4m x 4n), P = unnorm exp fp16, flash rescale,
// PV fp16 x1 (warp grid 4m x 4n).
// ---------------------------------------------------------------------------
#define PSTR 516
#define MC_OFF  (64 * PSTR)             // 64 x 32 floats (row, chunk*4+quarter)
#define INV_OFF (MC_OFF + 2048)
#define SOFF    (INV_OFF + 64)
#define STBUF2  9216
#define ATTN_SMEM ((SOFF + 2 * STBUF2) * 4)

__global__ __launch_bounds__(512)
void attn4(const uint32_t* __restrict__ th_h, const uint32_t* __restrict__ th_l,
           const uint32_t* __restrict__ ph_h, const uint32_t* __restrict__ ph_l,
           const uint32_t* __restrict__ gT_f,
           uint32_t* __restrict__ ag_f)
{
    extern __shared__ uint32_t sma[];
    const uint32_t smb = (uint32_t)__cvta_generic_to_shared(sma);

    const int b  = blockIdx.y;
    const int n0 = blockIdx.x * 64;
    const int t  = threadIdx.x;
    const int warp = t >> 5, lane = t & 31;
    const int g_ = lane >> 2, tg = lane & 3;
    const int mw = warp >> 2;          // 0..3: row group of 16
    const int nw = warp & 3;           // 0..3: col quarter
    const int rows0 = mw * 16;

    const int ar = (lane & 7) + ((lane >> 3) & 1) * 8;
    const int ak = (lane >> 4) * 4;
    const int br = (lane & 7) + (lane >> 4) * 8;
    const int bk = ((lane >> 3) & 1) * 4;

    // ---- stage q (temporarily in staging buf), hoist fragments to regs ----
    {
        int row = t >> 3, off = (t & 7) * 4;
        size_t src = ((size_t)b * LOC + n0 + row) * 32 + off;
        *(uint4*)&sma[SOFF + row * 36 + off]        = *(const uint4*)&th_h[src];
        *(uint4*)&sma[SOFF + 2304 + row * 36 + off] = *(const uint4*)&th_l[src];
    }
    __syncthreads();
    uint32_t qh[4][4], ql[4][4];
    {
        uint32_t qoff = smb + (SOFF + (rows0 + ar) * 36 + ak) * 4;
        #pragma unroll
        for (int s = 0; s < 4; s++) ldsm4(qh[s], qoff + s*32);
        #pragma unroll
        for (int s = 0; s < 4; s++) ldsm4(ql[s], qoff + 2304*4 + s*32);
    }
    __syncthreads();

    // ---- scores: 8 chunks of 128 phi rows ----
    const int srow = t >> 2, shalf = (t & 3) * 8;
    #define PREFS(mb_, buf_) do {                                              \
        size_t src = ((size_t)b * DOWN + (mb_) + srow) * 32 + shalf;           \
        uint32_t d = smb + (SOFF + (buf_) * STBUF2 + srow * 36 + shalf) * 4;   \
        cp16(d,      ph_h + src);      cp16(d + 16, ph_h + src + 4);           \
        uint32_t dl = d + 4608 * 4;                                            \
        cp16(dl,     ph_l + src);      cp16(dl + 16, ph_l + src + 4);          \
    } while (0)

    PREFS(0, 0);
    cp_commit();

    for (int c = 0; c < 8; c++) {
        cp_wait0();
        __syncthreads();
        if (c + 1 < 8) { PREFS((c + 1) * 128, (c + 1) & 1); cp_commit(); }

        const uint32_t bb = smb + (SOFF + (c & 1) * STBUF2) * 4;
        float4 sc[4];
        #pragma unroll
        for (int nf = 0; nf < 4; nf++) sc[nf] = make_float4(0.f, 0.f, 0.f, 0.f);

        #pragma unroll
        for (int s = 0; s < 4; s++) {
            #pragma unroll
            for (int p = 0; p < 2; p++) {
                uint32_t boffb = ((nw * 32 + p * 16 + br) * 36 + bk) * 4;
                uint32_t bh[4], bl[4];
                ldsm4(bh, bb + boffb + s*32);
                ldsm4(bl, bb + 4608*4 + boffb + s*32);
                mma_x3(sc[2*p],   qh[s], ql[s], bh[0], bh[1], bl[0], bl[1]);
                mma_x3(sc[2*p+1], qh[s], ql[s], bh[2], bh[3], bl[2], bl[3]);
            }
        }

        // per-(row, chunk, quarter) max over this warp's 32 cols
        float m0 = -1e30f, m1 = -1e30f;
        #pragma unroll
        for (int nf = 0; nf < 4; nf++) {
            m0 = fmaxf(m0, fmaxf(sc[nf].x, sc[nf].y));
            m1 = fmaxf(m1, fmaxf(sc[nf].z, sc[nf].w));
        }
        m0 = fmaxf(m0, __shfl_xor_sync(0xffffffffu, m0, 1));
        m0 = fmaxf(m0, __shfl_xor_sync(0xffffffffu, m0, 2));
        m1 = fmaxf(m1, __shfl_xor_sync(0xffffffffu, m1, 1));
        m1 = fmaxf(m1, __shfl_xor_sync(0xffffffffu, m1, 2));
        if (tg == 0) {
            ((float*)sma)[MC_OFF + (rows0 + g_) * 32 + c*4 + nw]     = m0;
            ((float*)sma)[MC_OFF + (rows0 + 8 + g_) * 32 + c*4 + nw] = m1;
        }
        #pragma unroll
        for (int nf = 0; nf < 4; nf++) {
            int pairidx = c*64 + nw*16 + nf*4 + tg;
            float4 v = sc[nf];
            sma[(rows0 + g_) * PSTR + pairidx]     = pack2h(__expf(v.x - m0), __expf(v.y - m0));
            sma[(rows0 + 8 + g_) * PSTR + pairidx] = pack2h(__expf(v.z - m1), __expf(v.w - m1));
        }
    }
    #undef PREFS

    // prefetch first PV g-chunk; flies during rescale
    #define PREFG(kb_, buf_) do {                                              \
        int gr = t >> 1; int gh = (t & 1) * 16;                                \
        size_t src = ((size_t)b * 256 + gr) * 512 + ((kb_) >> 1) + gh;         \
        uint32_t d = smb + (SOFF + (buf_) * STBUF2 + gr * 36 + gh) * 4;        \
        cp16(d,      gT_f + src);      cp16(d + 16, gT_f + src + 4);           \
        cp16(d + 32, gT_f + src + 8);  cp16(d + 48, gT_f + src + 12);          \
    } while (0)
    PREFG(0, 0);
    cp_commit();
    __syncthreads();   // P + m_c visible

    // ---- rescale: P *= exp(m_cq - m_final); row sums -> inv ----
    {
        int r = t >> 3, l8 = t & 7;
        const float* mc = (const float*)sma + MC_OFF + r * 32;
        float mf = -1e30f;
        #pragma unroll
        for (int i = 0; i < 32; i++) mf = fmaxf(mf, mc[i]);
        float sum = 0.f;
        #pragma unroll
        for (int grp = 0; grp < 32; grp++) {       // (chunk c = grp>>2, quarter = grp&3)
            float f = __expf(mc[grp] - mf);
            int j = grp * 16 + l8;
            #pragma unroll
            for (int rep = 0; rep < 2; rep++, j += 8) {
                uint32_t u = sma[r * PSTR + j];
                __half2 h = *(__half2*)&u;
                float f0 = __half2float(h.x) * f;
                float f1 = __half2float(h.y) * f;
                sum += f0 + f1;
                sma[r * PSTR + j] = pack2h(f0, f1);
            }
        }
        sum += __shfl_xor_sync(0xffffffffu, sum, 1);
        sum += __shfl_xor_sync(0xffffffffu, sum, 2);
        sum += __shfl_xor_sync(0xffffffffu, sum, 4);
        if (l8 == 0) ((float*)sma)[INV_OFF + r] = 1.0f / sum;
    }
    __syncthreads();

    // ---- PV (fp16 x1): out[64][256], warp tile 16 x 64 ----
    const int wn2 = nw * 64;
    float4 oc[8];
    #pragma unroll
    for (int nf = 0; nf < 8; nf++) oc[nf] = make_float4(0.f, 0.f, 0.f, 0.f);

    for (int ki = 0; ki < 16; ki++) {
        cp_wait0();
        __syncthreads();
        if (ki + 1 < 16) { PREFG((ki + 1) * 64, (ki + 1) & 1); cp_commit(); }

        const uint32_t bb = smb + (SOFF + (ki & 1) * STBUF2) * 4;
        #pragma unroll
        for (int s = 0; s < 4; s++) {
            int kp = ki * 32 + s * 8;
            uint32_t a0 = sma[(rows0 + g_) * PSTR + kp + tg];
            uint32_t a1 = sma[(rows0 + 8 + g_) * PSTR + kp + tg];
            uint32_t a2 = sma[(rows0 + g_) * PSTR + kp + tg + 4];
            uint32_t a3 = sma[(rows0 + 8 + g_) * PSTR + kp + tg + 4];
            #pragma unroll
            for (int p = 0; p < 4; p++) {
                uint32_t boffg = ((wn2 + p * 16 + br) * 36 + bk) * 4;
                uint32_t bg[4];
                ldsm4(bg, bb + boffg + s*32);
                mma_f16(oc[2*p],   a0, a1, a2, a3, bg[0], bg[1]);
                mma_f16(oc[2*p+1], a0, a1, a2, a3, bg[2], bg[3]);
            }
        }
    }
    #undef PREFG

    const float i0 = ((const float*)sma)[INV_OFF + rows0 + g_];
    const float i1 = ((const float*)sma)[INV_OFF + rows0 + 8 + g_];
    #pragma unroll
    for (int nf = 0; nf < 8; nf++) {
        int colp = wn2 / 2 + nf * 4 + tg;
        size_t r0 = ((size_t)b * LOC + n0 + rows0 + g_) * 128 + colp;
        size_t r1 = ((size_t)b * LOC + n0 + rows0 + 8 + g_) * 128 + colp;
        ag_f[r0] = pack2h(oc[nf].x * i0, oc[nf].y * i0);
        ag_f[r1] = pack2h(oc[nf].z * i1, oc[nf].w * i1);
    }
}

// ---------------------------------------------------------------------------
// kernel_launch
// ---------------------------------------------------------------------------
extern "C" void kernel_launch(void* const* d_in, const int* in_sizes, int n_in,
                              void* d_out, int out_size)
{
    const float* x       = (const float*)d_in[0];
    const float* k_theta = (const float*)d_in[1];
    const float* u_theta = (const float*)d_in[2];
    const float* k_phi   = (const float*)d_in[3];
    const float* u_phi   = (const float*)d_in[4];
    const float* k_g     = (const float*)d_in[5];
    const float* u_g     = (const float*)d_in[6];
    const float* k_attn  = (const float*)d_in[7];
    const float* u_attn  = (const float*)d_in[8];
    const float* sigma   = (const float*)d_in[9];
    float* out = (float*)d_out;

    uint32_t *xh, *xl, *wtpTh, *wtpTl, *wgTf, *waTf;
    uint32_t *thh, *thl, *phh, *phl, *gTf, *agf;
    cudaGetSymbolAddress((void**)&xh,    d_xh);
    cudaGetSymbolAddress((void**)&xl,    d_xl);
    cudaGetSymbolAddress((void**)&wtpTh, d_wtpTh);
    cudaGetSymbolAddress((void**)&wtpTl, d_wtpTl);
    cudaGetSymbolAddress((void**)&wgTf,  d_wgTf);
    cudaGetSymbolAddress((void**)&waTf,  d_waTf);
    cudaGetSymbolAddress((void**)&thh,   d_thh);
    cudaGetSymbolAddress((void**)&thl,   d_thl);
    cudaGetSymbolAddress((void**)&phh,   d_phh);
    cudaGetSymbolAddress((void**)&phl,   d_phl);
    cudaGetSymbolAddress((void**)&gTf,   d_gTf);
    cudaGetSymbolAddress((void**)&agf,   d_agf);

    cudaFuncSetAttribute(gemm_x3,  cudaFuncAttributeMaxDynamicSharedMemorySize, GEMM_SMEM);
    cudaFuncSetAttribute(gemm1<1>, cudaFuncAttributeMaxDynamicSharedMemorySize, GEMM1_SMEM);
    cudaFuncSetAttribute(gemm1<2>, cudaFuncAttributeMaxDynamicSharedMemorySize, GEMM1_SMEM);
    cudaFuncSetAttribute(attn4,    cudaFuncAttributeMaxDynamicSharedMemorySize, ATTN_SMEM);

    prep_w<<<640, 256>>>(k_theta, k_phi, k_g, k_attn, wtpTh, wtpTl, wgTf, waTf);
    prep_x<<<16384, 256>>>(x, xh, xl);
    spectral4_kernel<<<4, 256>>>(k_theta, u_theta, k_phi, u_phi,
                                 k_g, u_g, k_attn, u_attn);
    gemm_x3<<<dim3(1, MTOT / 128), 256, GEMM_SMEM>>>(
        xh, xl, wtpTh, wtpTl, thh, thl, phh, phl, 256);
    gemm1<1><<<dim3(4, MTOT / 128), 256, GEMM1_SMEM>>>(
        xh, wgTf, nullptr, gTf, nullptr, nullptr, 256, 256);
    attn4<<<dim3(LOC / 64, B_), 512, ATTN_SMEM>>>(thh, thl, phh, phl, gTf, agf);
    gemm1<2><<<dim3(8, MTOT / 128), 256, GEMM1_SMEM>>>(
        agf, waTf, out, nullptr, x, sigma, 512, 128);
}

// round 12
// speedup vs baseline: 6.1499x; 1.0547x over previous
#include <cuda_runtime.h>
#include <cuda_fp16.h>
#include <math.h>
#include <stdint.h>

#define B_   16
#define CC   512
#define C8   64
#define C2   256
#define LOC  4096
#define DOWN 1024
#define MTOT 65536

// ---------------------------------------------------------------------------
// Device scratch: unified fp16 planes (packed half2 u32, pairs along k)
// ---------------------------------------------------------------------------
__device__ float d_invs[4];
__device__ uint32_t d_xh   [MTOT * 256];
__device__ uint32_t d_xl   [MTOT * 256];
__device__ uint32_t d_wtpTh[128 * 256];
__device__ uint32_t d_wtpTl[128 * 256];
__device__ uint32_t d_wgTf [256 * 256];
__device__ uint32_t d_waTf [512 * 128];
__device__ uint32_t d_thh  [MTOT * 32];
__device__ uint32_t d_thl  [MTOT * 32];
__device__ uint32_t d_phh  [B_ * DOWN * 32];
__device__ uint32_t d_phl  [B_ * DOWN * 32];
__device__ uint32_t d_gTf  [B_ * C2 * 512];
__device__ uint32_t d_agf  [MTOT * 128];

// ---------------------------------------------------------------------------
// helpers
// ---------------------------------------------------------------------------
__device__ __forceinline__ uint32_t pack2h(float a, float b) {
    __half2 h = __floats2half2_rn(a, b);
    return *(uint32_t*)&h;
}
__device__ __forceinline__ void split2h(float a, float b, uint32_t& hi, uint32_t& lo) {
    float ha = __half2float(__float2half_rn(a));
    float hb = __half2float(__float2half_rn(b));
    hi = pack2h(ha, hb);
    lo = pack2h(a - ha, b - hb);
}
__device__ __forceinline__ void mma_f16(float4& d,
    uint32_t a0, uint32_t a1, uint32_t a2, uint32_t a3, uint32_t b0, uint32_t b1)
{
    asm volatile("mma.sync.aligned.m16n8k16.row.col.f32.f16.f16.f32 "
        "{%0,%1,%2,%3}, {%4,%5,%6,%7}, {%8,%9}, {%0,%1,%2,%3};"
        : "+f"(d.x), "+f"(d.y), "+f"(d.z), "+f"(d.w)
        : "r"(a0), "r"(a1), "r"(a2), "r"(a3), "r"(b0), "r"(b1));
}
__device__ __forceinline__ void mma_x3(float4& d,
    const uint32_t ah[4], const uint32_t al[4],
    uint32_t bh0, uint32_t bh1, uint32_t bl0, uint32_t bl1)
{
    mma_f16(d, ah[0], ah[1], ah[2], ah[3], bh0, bh1);
    mma_f16(d, ah[0], ah[1], ah[2], ah[3], bl0, bl1);
    mma_f16(d, al[0], al[1], al[2], al[3], bh0, bh1);
}
__device__ __forceinline__ void ldsm4(uint32_t r[4], uint32_t addr) {
    asm volatile("ldmatrix.sync.aligned.m8n8.x4.shared.b16 {%0,%1,%2,%3}, [%4];"
        : "=r"(r[0]), "=r"(r[1]), "=r"(r[2]), "=r"(r[3]) : "r"(addr));
}
__device__ __forceinline__ void cp16(uint32_t dst_saddr, const uint32_t* src) {
    asm volatile("cp.async.cg.shared.global [%0], [%1], 16;\n" :: "r"(dst_saddr), "l"(src));
}
__device__ __forceinline__ void cp_commit() {
    asm volatile("cp.async.commit_group;\n" ::: "memory");
}
__device__ __forceinline__ void cp_wait0() {
    asm volatile("cp.async.wait_group 0;\n" ::: "memory");
}
__device__ __forceinline__ void cp_wait1() {
    asm volatile("cp.async.wait_group 1;\n" ::: "memory");
}

// ---------------------------------------------------------------------------
// prep_all: blocks 0-3 spectral norms, 4-643 weight transpose/split,
// 644+ x split. All independent; merged to overlap on the SMs.
// ---------------------------------------------------------------------------
__global__ void prep_all(const float* __restrict__ x,
                         const float* __restrict__ kt, const float* __restrict__ ut,
                         const float* __restrict__ kp, const float* __restrict__ up,
                         const float* __restrict__ kg, const float* __restrict__ ug,
                         const float* __restrict__ ka, const float* __restrict__ ua,
                         uint32_t* __restrict__ xh,  uint32_t* __restrict__ xl,
                         uint32_t* __restrict__ tpTh, uint32_t* __restrict__ tpTl,
                         uint32_t* __restrict__ gTf,  uint32_t* __restrict__ aTf)
{
    __shared__ float us[512];
    __shared__ float v[512];
    __shared__ float red[256];
    const int t = threadIdx.x;
    const int blk = blockIdx.x;

    if (blk >= 644) {
        // ---- x split ----
        size_t idx = (size_t)(blk - 644) * 256 + t;
        const float4* p = (const float4*)(x + idx * 8);
        float4 v0 = p[0], v1 = p[1];
        uint32_t h0,l0,h1,l1,h2,l2,h3,l3;
        split2h(v0.x, v0.y, h0, l0); split2h(v0.z, v0.w, h1, l1);
        split2h(v1.x, v1.y, h2, l2); split2h(v1.z, v1.w, h3, l3);
        *(uint4*)&xh[idx * 4] = make_uint4(h0, h1, h2, h3);
        *(uint4*)&xl[idx * 4] = make_uint4(l0, l1, l2, l3);
        return;
    }
    if (blk >= 4) {
        // ---- weight transpose + split ----
        int i = (blk - 4) * 256 + t;
        if (i < 32768) {
            int n = i >> 8, j = i & 255;
            float a, b;
            if (n < 64) { a = kt[(2*j)*64 + n];      b = kt[(2*j+1)*64 + n]; }
            else        { a = kp[(2*j)*64 + n - 64]; b = kp[(2*j+1)*64 + n - 64]; }
            uint32_t h, l; split2h(a, b, h, l);
            tpTh[i] = h; tpTl[i] = l;
        } else if (i < 98304) {
            int i2 = i - 32768; int n = i2 >> 8, j = i2 & 255;
            gTf[i2] = pack2h(kg[(2*j)*256 + n], kg[(2*j+1)*256 + n]);
        } else if (i < 163840) {
            int i2 = i - 98304; int n = i2 >> 7, j = i2 & 127;
            aTf[i2] = pack2h(ka[(2*j)*512 + n], ka[(2*j+1)*512 + n]);
        }
        return;
    }

    // ---- spectral norm (blocks 0..3) ----
    const float* W; const float* u; int Cin, Cout;
    switch (blk) {
        case 0:  W = kt; u = ut; Cin = 512; Cout = 64;  break;
        case 1:  W = kp; u = up; Cin = 512; Cout = 64;  break;
        case 2:  W = kg; u = ug; Cin = 512; Cout = 256; break;
        default: W = ka; u = ua; Cin = 256; Cout = 512; break;
    }
    for (int j = t; j < Cout; j += 256) us[j] = u[j];
    __syncthreads();
    for (int i = t; i < Cin; i += 256) {
        const float4* wr = (const float4*)(W + (size_t)i * Cout);
        float s = 0.f;
        for (int j = 0; j < Cout / 4; j++) {
            float4 w4 = wr[j];
            s += us[4*j]*w4.x + us[4*j+1]*w4.y + us[4*j+2]*w4.z + us[4*j+3]*w4.w;
        }
        v[i] = s;
    }
    __syncthreads();
    float ss = 0.f;
    for (int i = t; i < Cin; i += 256) ss += v[i] * v[i];
    red[t] = ss; __syncthreads();
    for (int o = 128; o; o >>= 1) { if (t < o) red[t] += red[t + o]; __syncthreads(); }
    float inv_vn = 1.0f / (sqrtf(red[0]) + 1e-12f);
    __syncthreads();
    float rr = 0.f;
    for (int j = t; j < Cout; j += 256) {
        float s = 0.f;
        for (int i = 0; i < Cin; i++) s += v[i] * W[(size_t)i * Cout + j];
        s *= inv_vn;
        rr += s * s;
    }
    red[t] = rr; __syncthreads();
    for (int o = 128; o; o >>= 1) { if (t < o) red[t] += red[t + o]; __syncthreads(); }
    if (t == 0) {
        float rn = red[0];
        d_invs[blk] = (sqrtf(rn) + 1e-12f) / rn;
    }
}

// ---------------------------------------------------------------------------
// fp16 x3 GEMM (theta/phi conv): unchanged from round 11
// ---------------------------------------------------------------------------
#define PLANE 2560
#define GEMM_SMEM (8 * PLANE * 4)

__global__ __launch_bounds__(256, 2)
void gemm_x3(const uint32_t* __restrict__ Ah, const uint32_t* __restrict__ Al,
             const uint32_t* __restrict__ Bh, const uint32_t* __restrict__ Bl,
             uint32_t* __restrict__ oph, uint32_t* __restrict__ opl,
             uint32_t* __restrict__ phh, uint32_t* __restrict__ phl, int KP)
{
    extern __shared__ uint32_t smg[];
    const uint32_t smb = (uint32_t)__cvta_generic_to_shared(smg);

    const int bm = blockIdx.y * 128;
    const int t = threadIdx.x;
    const int warp = t >> 5, lane = t & 31, g = lane >> 2, tg = lane & 3;
    const int wm = (warp >> 1) * 32, wn = (warp & 1) * 64;

    const int ar = (lane & 7) + ((lane >> 3) & 1) * 8;
    const int ak = (lane >> 4) * 4;
    const int br = (lane & 7) + (lane >> 4) * 8;
    const int bk = ((lane >> 3) & 1) * 4;
    uint32_t aoff[2], boff[4];
    #pragma unroll
    for (int mf = 0; mf < 2; mf++) aoff[mf] = ((wm + mf*16 + ar) * 20 + ak) * 4;
    #pragma unroll
    for (int p = 0; p < 4; p++)    boff[p]  = ((wn + p*16 + br) * 20 + bk) * 4;

    const int rs = t >> 1;
    const int hf = (t & 1) * 8;
    const int sidx = rs * 20 + hf;
    const uint32_t* pAh = Ah + (size_t)(bm + rs) * KP + hf;
    const uint32_t* pAl = Al + (size_t)(bm + rs) * KP + hf;
    const uint32_t* pBh = Bh + (size_t)rs * KP + hf;
    const uint32_t* pBl = Bl + (size_t)rs * KP + hf;

    float4 acc[2][8];
    #pragma unroll
    for (int i = 0; i < 2; i++)
        #pragma unroll
        for (int j = 0; j < 8; j++) acc[i][j] = make_float4(0.f, 0.f, 0.f, 0.f);

    const int nt = KP / 16;

    #define PREF(kt_, buf_) do {                                       \
        size_t off = (size_t)(kt_) * 16;                                \
        uint32_t d0 = smb + ((buf_) * 4 * PLANE + sidx) * 4;            \
        cp16(d0,              pAh + off); cp16(d0 + 16,             pAh + off + 4); \
        cp16(d0 + PLANE*4,    pAl + off); cp16(d0 + PLANE*4 + 16,   pAl + off + 4); \
        cp16(d0 + 2*PLANE*4,  pBh + off); cp16(d0 + 2*PLANE*4 + 16, pBh + off + 4); \
        cp16(d0 + 3*PLANE*4,  pBl + off); cp16(d0 + 3*PLANE*4 + 16, pBl + off + 4); \
    } while (0)

    PREF(0, 0);
    cp_commit();

    for (int kt = 0; kt < nt; kt++) {
        cp_wait0();
        __syncthreads();
        if (kt + 1 < nt) { PREF(kt + 1, (kt + 1) & 1); cp_commit(); }

        const uint32_t base = smb + ((kt & 1) * 4 * PLANE) * 4;
        #pragma unroll
        for (int s = 0; s < 2; s++) {
            uint32_t ah0[4], ah1[4], al0[4], al1[4];
            ldsm4(ah0, base + aoff[0] + s*32);
            ldsm4(ah1, base + aoff[1] + s*32);
            ldsm4(al0, base + PLANE*4 + aoff[0] + s*32);
            ldsm4(al1, base + PLANE*4 + aoff[1] + s*32);
            #pragma unroll
            for (int p = 0; p < 4; p++) {
                uint32_t bh[4], bl[4];
                ldsm4(bh, base + 2*PLANE*4 + boff[p] + s*32);
                ldsm4(bl, base + 3*PLANE*4 + boff[p] + s*32);
                mma_x3(acc[0][2*p],   ah0, al0, bh[0], bh[1], bl[0], bl[1]);
                mma_x3(acc[0][2*p+1], ah0, al0, bh[2], bh[3], bl[2], bl[3]);
                mma_x3(acc[1][2*p],   ah1, al1, bh[0], bh[1], bl[0], bl[1]);
                mma_x3(acc[1][2*p+1], ah1, al1, bh[2], bh[3], bl[2], bl[3]);
            }
        }
    }
    #undef PREF
    __syncthreads();

    const float s0 = d_invs[0], s1 = d_invs[1];
    float* smf = (float*)smg;

    #pragma unroll
    for (int mf = 0; mf < 2; mf++) {
        int rl = wm + mf * 16 + g;
        int row = bm + rl;
        #pragma unroll
        for (int nf = 0; nf < 8; nf++) {
            int coln = wn + nf * 8 + 2 * tg;
            float4 c = acc[mf][nf];
            if (coln < 64) {
                int colp = nf * 4 + tg;
                uint32_t h0, l0, h1, l1;
                split2h(c.x * s0, c.y * s0, h0, l0);
                split2h(c.z * s0, c.w * s0, h1, l1);
                oph[(size_t)row * 32 + colp]       = h0;
                opl[(size_t)row * 32 + colp]       = l0;
                oph[(size_t)(row + 8) * 32 + colp] = h1;
                opl[(size_t)(row + 8) * 32 + colp] = l1;
            } else {
                int col = coln - 64;
                smf[rl * 68 + col]           = c.x * s1;
                smf[rl * 68 + col + 1]       = c.y * s1;
                smf[(rl + 8) * 68 + col]     = c.z * s1;
                smf[(rl + 8) * 68 + col + 1] = c.w * s1;
            }
        }
    }
    __syncthreads();

    {
        int b  = blockIdx.y >> 5;
        int h2 = blockIdx.y & 31;
        #pragma unroll
        for (int i = 0; i < 4; i++) {
            int idx = t * 4 + i;
            int w2 = idx >> 5, cp = idx & 31;
            int c0 = cp * 2;
            int r0 = 2 * w2;
            float a0 = fmaxf(fmaxf(smf[r0*68 + c0],      smf[(r0+1)*68 + c0]),
                             fmaxf(smf[(r0+64)*68 + c0], smf[(r0+65)*68 + c0]));
            float a1 = fmaxf(fmaxf(smf[r0*68 + c0+1],      smf[(r0+1)*68 + c0+1]),
                             fmaxf(smf[(r0+64)*68 + c0+1], smf[(r0+65)*68 + c0+1]));
            uint32_t h, l; split2h(a0, a1, h, l);
            size_t o = ((size_t)b * 1024 + h2 * 32 + w2) * 32 + cp;
            phh[o] = h; phl[o] = l;
        }
    }
}

// ---------------------------------------------------------------------------
// fp16 x1 GEMM v2: 128x128 tile, 8 warps (4m x 2n), warp 32x64, 3-stage.
// MODE 1: g conv -> fused 2x2 pool -> transposed fp16 gTf
// MODE 2: residual: of = X + sigma*invs[3]*acc
// ---------------------------------------------------------------------------
#define G1BUF 5120                       // A 128*20 + B 128*20
#define GEMM1_SMEM 69632                 // max(3*G1BUF*4, 128*132*4 pool tile)

template<int MODE>
__global__ __launch_bounds__(256, 2)
void gemm1(const uint32_t* __restrict__ Ah, const uint32_t* __restrict__ Bh,
           float* __restrict__ of, uint32_t* __restrict__ gTf,
           const float* __restrict__ X, const float* __restrict__ sigma_ptr,
           int N, int KP)
{
    extern __shared__ uint32_t smg[];
    const uint32_t smb = (uint32_t)__cvta_generic_to_shared(smg);

    const int bm = blockIdx.y * 128;
    const int bn = blockIdx.x * 128;
    const int t = threadIdx.x;
    const int warp = t >> 5, lane = t & 31, g = lane >> 2, tg = lane & 3;
    const int wm = (warp >> 1) * 32, wn = (warp & 1) * 64;

    const int ar = (lane & 7) + ((lane >> 3) & 1) * 8;
    const int ak = (lane >> 4) * 4;
    const int br = (lane & 7) + (lane >> 4) * 8;
    const int bk = ((lane >> 3) & 1) * 4;
    uint32_t aoff[2], boff[4];
    #pragma unroll
    for (int mf = 0; mf < 2; mf++) aoff[mf] = ((wm + mf*16 + ar) * 20 + ak) * 4;
    #pragma unroll
    for (int p = 0; p < 4; p++)    boff[p]  = ((2560 + (wn + p*16 + br) * 20 + bk)) * 4;

    const int rs = t >> 1, hf = (t & 1) * 8;
    const uint32_t* pA = Ah + (size_t)(bm + rs) * KP + hf;
    const uint32_t* pB = Bh + (size_t)(bn + rs) * KP + hf;
    const uint32_t sA = (rs * 20 + hf) * 4;
    const uint32_t sB = (2560 + rs * 20 + hf) * 4;

    float4 acc[2][8];
    #pragma unroll
    for (int i = 0; i < 2; i++)
        #pragma unroll
        for (int j = 0; j < 8; j++) acc[i][j] = make_float4(0.f, 0.f, 0.f, 0.f);

    const int nt = KP / 16;

    #define PREF1(kt_, buf_) do {                                   \
        size_t off = (size_t)(kt_) * 16;                             \
        uint32_t da = smb + (buf_) * G1BUF * 4 + sA;                 \
        cp16(da, pA + off); cp16(da + 16, pA + off + 4);             \
        uint32_t db = smb + (buf_) * G1BUF * 4 + sB;                 \
        cp16(db, pB + off); cp16(db + 16, pB + off + 4);             \
    } while (0)

    PREF1(0, 0); cp_commit();
    PREF1(1, 1); cp_commit();

    for (int kt = 0; kt < nt; kt++) {
        if (kt == nt - 1) cp_wait0(); else cp_wait1();
        __syncthreads();
        if (kt + 2 < nt) { PREF1(kt + 2, (kt + 2) % 3); cp_commit(); }

        const uint32_t base = smb + ((kt % 3) * G1BUF) * 4;
        #pragma unroll
        for (int s = 0; s < 2; s++) {
            uint32_t a0[4], a1[4];
            ldsm4(a0, base + aoff[0] + s*32);
            ldsm4(a1, base + aoff[1] + s*32);
            #pragma unroll
            for (int p = 0; p < 4; p++) {
                uint32_t bf[4];
                ldsm4(bf, base + boff[p] + s*32);
                mma_f16(acc[0][2*p],   a0[0], a0[1], a0[2], a0[3], bf[0], bf[1]);
                mma_f16(acc[0][2*p+1], a0[0], a0[1], a0[2], a0[3], bf[2], bf[3]);
                mma_f16(acc[1][2*p],   a1[0], a1[1], a1[2], a1[3], bf[0], bf[1]);
                mma_f16(acc[1][2*p+1], a1[0], a1[1], a1[2], a1[3], bf[2], bf[3]);
            }
        }
    }
    #undef PREF1

    const float s0 = (MODE == 1) ? d_invs[2] : d_invs[3] * __ldg(sigma_ptr);

    if (MODE == 1) {
        // scaled fp32 tile [128 x 128] into smem (stride 132), fused pool
        __syncthreads();
        float* smf = (float*)smg;
        #pragma unroll
        for (int mf = 0; mf < 2; mf++) {
            int rl = wm + mf * 16 + g;
            #pragma unroll
            for (int nf = 0; nf < 8; nf++) {
                int col = wn + nf * 8 + 2 * tg;
                float4 c = acc[mf][nf];
                smf[rl * 132 + col]           = c.x * s0;
                smf[rl * 132 + col + 1]       = c.y * s0;
                smf[(rl + 8) * 132 + col]     = c.z * s0;
                smf[(rl + 8) * 132 + col + 1] = c.w * s0;
            }
        }
        __syncthreads();
        int b  = blockIdx.y >> 5;
        int h2 = blockIdx.y & 31;
        #pragma unroll
        for (int i = 0; i < 8; i++) {
            int idx = t * 8 + i;               // 0..2047
            int c = idx >> 4, w2p = idx & 15;
            int r0 = 4 * w2p;
            float p0 = fmaxf(fmaxf(smf[r0*132 + c],      smf[(r0+1)*132 + c]),
                             fmaxf(smf[(r0+64)*132 + c], smf[(r0+65)*132 + c]));
            float p1 = fmaxf(fmaxf(smf[(r0+2)*132 + c],  smf[(r0+3)*132 + c]),
                             fmaxf(smf[(r0+66)*132 + c], smf[(r0+67)*132 + c]));
            gTf[((size_t)b * 256 + bn + c) * 512 + h2 * 16 + w2p] = pack2h(p0, p1);
        }
    } else {
        #pragma unroll
        for (int mf = 0; mf < 2; mf++) {
            int row = bm + wm + mf * 16 + g;
            #pragma unroll
            for (int nf = 0; nf < 8; nf++) {
                int col = bn + wn + nf * 8 + 2 * tg;
                float4 c = acc[mf][nf];
                size_t i0 = (size_t)row * N + col;
                size_t i1 = (size_t)(row + 8) * N + col;
                float2 x0 = *(const float2*)&X[i0];
                float2 x1 = *(const float2*)&X[i1];
                *(float2*)&of[i0] = make_float2(x0.x + s0 * c.x, x0.y + s0 * c.y);
                *(float2*)&of[i1] = make_float2(x1.x + s0 * c.z, x1.y + s0 * c.w);
            }
        }
    }
}

// ---------------------------------------------------------------------------
// attn4: 512 threads, 64 q-rows/block; PV P-fragments via ldmatrix
// ---------------------------------------------------------------------------
#define PSTR 516
#define MC_OFF  (64 * PSTR)
#define INV_OFF (MC_OFF + 2048)
#define SOFF    (INV_OFF + 64)
#define STBUF2  9216
#define ATTN_SMEM ((SOFF + 2 * STBUF2) * 4)

__global__ __launch_bounds__(512)
void attn4(const uint32_t* __restrict__ th_h, const uint32_t* __restrict__ th_l,
           const uint32_t* __restrict__ ph_h, const uint32_t* __restrict__ ph_l,
           const uint32_t* __restrict__ gT_f,
           uint32_t* __restrict__ ag_f)
{
    extern __shared__ uint32_t sma[];
    const uint32_t smb = (uint32_t)__cvta_generic_to_shared(sma);

    const int b  = blockIdx.y;
    const int n0 = blockIdx.x * 64;
    const int t  = threadIdx.x;
    const int warp = t >> 5, lane = t & 31;
    const int g_ = lane >> 2, tg = lane & 3;
    const int mw = warp >> 2;
    const int nw = warp & 3;
    const int rows0 = mw * 16;

    const int ar = (lane & 7) + ((lane >> 3) & 1) * 8;
    const int ak = (lane >> 4) * 4;
    const int br = (lane & 7) + (lane >> 4) * 8;
    const int bk = ((lane >> 3) & 1) * 4;

    {
        int row = t >> 3, off = (t & 7) * 4;
        size_t src = ((size_t)b * LOC + n0 + row) * 32 + off;
        *(uint4*)&sma[SOFF + row * 36 + off]        = *(const uint4*)&th_h[src];
        *(uint4*)&sma[SOFF + 2304 + row * 36 + off] = *(const uint4*)&th_l[src];
    }
    __syncthreads();
    uint32_t qh[4][4], ql[4][4];
    {
        uint32_t qoff = smb + (SOFF + (rows0 + ar) * 36 + ak) * 4;
        #pragma unroll
        for (int s = 0; s < 4; s++) ldsm4(qh[s], qoff + s*32);
        #pragma unroll
        for (int s = 0; s < 4; s++) ldsm4(ql[s], qoff + 2304*4 + s*32);
    }
    __syncthreads();

    const int srow = t >> 2, shalf = (t & 3) * 8;
    #define PREFS(mb_, buf_) do {                                              \
        size_t src = ((size_t)b * DOWN + (mb_) + srow) * 32 + shalf;           \
        uint32_t d = smb + (SOFF + (buf_) * STBUF2 + srow * 36 + shalf) * 4;   \
        cp16(d,      ph_h + src);      cp16(d + 16, ph_h + src + 4);           \
        uint32_t dl = d + 4608 * 4;                                            \
        cp16(dl,     ph_l + src);      cp16(dl + 16, ph_l + src + 4);          \
    } while (0)

    PREFS(0, 0);
    cp_commit();

    for (int c = 0; c < 8; c++) {
        cp_wait0();
        __syncthreads();
        if (c + 1 < 8) { PREFS((c + 1) * 128, (c + 1) & 1); cp_commit(); }

        const uint32_t bb = smb + (SOFF + (c & 1) * STBUF2) * 4;
        float4 sc[4];
        #pragma unroll
        for (int nf = 0; nf < 4; nf++) sc[nf] = make_float4(0.f, 0.f, 0.f, 0.f);

        #pragma unroll
        for (int s = 0; s < 4; s++) {
            #pragma unroll
            for (int p = 0; p < 2; p++) {
                uint32_t boffb = ((nw * 32 + p * 16 + br) * 36 + bk) * 4;
                uint32_t bh[4], bl[4];
                ldsm4(bh, bb + boffb + s*32);
                ldsm4(bl, bb + 4608*4 + boffb + s*32);
                mma_x3(sc[2*p],   qh[s], ql[s], bh[0], bh[1], bl[0], bl[1]);
                mma_x3(sc[2*p+1], qh[s], ql[s], bh[2], bh[3], bl[2], bl[3]);
            }
        }

        float m0 = -1e30f, m1 = -1e30f;
        #pragma unroll
        for (int nf = 0; nf < 4; nf++) {
            m0 = fmaxf(m0, fmaxf(sc[nf].x, sc[nf].y));
            m1 = fmaxf(m1, fmaxf(sc[nf].z, sc[nf].w));
        }
        m0 = fmaxf(m0, __shfl_xor_sync(0xffffffffu, m0, 1));
        m0 = fmaxf(m0, __shfl_xor_sync(0xffffffffu, m0, 2));
        m1 = fmaxf(m1, __shfl_xor_sync(0xffffffffu, m1, 1));
        m1 = fmaxf(m1, __shfl_xor_sync(0xffffffffu, m1, 2));
        if (tg == 0) {
            ((float*)sma)[MC_OFF + (rows0 + g_) * 32 + c*4 + nw]     = m0;
            ((float*)sma)[MC_OFF + (rows0 + 8 + g_) * 32 + c*4 + nw] = m1;
        }
        #pragma unroll
        for (int nf = 0; nf < 4; nf++) {
            int pairidx = c*64 + nw*16 + nf*4 + tg;
            float4 v = sc[nf];
            sma[(rows0 + g_) * PSTR + pairidx]     = pack2h(__expf(v.x - m0), __expf(v.y - m0));
            sma[(rows0 + 8 + g_) * PSTR + pairidx] = pack2h(__expf(v.z - m1), __expf(v.w - m1));
        }
    }
    #undef PREFS

    #define PREFG(kb_, buf_) do {                                              \
        int gr = t >> 1; int gh = (t & 1) * 16;                                \
        size_t src = ((size_t)b * 256 + gr) * 512 + ((kb_) >> 1) + gh;         \
        uint32_t d = smb + (SOFF + (buf_) * STBUF2 + gr * 36 + gh) * 4;        \
        cp16(d,      gT_f + src);      cp16(d + 16, gT_f + src + 4);           \
        cp16(d + 32, gT_f + src + 8);  cp16(d + 48, gT_f + src + 12);          \
    } while (0)
    PREFG(0, 0);
    cp_commit();
    __syncthreads();

    {
        int r = t >> 3, l8 = t & 7;
        const float* mc = (const float*)sma + MC_OFF + r * 32;
        float mf = -1e30f;
        #pragma unroll
        for (int i = 0; i < 32; i++) mf = fmaxf(mf, mc[i]);
        float sum = 0.f;
        #pragma unroll
        for (int grp = 0; grp < 32; grp++) {
            float f = __expf(mc[grp] - mf);
            int j = grp * 16 + l8;
            #pragma unroll
            for (int rep = 0; rep < 2; rep++, j += 8) {
                uint32_t u = sma[r * PSTR + j];
                __half2 h = *(__half2*)&u;
                float f0 = __half2float(h.x) * f;
                float f1 = __half2float(h.y) * f;
                sum += f0 + f1;
                sma[r * PSTR + j] = pack2h(f0, f1);
            }
        }
        sum += __shfl_xor_sync(0xffffffffu, sum, 1);
        sum += __shfl_xor_sync(0xffffffffu, sum, 2);
        sum += __shfl_xor_sync(0xffffffffu, sum, 4);
        if (l8 == 0) ((float*)sma)[INV_OFF + r] = 1.0f / sum;
    }
    __syncthreads();

    // ---- PV (fp16 x1): out[64][256], warp tile 16 x 64; P frags via ldsm ----
    const int wn2 = nw * 64;
    const uint32_t poff = ((rows0 + ar) * PSTR + ak) * 4;   // P fragment base
    float4 oc[8];
    #pragma unroll
    for (int nf = 0; nf < 8; nf++) oc[nf] = make_float4(0.f, 0.f, 0.f, 0.f);

    for (int ki = 0; ki < 16; ki++) {
        cp_wait0();
        __syncthreads();
        if (ki + 1 < 16) { PREFG((ki + 1) * 64, (ki + 1) & 1); cp_commit(); }

        const uint32_t bb = smb + (SOFF + (ki & 1) * STBUF2) * 4;
        #pragma unroll
        for (int s = 0; s < 4; s++) {
            uint32_t a[4];
            ldsm4(a, smb + poff + (ki * 32 + s * 8) * 4);
            #pragma unroll
            for (int p = 0; p < 4; p++) {
                uint32_t boffg = ((wn2 + p * 16 + br) * 36 + bk) * 4;
                uint32_t bg[4];
                ldsm4(bg, bb + boffg + s*32);
                mma_f16(oc[2*p],   a[0], a[1], a[2], a[3], bg[0], bg[1]);
                mma_f16(oc[2*p+1], a[0], a[1], a[2], a[3], bg[2], bg[3]);
            }
        }
    }
    #undef PREFG

    const float i0 = ((const float*)sma)[INV_OFF + rows0 + g_];
    const float i1 = ((const float*)sma)[INV_OFF + rows0 + 8 + g_];
    #pragma unroll
    for (int nf = 0; nf < 8; nf++) {
        int colp = wn2 / 2 + nf * 4 + tg;
        size_t r0 = ((size_t)b * LOC + n0 + rows0 + g_) * 128 + colp;
        size_t r1 = ((size_t)b * LOC + n0 + rows0 + 8 + g_) * 128 + colp;
        ag_f[r0] = pack2h(oc[nf].x * i0, oc[nf].y * i0);
        ag_f[r1] = pack2h(oc[nf].z * i1, oc[nf].w * i1);
    }
}

// ---------------------------------------------------------------------------
// kernel_launch
// ---------------------------------------------------------------------------
extern "C" void kernel_launch(void* const* d_in, const int* in_sizes, int n_in,
                              void* d_out, int out_size)
{
    const float* x       = (const float*)d_in[0];
    const float* k_theta = (const float*)d_in[1];
    const float* u_theta = (const float*)d_in[2];
    const float* k_phi   = (const float*)d_in[3];
    const float* u_phi   = (const float*)d_in[4];
    const float* k_g     = (const float*)d_in[5];
    const float* u_g     = (const float*)d_in[6];
    const float* k_attn  = (const float*)d_in[7];
    const float* u_attn  = (const float*)d_in[8];
    const float* sigma   = (const float*)d_in[9];
    float* out = (float*)d_out;

    uint32_t *xh, *xl, *wtpTh, *wtpTl, *wgTf, *waTf;
    uint32_t *thh, *thl, *phh, *phl, *gTf, *agf;
    cudaGetSymbolAddress((void**)&xh,    d_xh);
    cudaGetSymbolAddress((void**)&xl,    d_xl);
    cudaGetSymbolAddress((void**)&wtpTh, d_wtpTh);
    cudaGetSymbolAddress((void**)&wtpTl, d_wtpTl);
    cudaGetSymbolAddress((void**)&wgTf,  d_wgTf);
    cudaGetSymbolAddress((void**)&waTf,  d_waTf);
    cudaGetSymbolAddress((void**)&thh,   d_thh);
    cudaGetSymbolAddress((void**)&thl,   d_thl);
    cudaGetSymbolAddress((void**)&phh,   d_phh);
    cudaGetSymbolAddress((void**)&phl,   d_phl);
    cudaGetSymbolAddress((void**)&gTf,   d_gTf);
    cudaGetSymbolAddress((void**)&agf,   d_agf);

    cudaFuncSetAttribute(gemm_x3,  cudaFuncAttributeMaxDynamicSharedMemorySize, GEMM_SMEM);
    cudaFuncSetAttribute(gemm1<1>, cudaFuncAttributeMaxDynamicSharedMemorySize, GEMM1_SMEM);
    cudaFuncSetAttribute(gemm1<2>, cudaFuncAttributeMaxDynamicSharedMemorySize, GEMM1_SMEM);
    cudaFuncSetAttribute(attn4,    cudaFuncAttributeMaxDynamicSharedMemorySize, ATTN_SMEM);

    // merged prep: spectral (4) + weights (640) + x split (16384)
    prep_all<<<17028, 256>>>(x, k_theta, u_theta, k_phi, u_phi,
                             k_g, u_g, k_attn, u_attn,
                             xh, xl, wtpTh, wtpTl, wgTf, waTf);
    // theta conv + phi conv with fused phi pooling (fp16 x3)
    gemm_x3<<<dim3(1, MTOT / 128), 256, GEMM_SMEM>>>(
        xh, xl, wtpTh, wtpTl, thh, thl, phh, phl, 256);
    // g conv with fused pooling -> transposed fp16 gTf (128x128 tiles)
    gemm1<1><<<dim3(2, MTOT / 128), 256, GEMM1_SMEM>>>(
        xh, wgTf, nullptr, gTf, nullptr, nullptr, 256, 256);
    // fused attention
    attn4<<<dim3(LOC / 64, B_), 512, ATTN_SMEM>>>(thh, thl, phh, phl, gTf, agf);
    // output conv + residual (128x128 tiles)
    gemm1<2><<<dim3(4, MTOT / 128), 256, GEMM1_SMEM>>>(
        agf, waTf, out, nullptr, x, sigma, 512, 128);
}